// round 1
// baseline (speedup 1.0000x reference)
#include <cuda_runtime.h>
#include <cstdint>
#include <cstddef>

// Problem constants
// B=4, S=8192, D=1024, H=8, DK=128, P=1, E=129, M=B*S=32768, Kfc=H*E=1032
#define NB 4
#define NS 8192
#define ND 1024
#define NH 8
#define NDK 128
#define NE 129
#define NM 32768
#define KFC 1032

// ---------------- scratch (static device globals; no allocations) ----------
static __device__ float g_qp[33554432];   // (M, D)  q projection
static __device__ float g_kp[33554432];   // (M, D)  k projection (LN'd in place)
static __device__ float g_vp[33554432];   // (M, D)  v projection (LN'd in place)
static __device__ float g_qc[33816576];   // (M, 1032) q with pos concat per head
static __device__ float g_pa[532512];     // (32, 129, 129) p_attn
static __device__ float g_G [4227072];    // (B, 1024, 1032) G' = pa @ Wfc_h^T

// ---------------------------------------------------------------------------
// Generic TN SGEMM: C[M,N] = A(MxK,row-major) * B(NxK,row-major)^T + bias[n]
// BM=BN=128, BK=8, 256 threads, 8x8 per thread.
// If bBatchRows > 0: B advances by N*K for every bBatchRows rows of A.
// Requires M%128==0, N%128==0, K%8==0, rows 16B-aligned.
// ---------------------------------------------------------------------------
__global__ __launch_bounds__(256, 2) void gemm_tn(
    const float* __restrict__ A, const float* __restrict__ Bm,
    const float* __restrict__ bias, float* __restrict__ C,
    int M, int N, int K, int bBatchRows)
{
    __shared__ float As[8][128];
    __shared__ float Bs[8][128];

    const int tid = threadIdx.x;
    const int tx = tid & 15;
    const int ty = tid >> 4;
    const int m0 = blockIdx.y * 128;
    const int n0 = blockIdx.x * 128;

    const float* Ab = A + (size_t)m0 * K;
    const float* Bb = Bm + (size_t)n0 * K;
    if (bBatchRows) Bb += (size_t)(m0 / bBatchRows) * (size_t)N * K;

    const int lrow = tid >> 1;
    const int lk   = (tid & 1) * 4;

    float acc[8][8];
#pragma unroll
    for (int i = 0; i < 8; i++)
#pragma unroll
        for (int j = 0; j < 8; j++) acc[i][j] = 0.f;

    for (int k0 = 0; k0 < K; k0 += 8) {
        float4 a = *(const float4*)(Ab + (size_t)lrow * K + k0 + lk);
        float4 b = *(const float4*)(Bb + (size_t)lrow * K + k0 + lk);
        As[lk + 0][lrow] = a.x; As[lk + 1][lrow] = a.y;
        As[lk + 2][lrow] = a.z; As[lk + 3][lrow] = a.w;
        Bs[lk + 0][lrow] = b.x; Bs[lk + 1][lrow] = b.y;
        Bs[lk + 2][lrow] = b.z; Bs[lk + 3][lrow] = b.w;
        __syncthreads();

#pragma unroll
        for (int kk = 0; kk < 8; kk++) {
            float ar[8], br[8];
            *(float4*)&ar[0] = *(const float4*)&As[kk][ty * 8];
            *(float4*)&ar[4] = *(const float4*)&As[kk][ty * 8 + 4];
            *(float4*)&br[0] = *(const float4*)&Bs[kk][tx * 8];
            *(float4*)&br[4] = *(const float4*)&Bs[kk][tx * 8 + 4];
#pragma unroll
            for (int i = 0; i < 8; i++)
#pragma unroll
                for (int j = 0; j < 8; j++)
                    acc[i][j] = fmaf(ar[i], br[j], acc[i][j]);
        }
        __syncthreads();
    }

    float bb[8];
#pragma unroll
    for (int j = 0; j < 8; j++) bb[j] = bias[n0 + tx * 8 + j];

#pragma unroll
    for (int i = 0; i < 8; i++) {
        size_t row = (size_t)(m0 + ty * 8 + i);
        float4 o0, o1;
        o0.x = acc[i][0] + bb[0]; o0.y = acc[i][1] + bb[1];
        o0.z = acc[i][2] + bb[2]; o0.w = acc[i][3] + bb[3];
        o1.x = acc[i][4] + bb[4]; o1.y = acc[i][5] + bb[5];
        o1.z = acc[i][6] + bb[6]; o1.w = acc[i][7] + bb[7];
        *(float4*)(C + row * N + n0 + tx * 8)     = o0;
        *(float4*)(C + row * N + n0 + tx * 8 + 4) = o1;
    }
}

// ---------------------------------------------------------------------------
// Per-head LayerNorm, in place, on both kp and vp.
// grid (M, 2), block 256: warp w handles head w of row m.
// ---------------------------------------------------------------------------
__global__ __launch_bounds__(256) void ln_kernel(
    float* __restrict__ kp, float* __restrict__ vp,
    const float* __restrict__ gK, const float* __restrict__ bK,
    const float* __restrict__ gV, const float* __restrict__ bV)
{
    const int m = blockIdx.x;
    float* buf      = blockIdx.y ? vp : kp;
    const float* g  = blockIdx.y ? gV : gK;
    const float* be = blockIdx.y ? bV : bK;

    const int w = threadIdx.x >> 5;
    const int lane = threadIdx.x & 31;

    float* p = buf + (size_t)m * ND + w * NDK + lane * 4;
    float4 x = *(float4*)p;
    float s  = x.x + x.y + x.z + x.w;
    float s2 = x.x * x.x + x.y * x.y + x.z * x.z + x.w * x.w;
#pragma unroll
    for (int o = 16; o > 0; o >>= 1) {
        s  += __shfl_xor_sync(0xffffffffu, s,  o);
        s2 += __shfl_xor_sync(0xffffffffu, s2, o);
    }
    const float mean = s * (1.f / 128.f);
    const float var  = s2 * (1.f / 128.f) - mean * mean;
    const float rstd = rsqrtf(var + 1e-5f);

    float4 gv = *(const float4*)(g  + w * NDK + lane * 4);
    float4 bv = *(const float4*)(be + w * NDK + lane * 4);
    float4 y;
    y.x = (x.x - mean) * rstd * gv.x + bv.x;
    y.y = (x.y - mean) * rstd * gv.y + bv.y;
    y.z = (x.z - mean) * rstd * gv.z + bv.z;
    y.w = (x.w - mean) * rstd * gv.w + bv.w;
    *(float4*)p = y;
}

// ---------------------------------------------------------------------------
// p_attn core: pa[bh][1+d][1+e] += sum_s kn[s,d]*vn[s,e] / S  (d,e in [0,128))
// grid (2 dt, 2 et, 32*4 bh*split), block 256, 4x4 per thread, 64x64 tile.
// ---------------------------------------------------------------------------
__global__ __launch_bounds__(256) void pa_core(
    const float* __restrict__ kp, const float* __restrict__ vp,
    float* __restrict__ pa)
{
    const int dt = blockIdx.x, et = blockIdx.y;
    const int z = blockIdx.z;
    const int bh = z & 31;
    const int sp = z >> 5;
    const int b = bh >> 3, h = bh & 7;

    const float* kb = kp + ((size_t)b * NS) * ND + h * NDK + dt * 64;
    const float* vb = vp + ((size_t)b * NS) * ND + h * NDK + et * 64;

    __shared__ float Ks[32][64];
    __shared__ float Vs[32][64];

    const int tid = threadIdx.x;
    const int tx = tid & 15, ty = tid >> 4;

    float acc[4][4];
#pragma unroll
    for (int i = 0; i < 4; i++)
#pragma unroll
        for (int j = 0; j < 4; j++) acc[i][j] = 0.f;

    const int s_begin = sp * 2048;
    for (int s0 = s_begin; s0 < s_begin + 2048; s0 += 32) {
#pragma unroll
        for (int r = 0; r < 2; r++) {
            int f = tid + r * 256;
            int sl = f >> 4;
            int c4 = (f & 15) * 4;
            *(float4*)&Ks[sl][c4] = *(const float4*)(kb + (size_t)(s0 + sl) * ND + c4);
            *(float4*)&Vs[sl][c4] = *(const float4*)(vb + (size_t)(s0 + sl) * ND + c4);
        }
        __syncthreads();
#pragma unroll
        for (int s = 0; s < 32; s++) {
            float4 av = *(const float4*)&Ks[s][ty * 4];
            float4 bv = *(const float4*)&Vs[s][tx * 4];
            float ar[4] = {av.x, av.y, av.z, av.w};
            float br[4] = {bv.x, bv.y, bv.z, bv.w};
#pragma unroll
            for (int i = 0; i < 4; i++)
#pragma unroll
                for (int j = 0; j < 4; j++)
                    acc[i][j] = fmaf(ar[i], br[j], acc[i][j]);
        }
        __syncthreads();
    }

    const float invS = 1.0f / (float)NS;
    float* pab = pa + (size_t)bh * NE * NE;
    const int d0 = 1 + dt * 64 + ty * 4;
    const int e0 = 1 + et * 64 + tx * 4;
#pragma unroll
    for (int i = 0; i < 4; i++)
#pragma unroll
        for (int j = 0; j < 4; j++)
            atomicAdd(&pab[(d0 + i) * NE + (e0 + j)], acc[i][j] * invS);
}

// ---------------------------------------------------------------------------
// p_attn edges: row 0 (pos . Vc), col 0 (Kc . pos), corner (pos . pos), /S
// grid (32, 8 s-splits), block 256.
// ---------------------------------------------------------------------------
__global__ __launch_bounds__(256) void pa_edges(
    const float* __restrict__ kp, const float* __restrict__ vp,
    const float* __restrict__ pos, float* __restrict__ pa)
{
    const int bh = blockIdx.x;
    const int b = bh >> 3, h = bh & 7;
    const int sp = blockIdx.y;

    const float* posb = pos + (size_t)b * NS + sp * 1024;
    const float* vb = vp + ((size_t)b * NS + sp * 1024) * ND + h * NDK;
    const float* kb = kp + ((size_t)b * NS + sp * 1024) * ND + h * NDK;

    const int tid = threadIdx.x;
    const int col = tid & 127;
    const float* src = (tid < 128) ? vb : kb;

    __shared__ float ps[256];
    float a0 = 0.f, a1 = 0.f, a2 = 0.f, a3 = 0.f;
    for (int s0 = 0; s0 < 1024; s0 += 256) {
        __syncthreads();
        ps[tid] = posb[s0 + tid];
        __syncthreads();
#pragma unroll 4
        for (int t = 0; t < 256; t += 4) {
            a0 = fmaf(ps[t + 0], src[(size_t)(s0 + t + 0) * ND + col], a0);
            a1 = fmaf(ps[t + 1], src[(size_t)(s0 + t + 1) * ND + col], a1);
            a2 = fmaf(ps[t + 2], src[(size_t)(s0 + t + 2) * ND + col], a2);
            a3 = fmaf(ps[t + 3], src[(size_t)(s0 + t + 3) * ND + col], a3);
        }
    }
    float acc = (a0 + a1) + (a2 + a3);

    // pos^2 partial
    float p2 = 0.f;
    for (int s = tid; s < 1024; s += 256) {
        float p = posb[s];
        p2 = fmaf(p, p, p2);
    }

    const float invS = 1.0f / (float)NS;
    float* pab = pa + (size_t)bh * NE * NE;
    if (tid < 128) atomicAdd(&pab[0 * NE + (1 + col)], acc * invS);
    else           atomicAdd(&pab[(1 + col) * NE + 0], acc * invS);

    __shared__ float red[256];
    red[tid] = p2;
    __syncthreads();
    for (int o = 128; o > 0; o >>= 1) {
        if (tid < o) red[tid] += red[tid + o];
        __syncthreads();
    }
    if (tid == 0) atomicAdd(&pab[0], red[0] * invS);
}

// ---------------------------------------------------------------------------
// G'[b][n][h*129+d] = sum_e pa[b,h,d,e] * Wfc[n, h*129+e]
// grid (8 n-tiles, 8 h, 4 b), block 256, dynamic smem (pa + Wfc tiles).
// ---------------------------------------------------------------------------
__global__ __launch_bounds__(256) void g_kernel(
    const float* __restrict__ pa, const float* __restrict__ Wfc,
    float* __restrict__ Gp)
{
    extern __shared__ float sm[];
    float* pas = sm;               // 129 rows x 132 stride
    float* ws  = sm + 129 * 132;   // 128 rows x 132 stride

    const int nt = blockIdx.x, h = blockIdx.y, b = blockIdx.z;
    const int tid = threadIdx.x;
    const int n0 = nt * 128;

    const float* pab = pa + ((size_t)(b * NH + h)) * NE * NE;
    for (int i = tid; i < NE * NE; i += 256) {
        int d = i / NE, e = i - d * NE;
        pas[d * 132 + e] = pab[i];
    }
    for (int i = tid; i < 128 * NE; i += 256) {
        int n = i / NE, e = i - n * NE;
        ws[n * 132 + e] = Wfc[(size_t)(n0 + n) * KFC + h * NE + e];
    }
    __syncthreads();

    for (int o = tid; o < 128 * NE; o += 256) {
        int n = o / NE, d = o - n * NE;
        const float* pr = &pas[d * 132];
        const float* wr = &ws[n * 132];
        float acc = 0.f;
#pragma unroll 8
        for (int e4 = 0; e4 < 128; e4 += 4) {
            float4 a = *(const float4*)(pr + e4);
            float4 w = *(const float4*)(wr + e4);
            acc = fmaf(a.x, w.x, acc);
            acc = fmaf(a.y, w.y, acc);
            acc = fmaf(a.z, w.z, acc);
            acc = fmaf(a.w, w.w, acc);
        }
        acc = fmaf(pr[128], wr[128], acc);
        Gp[((size_t)b * ND + n0 + n) * KFC + h * NE + d] = acc;
    }
}

// ---------------------------------------------------------------------------
// Build Qcat (M, 1032): per head col 0 = pos, cols 1..128 = qp head slice.
// ---------------------------------------------------------------------------
__global__ __launch_bounds__(256) void qcat_kernel(
    const float* __restrict__ qp, const float* __restrict__ pos,
    float* __restrict__ qcat)
{
    const int m = blockIdx.x;
    const float* qr = qp + (size_t)m * ND;
    float* o = qcat + (size_t)m * KFC;
    const float pv = pos[m];
    for (int kk = threadIdx.x; kk < KFC; kk += 256) {
        int h = kk / NE;
        int d = kk - h * NE;
        o[kk] = d ? qr[h * NDK + d - 1] : pv;
    }
}

// ---------------------------------------------------------------------------
extern "C" void kernel_launch(void* const* d_in, const int* in_sizes, int n_in,
                              void* d_out, int out_size)
{
    (void)in_sizes; (void)n_in; (void)out_size;
    const float* query = (const float*)d_in[0];
    const float* key   = (const float*)d_in[1];
    const float* value = (const float*)d_in[2];
    const float* pos   = (const float*)d_in[3];
    const float* Wq    = (const float*)d_in[4];
    const float* bq    = (const float*)d_in[5];
    const float* Wk    = (const float*)d_in[6];
    const float* bk    = (const float*)d_in[7];
    const float* Wv    = (const float*)d_in[8];
    const float* bv    = (const float*)d_in[9];
    const float* gK    = (const float*)d_in[10];
    const float* betaK = (const float*)d_in[11];
    const float* gV    = (const float*)d_in[12];
    const float* betaV = (const float*)d_in[13];
    const float* Wfc   = (const float*)d_in[14];
    const float* bfc   = (const float*)d_in[15];
    float* out = (float*)d_out;

    float *qp, *kp, *vp, *qc, *pa, *Gp;
    cudaGetSymbolAddress((void**)&qp, g_qp);
    cudaGetSymbolAddress((void**)&kp, g_kp);
    cudaGetSymbolAddress((void**)&vp, g_vp);
    cudaGetSymbolAddress((void**)&qc, g_qc);
    cudaGetSymbolAddress((void**)&pa, g_pa);
    cudaGetSymbolAddress((void**)&Gp, g_G);

    dim3 gProj(ND / 128, NM / 128);  // (8, 256)

    // QKV projections
    gemm_tn<<<gProj, 256>>>(query, Wq, bq, qp, NM, ND, ND, 0);
    gemm_tn<<<gProj, 256>>>(key,   Wk, bk, kp, NM, ND, ND, 0);
    gemm_tn<<<gProj, 256>>>(value, Wv, bv, vp, NM, ND, ND, 0);

    // per-head LayerNorm on K and V (in place)
    ln_kernel<<<dim3(NM, 2), 256>>>(kp, vp, gK, betaK, gV, betaV);

    // p_attn = Kc^T Vc / S
    cudaMemsetAsync(pa, 0, (size_t)32 * NE * NE * sizeof(float));
    pa_core<<<dim3(2, 2, 128), 256>>>(kp, vp, pa);
    pa_edges<<<dim3(32, 8), 256>>>(kp, vp, pos, pa);

    // G' = pa @ Wfc_h^T  (B, 1024, 1032)
    cudaFuncSetAttribute(g_kernel, cudaFuncAttributeMaxDynamicSharedMemorySize,
                         (129 + 128) * 132 * (int)sizeof(float));
    g_kernel<<<dim3(8, NH, NB), 256, (129 + 128) * 132 * sizeof(float)>>>(pa, Wfc, Gp);

    // Qcat
    qcat_kernel<<<NM, 256>>>(qp, pos, qc);

    // out = Qcat @ G'^T(per-batch) + bfc
    gemm_tn<<<gProj, 256>>>(qc, Gp, bfc, out, NM, ND, KFC, NS);
}

// round 3
// speedup vs baseline: 2.8108x; 2.8108x over previous
#include <cuda_runtime.h>
#include <cuda.h>
#include <cuda_bf16.h>
#include <cstdint>
#include <cstddef>

// Problem constants
#define NB 4
#define NS 8192
#define ND 1024
#define NH 8
#define NDK 128
#define NE 129
#define NM 32768
#define KFC 1032

// ---------------- scratch (static device globals; no allocations) ----------
static __device__ float g_qp[33554432];             // (M, D)  q projection
static __device__ float g_kp[33554432];             // (M, D)  k projection (LN'd)
static __device__ float g_vp[33554432];             // (M, D)  v projection (LN'd)
static __device__ float g_pa[532512];               // (32, 129, 129) p_attn
static __device__ float g_G [4227072];              // (B, 1024, 1032) G'
static __device__ __nv_bfloat16 g_ahi[33816576];    // A operand hi (acts / qcat)
static __device__ __nv_bfloat16 g_alo[33816576];    // A operand lo
static __device__ __nv_bfloat16 g_bhi[4227072];     // B operand hi (weights / G)
static __device__ __nv_bfloat16 g_blo[4227072];     // B operand lo

// ============================ PTX helpers ==================================
__device__ __forceinline__ uint32_t smem_u32(const void* p) {
    uint32_t a;
    asm("{ .reg .u64 t; cvta.to.shared.u64 t, %1; cvt.u32.u64 %0, t; }"
        : "=r"(a) : "l"(p));
    return a;
}
__device__ __forceinline__ void mbar_init(uint32_t mbar, uint32_t cnt) {
    asm volatile("mbarrier.init.shared.b64 [%0], %1;" :: "r"(mbar), "r"(cnt) : "memory");
}
__device__ __forceinline__ void mbar_expect_tx(uint32_t mbar, uint32_t bytes) {
    asm volatile("mbarrier.arrive.expect_tx.shared.b64 _, [%0], %1;"
                 :: "r"(mbar), "r"(bytes) : "memory");
}
__device__ __forceinline__ void mbar_arrive(uint32_t mbar) {
    asm volatile("mbarrier.arrive.shared.b64 _, [%0];" :: "r"(mbar) : "memory");
}
__device__ __forceinline__ void mbar_wait(uint32_t mbar, uint32_t parity) {
    asm volatile(
        "{\n\t.reg .pred P;\n\t"
        "BWL_%=:\n\t"
        "mbarrier.try_wait.parity.acquire.cta.shared::cta.b64 P, [%0], %1, 0x989680;\n\t"
        "@P bra.uni BWD_%=;\n\t"
        "bra.uni BWL_%=;\n\t"
        "BWD_%=:\n\t}"
        :: "r"(mbar), "r"(parity) : "memory");
}
__device__ __forceinline__ void tma_load_3d(uint32_t dst, const CUtensorMap* tm,
                                            int x, int y, int z, uint32_t mbar) {
    asm volatile(
        "cp.async.bulk.tensor.3d.shared::cta.global.tile.mbarrier::complete_tx::bytes "
        "[%0], [%1, {%2, %3, %4}], [%5];"
        :: "r"(dst), "l"(tm), "r"(x), "r"(y), "r"(z), "r"(mbar) : "memory");
}
__device__ __forceinline__ void fence_async_shared() {
    asm volatile("fence.proxy.async.shared::cta;" ::: "memory");
}
__device__ __forceinline__ void ldsm4(uint32_t* r, uint32_t addr) {
    asm volatile("ldmatrix.sync.aligned.m8n8.x4.shared.b16 {%0,%1,%2,%3}, [%4];"
                 : "=r"(r[0]), "=r"(r[1]), "=r"(r[2]), "=r"(r[3]) : "r"(addr));
}
__device__ __forceinline__ void mma_bf16(float* c, const uint32_t* a, const uint32_t* b) {
    asm volatile(
        "mma.sync.aligned.m16n8k16.row.col.f32.bf16.bf16.f32 "
        "{%0,%1,%2,%3}, {%4,%5,%6,%7}, {%8,%9}, {%0,%1,%2,%3};"
        : "+f"(c[0]), "+f"(c[1]), "+f"(c[2]), "+f"(c[3])
        : "r"(a[0]), "r"(a[1]), "r"(a[2]), "r"(a[3]), "r"(b[0]), "r"(b[1]));
}
// SW128 swizzled smem address: tile row (128B wide) r, byte col c
__device__ __forceinline__ uint32_t swz(uint32_t base, int r, int c) {
    return base + r * 128 + (c ^ ((r & 7) << 4));
}

// ============================ bf16x3 tensor-core GEMM ======================
// C[M,1024] = A(MxK) * B(1024xK)^T + bias, via A,B split into bf16 hi+lo.
// CTA tile 128x128, BK=64, 8 warps (warp tile 64x32), 3-stage TMA pipeline.
static constexpr int ST = 3;
static constexpr uint32_t OP_BYTES = 128 * 64 * 2;      // 16 KB per operand half
static constexpr uint32_t STG_BYTES = 4 * OP_BYTES;     // 64 KB per stage
static constexpr uint32_t CTRL_BYTES = 1024;
static constexpr uint32_t SMEM_DYN = CTRL_BYTES + ST * STG_BYTES;  // 197632

__global__ __launch_bounds__(256, 1) void gemm_mma(
    const __grid_constant__ CUtensorMap tmAhi,
    const __grid_constant__ CUtensorMap tmAlo,
    const __grid_constant__ CUtensorMap tmBhi,
    const __grid_constant__ CUtensorMap tmBlo,
    const float* __restrict__ bias,
    float* __restrict__ C,
    int KB, int mRowsPerZ, int bBatched)
{
    extern __shared__ __align__(1024) char smem[];
    const uint32_t sb = smem_u32(smem);
    const int tid = threadIdx.x;
    const int wid = tid >> 5, lane = tid & 31;
    const int warp_row = wid >> 2;     // 0..1
    const int warp_col = wid & 3;      // 0..3

    const uint32_t full0  = sb;        // ST mbarriers, 8B each
    const uint32_t empty0 = sb + 64;
    const uint32_t tiles  = sb + CTRL_BYTES;

    const int n0 = blockIdx.x * 128;
    const int m0 = blockIdx.z * mRowsPerZ + blockIdx.y * 128;
    const int zB = bBatched ? blockIdx.z : 0;

    if (tid == 0) {
        for (int s = 0; s < ST; s++) {
            mbar_init(full0 + s * 8, 1);
            mbar_init(empty0 + s * 8, 256);
        }
        fence_async_shared();
    }
    __syncthreads();

    // prologue: fill all ST stages
    if (tid == 0) {
        for (int s = 0; s < ST; s++) {
            uint32_t fb = full0 + s * 8;
            mbar_expect_tx(fb, STG_BYTES);
            uint32_t a0 = tiles + s * STG_BYTES;
            tma_load_3d(a0,                 &tmAhi, s * 64, m0, 0,  fb);
            tma_load_3d(a0 + OP_BYTES,      &tmAlo, s * 64, m0, 0,  fb);
            tma_load_3d(a0 + 2 * OP_BYTES,  &tmBhi, s * 64, n0, zB, fb);
            tma_load_3d(a0 + 3 * OP_BYTES,  &tmBlo, s * 64, n0, zB, fb);
        }
    }

    float acc[4][4][4];
#pragma unroll
    for (int mi = 0; mi < 4; mi++)
#pragma unroll
        for (int ni = 0; ni < 4; ni++)
#pragma unroll
            for (int q = 0; q < 4; q++) acc[mi][ni][q] = 0.f;

    // ldmatrix lane addressing (within tile)
    const int aR = lane & 15;
    const int aC = (lane >> 4) << 4;                      // 0 or 16
    const int bR = ((lane >> 4) << 3) + (lane & 7);
    const int bC = ((lane >> 3) & 1) << 4;

    for (int kb = 0; kb < KB; kb++) {
        const int s = kb % ST;
        const uint32_t ph = (uint32_t)((kb / ST) & 1);
        mbar_wait(full0 + s * 8, ph);

        const uint32_t A0 = tiles + s * STG_BYTES;
        const uint32_t B0 = A0 + 2 * OP_BYTES;

#pragma unroll
        for (int ki = 0; ki < 4; ki++) {
            const int kc = ki * 32;
            uint32_t ahi[4][4], alo[4][4], bhi[4][2], blo[4][2];
#pragma unroll
            for (int mi = 0; mi < 4; mi++) {
                int r = warp_row * 64 + mi * 16 + aR;
                uint32_t ad = swz(A0, r, kc + aC);
                ldsm4(ahi[mi], ad);
                ldsm4(alo[mi], ad + OP_BYTES);
            }
#pragma unroll
            for (int g = 0; g < 2; g++) {
                int r = warp_col * 32 + g * 16 + bR;
                uint32_t bd = swz(B0, r, kc + bC);
                uint32_t t[4];
                ldsm4(t, bd);
                bhi[2 * g][0] = t[0]; bhi[2 * g][1] = t[1];
                bhi[2 * g + 1][0] = t[2]; bhi[2 * g + 1][1] = t[3];
                ldsm4(t, bd + OP_BYTES);
                blo[2 * g][0] = t[0]; blo[2 * g][1] = t[1];
                blo[2 * g + 1][0] = t[2]; blo[2 * g + 1][1] = t[3];
            }
#pragma unroll
            for (int mi = 0; mi < 4; mi++)
#pragma unroll
                for (int ni = 0; ni < 4; ni++) {
                    mma_bf16(acc[mi][ni], ahi[mi], bhi[ni]);
                    mma_bf16(acc[mi][ni], ahi[mi], blo[ni]);
                    mma_bf16(acc[mi][ni], alo[mi], bhi[ni]);
                }
        }

        mbar_arrive(empty0 + s * 8);

        if (tid == 0 && kb + ST < KB) {
            mbar_wait(empty0 + s * 8, ph);   // all 256 consumed this round
            uint32_t fb = full0 + s * 8;
            mbar_expect_tx(fb, STG_BYTES);
            uint32_t a0 = tiles + s * STG_BYTES;
            int kx = (kb + ST) * 64;
            tma_load_3d(a0,                &tmAhi, kx, m0, 0,  fb);
            tma_load_3d(a0 + OP_BYTES,     &tmAlo, kx, m0, 0,  fb);
            tma_load_3d(a0 + 2 * OP_BYTES, &tmBhi, kx, n0, zB, fb);
            tma_load_3d(a0 + 3 * OP_BYTES, &tmBlo, kx, n0, zB, fb);
        }
    }

    // epilogue: bias add + store
#pragma unroll
    for (int mi = 0; mi < 4; mi++) {
        int r = m0 + warp_row * 64 + mi * 16 + (lane >> 2);
#pragma unroll
        for (int ni = 0; ni < 4; ni++) {
            int cc = n0 + warp_col * 32 + ni * 8 + (lane & 3) * 2;
            float b0v = bias[cc], b1v = bias[cc + 1];
            float2 v0 = { acc[mi][ni][0] + b0v, acc[mi][ni][1] + b1v };
            float2 v1 = { acc[mi][ni][2] + b0v, acc[mi][ni][3] + b1v };
            *(float2*)(C + (size_t)r * 1024 + cc) = v0;
            *(float2*)(C + (size_t)(r + 8) * 1024 + cc) = v1;
        }
    }
}

// ---------------------------------------------------------------------------
// fp32 -> bf16 hi/lo split (n multiple of 4)
// ---------------------------------------------------------------------------
__global__ __launch_bounds__(256) void split_kernel(
    const float* __restrict__ src, __nv_bfloat16* __restrict__ hi,
    __nv_bfloat16* __restrict__ lo, int n)
{
    int i = (blockIdx.x * 256 + threadIdx.x) * 4;
    if (i >= n) return;
    float4 v = *(const float4*)(src + i);
    __nv_bfloat16 h0 = __float2bfloat16(v.x);
    __nv_bfloat16 h1 = __float2bfloat16(v.y);
    __nv_bfloat16 h2 = __float2bfloat16(v.z);
    __nv_bfloat16 h3 = __float2bfloat16(v.w);
    __nv_bfloat16 l0 = __float2bfloat16(v.x - __bfloat162float(h0));
    __nv_bfloat16 l1 = __float2bfloat16(v.y - __bfloat162float(h1));
    __nv_bfloat16 l2 = __float2bfloat16(v.z - __bfloat162float(h2));
    __nv_bfloat16 l3 = __float2bfloat16(v.w - __bfloat162float(h3));
    __nv_bfloat162* hp = (__nv_bfloat162*)(hi + i);
    __nv_bfloat162* lp = (__nv_bfloat162*)(lo + i);
    hp[0] = __nv_bfloat162(h0, h1);
    hp[1] = __nv_bfloat162(h2, h3);
    lp[0] = __nv_bfloat162(l0, l1);
    lp[1] = __nv_bfloat162(l2, l3);
}

// ---------------------------------------------------------------------------
// Per-head LayerNorm, in place, on both kp and vp.
// ---------------------------------------------------------------------------
__global__ __launch_bounds__(256) void ln_kernel(
    float* __restrict__ kp, float* __restrict__ vp,
    const float* __restrict__ gK, const float* __restrict__ bK,
    const float* __restrict__ gV, const float* __restrict__ bV)
{
    const int m = blockIdx.x;
    float* buf      = blockIdx.y ? vp : kp;
    const float* g  = blockIdx.y ? gV : gK;
    const float* be = blockIdx.y ? bV : bK;

    const int w = threadIdx.x >> 5;
    const int lane = threadIdx.x & 31;

    float* p = buf + (size_t)m * ND + w * NDK + lane * 4;
    float4 x = *(float4*)p;
    float s  = x.x + x.y + x.z + x.w;
    float s2 = x.x * x.x + x.y * x.y + x.z * x.z + x.w * x.w;
#pragma unroll
    for (int o = 16; o > 0; o >>= 1) {
        s  += __shfl_xor_sync(0xffffffffu, s,  o);
        s2 += __shfl_xor_sync(0xffffffffu, s2, o);
    }
    const float mean = s * (1.f / 128.f);
    const float var  = s2 * (1.f / 128.f) - mean * mean;
    const float rstd = rsqrtf(var + 1e-5f);

    float4 gv = *(const float4*)(g  + w * NDK + lane * 4);
    float4 bv = *(const float4*)(be + w * NDK + lane * 4);
    float4 y;
    y.x = (x.x - mean) * rstd * gv.x + bv.x;
    y.y = (x.y - mean) * rstd * gv.y + bv.y;
    y.z = (x.z - mean) * rstd * gv.z + bv.z;
    y.w = (x.w - mean) * rstd * gv.w + bv.w;
    *(float4*)p = y;
}

// ---------------------------------------------------------------------------
// p_attn core (FFMA): pa[bh][1+d][1+e] += sum_s kn[s,d]*vn[s,e] / S
// ---------------------------------------------------------------------------
__global__ __launch_bounds__(256) void pa_core(
    const float* __restrict__ kp, const float* __restrict__ vp,
    float* __restrict__ pa)
{
    const int dt = blockIdx.x, et = blockIdx.y;
    const int z = blockIdx.z;
    const int bh = z & 31;
    const int sp = z >> 5;
    const int b = bh >> 3, h = bh & 7;

    const float* kb = kp + ((size_t)b * NS) * ND + h * NDK + dt * 64;
    const float* vb = vp + ((size_t)b * NS) * ND + h * NDK + et * 64;

    __shared__ float Ks[32][64];
    __shared__ float Vs[32][64];

    const int tid = threadIdx.x;
    const int tx = tid & 15, ty = tid >> 4;

    float acc[4][4];
#pragma unroll
    for (int i = 0; i < 4; i++)
#pragma unroll
        for (int j = 0; j < 4; j++) acc[i][j] = 0.f;

    const int s_begin = sp * 2048;
    for (int s0 = s_begin; s0 < s_begin + 2048; s0 += 32) {
#pragma unroll
        for (int r = 0; r < 2; r++) {
            int f = tid + r * 256;
            int sl = f >> 4;
            int c4 = (f & 15) * 4;
            *(float4*)&Ks[sl][c4] = *(const float4*)(kb + (size_t)(s0 + sl) * ND + c4);
            *(float4*)&Vs[sl][c4] = *(const float4*)(vb + (size_t)(s0 + sl) * ND + c4);
        }
        __syncthreads();
#pragma unroll
        for (int s = 0; s < 32; s++) {
            float4 av = *(const float4*)&Ks[s][ty * 4];
            float4 bv = *(const float4*)&Vs[s][tx * 4];
            float ar[4] = {av.x, av.y, av.z, av.w};
            float br[4] = {bv.x, bv.y, bv.z, bv.w};
#pragma unroll
            for (int i = 0; i < 4; i++)
#pragma unroll
                for (int j = 0; j < 4; j++)
                    acc[i][j] = fmaf(ar[i], br[j], acc[i][j]);
        }
        __syncthreads();
    }

    const float invS = 1.0f / (float)NS;
    float* pab = pa + (size_t)bh * NE * NE;
    const int d0 = 1 + dt * 64 + ty * 4;
    const int e0 = 1 + et * 64 + tx * 4;
#pragma unroll
    for (int i = 0; i < 4; i++)
#pragma unroll
        for (int j = 0; j < 4; j++)
            atomicAdd(&pab[(d0 + i) * NE + (e0 + j)], acc[i][j] * invS);
}

// ---------------------------------------------------------------------------
// p_attn edges: row 0 (pos . Vc), col 0 (Kc . pos), corner (pos . pos), /S
// ---------------------------------------------------------------------------
__global__ __launch_bounds__(256) void pa_edges(
    const float* __restrict__ kp, const float* __restrict__ vp,
    const float* __restrict__ pos, float* __restrict__ pa)
{
    const int bh = blockIdx.x;
    const int b = bh >> 3, h = bh & 7;
    const int sp = blockIdx.y;

    const float* posb = pos + (size_t)b * NS + sp * 1024;
    const float* vb = vp + ((size_t)b * NS + sp * 1024) * ND + h * NDK;
    const float* kb = kp + ((size_t)b * NS + sp * 1024) * ND + h * NDK;

    const int tid = threadIdx.x;
    const int col = tid & 127;
    const float* src = (tid < 128) ? vb : kb;

    __shared__ float ps[256];
    float a0 = 0.f, a1 = 0.f, a2 = 0.f, a3 = 0.f;
    for (int s0 = 0; s0 < 1024; s0 += 256) {
        __syncthreads();
        ps[tid] = posb[s0 + tid];
        __syncthreads();
#pragma unroll 4
        for (int t = 0; t < 256; t += 4) {
            a0 = fmaf(ps[t + 0], src[(size_t)(s0 + t + 0) * ND + col], a0);
            a1 = fmaf(ps[t + 1], src[(size_t)(s0 + t + 1) * ND + col], a1);
            a2 = fmaf(ps[t + 2], src[(size_t)(s0 + t + 2) * ND + col], a2);
            a3 = fmaf(ps[t + 3], src[(size_t)(s0 + t + 3) * ND + col], a3);
        }
    }
    float acc = (a0 + a1) + (a2 + a3);

    float p2 = 0.f;
    for (int s = tid; s < 1024; s += 256) {
        float p = posb[s];
        p2 = fmaf(p, p, p2);
    }

    const float invS = 1.0f / (float)NS;
    float* pab = pa + (size_t)bh * NE * NE;
    if (tid < 128) atomicAdd(&pab[0 * NE + (1 + col)], acc * invS);
    else           atomicAdd(&pab[(1 + col) * NE + 0], acc * invS);

    __shared__ float red[256];
    red[tid] = p2;
    __syncthreads();
    for (int o = 128; o > 0; o >>= 1) {
        if (tid < o) red[tid] += red[tid + o];
        __syncthreads();
    }
    if (tid == 0) atomicAdd(&pab[0], red[0] * invS);
}

// ---------------------------------------------------------------------------
// G'[b][n][h*129+d] = sum_e pa[b,h,d,e] * Wfc[n, h*129+e]
// ---------------------------------------------------------------------------
__global__ __launch_bounds__(256) void g_kernel(
    const float* __restrict__ pa, const float* __restrict__ Wfc,
    float* __restrict__ Gp)
{
    extern __shared__ float sm[];
    float* pas = sm;               // 129 rows x 132 stride
    float* ws  = sm + 129 * 132;   // 128 rows x 132 stride

    const int nt = blockIdx.x, h = blockIdx.y, b = blockIdx.z;
    const int tid = threadIdx.x;
    const int n0 = nt * 128;

    const float* pab = pa + ((size_t)(b * NH + h)) * NE * NE;
    for (int i = tid; i < NE * NE; i += 256) {
        int d = i / NE, e = i - d * NE;
        pas[d * 132 + e] = pab[i];
    }
    for (int i = tid; i < 128 * NE; i += 256) {
        int n = i / NE, e = i - n * NE;
        ws[n * 132 + e] = Wfc[(size_t)(n0 + n) * KFC + h * NE + e];
    }
    __syncthreads();

    for (int o = tid; o < 128 * NE; o += 256) {
        int n = o / NE, d = o - n * NE;
        const float* pr = &pas[d * 132];
        const float* wr = &ws[n * 132];
        float acc = 0.f;
#pragma unroll 8
        for (int e4 = 0; e4 < 128; e4 += 4) {
            float4 a = *(const float4*)(pr + e4);
            float4 w = *(const float4*)(wr + e4);
            acc = fmaf(a.x, w.x, acc);
            acc = fmaf(a.y, w.y, acc);
            acc = fmaf(a.z, w.z, acc);
            acc = fmaf(a.w, w.w, acc);
        }
        acc = fmaf(pr[128], wr[128], acc);
        Gp[((size_t)b * ND + n0 + n) * KFC + h * NE + d] = acc;
    }
}

// ---------------------------------------------------------------------------
// Build Qcat (M, 1032) directly as bf16 hi/lo
// ---------------------------------------------------------------------------
__global__ __launch_bounds__(256) void qcat_hl_kernel(
    const float* __restrict__ qp, const float* __restrict__ pos,
    __nv_bfloat16* __restrict__ hi, __nv_bfloat16* __restrict__ lo)
{
    const int m = blockIdx.x;
    const float* qr = qp + (size_t)m * ND;
    const float pv = pos[m];
    for (int kk = threadIdx.x; kk < KFC; kk += 256) {
        int h = kk / NE;
        int d = kk - h * NE;
        float v = d ? qr[h * NDK + d - 1] : pv;
        __nv_bfloat16 hh = __float2bfloat16(v);
        hi[(size_t)m * KFC + kk] = hh;
        lo[(size_t)m * KFC + kk] = __float2bfloat16(v - __bfloat162float(hh));
    }
}

// ============================ host side ====================================
typedef CUresult (*EncodeFn)(CUtensorMap*, CUtensorMapDataType, cuuint32_t, void*,
                             const cuuint64_t*, const cuuint64_t*, const cuuint32_t*,
                             const cuuint32_t*, CUtensorMapInterleave, CUtensorMapSwizzle,
                             CUtensorMapL2promotion, CUtensorMapFloatOOBfill);

static EncodeFn get_encode() {
    static EncodeFn fn = nullptr;
    if (!fn) {
        void* p = nullptr;
        cudaDriverEntryPointQueryResult st;
        cudaGetDriverEntryPoint("cuTensorMapEncodeTiled", &p, cudaEnableDefault, &st);
        fn = (EncodeFn)p;
    }
    return fn;
}

// bf16 map: dims [k, rows, nz], box [64, 128, 1], SW128
static void encode_bf16(CUtensorMap* m, const void* base,
                        uint64_t kdim, uint64_t rows, uint64_t nz) {
    cuuint64_t dims[3]    = { kdim, rows, nz };
    cuuint64_t strides[2] = { kdim * 2, rows * kdim * 2 };
    cuuint32_t box[3]     = { 64, 128, 1 };
    cuuint32_t est[3]     = { 1, 1, 1 };
    get_encode()(m, CU_TENSOR_MAP_DATA_TYPE_BFLOAT16, 3, (void*)base,
                 dims, strides, box, est,
                 CU_TENSOR_MAP_INTERLEAVE_NONE, CU_TENSOR_MAP_SWIZZLE_128B,
                 CU_TENSOR_MAP_L2_PROMOTION_L2_128B, CU_TENSOR_MAP_FLOAT_OOB_FILL_NONE);
}

extern "C" void kernel_launch(void* const* d_in, const int* in_sizes, int n_in,
                              void* d_out, int out_size)
{
    (void)in_sizes; (void)n_in; (void)out_size;
    const float* query = (const float*)d_in[0];
    const float* key   = (const float*)d_in[1];
    const float* value = (const float*)d_in[2];
    const float* pos   = (const float*)d_in[3];
    const float* Wq    = (const float*)d_in[4];
    const float* bq    = (const float*)d_in[5];
    const float* Wk    = (const float*)d_in[6];
    const float* bk    = (const float*)d_in[7];
    const float* Wv    = (const float*)d_in[8];
    const float* bv    = (const float*)d_in[9];
    const float* gK    = (const float*)d_in[10];
    const float* betaK = (const float*)d_in[11];
    const float* gV    = (const float*)d_in[12];
    const float* betaV = (const float*)d_in[13];
    const float* Wfc   = (const float*)d_in[14];
    const float* bfc   = (const float*)d_in[15];
    float* out = (float*)d_out;

    float *qp, *kp, *vp, *pa, *Gp;
    __nv_bfloat16 *ahi, *alo, *bhi, *blo;
    cudaGetSymbolAddress((void**)&qp, g_qp);
    cudaGetSymbolAddress((void**)&kp, g_kp);
    cudaGetSymbolAddress((void**)&vp, g_vp);
    cudaGetSymbolAddress((void**)&pa, g_pa);
    cudaGetSymbolAddress((void**)&Gp, g_G);
    cudaGetSymbolAddress((void**)&ahi, g_ahi);
    cudaGetSymbolAddress((void**)&alo, g_alo);
    cudaGetSymbolAddress((void**)&bhi, g_bhi);
    cudaGetSymbolAddress((void**)&blo, g_blo);

    cudaFuncSetAttribute(gemm_mma, cudaFuncAttributeMaxDynamicSharedMemorySize,
                         (int)SMEM_DYN);
    cudaFuncSetAttribute(g_kernel, cudaFuncAttributeMaxDynamicSharedMemorySize,
                         (129 + 128) * 132 * (int)sizeof(float));

    // Tensor maps (bf16 operands)
    CUtensorMap tAh, tAl, tBh, tBl, tA2h, tA2l, tB2h, tB2l;
    encode_bf16(&tAh, ahi, 1024, 32768, 1);
    encode_bf16(&tAl, alo, 1024, 32768, 1);
    encode_bf16(&tBh, bhi, 1024, 1024, 1);
    encode_bf16(&tBl, blo, 1024, 1024, 1);
    encode_bf16(&tA2h, ahi, 1032, 32768, 1);
    encode_bf16(&tA2l, alo, 1032, 32768, 1);
    encode_bf16(&tB2h, bhi, 1032, 1024, 4);
    encode_bf16(&tB2l, blo, 1032, 1024, 4);

    dim3 gProj(8, 256, 1);
    const int NA = 33554432, NW = 1048576, NG = 4227072;

    // Q projection
    split_kernel<<<NA / 1024, 256>>>(query, ahi, alo, NA);
    split_kernel<<<NW / 1024, 256>>>(Wq, bhi, blo, NW);
    gemm_mma<<<gProj, 256, SMEM_DYN>>>(tAh, tAl, tBh, tBl, bq, qp, 16, 32768, 0);

    // K projection
    split_kernel<<<NA / 1024, 256>>>(key, ahi, alo, NA);
    split_kernel<<<NW / 1024, 256>>>(Wk, bhi, blo, NW);
    gemm_mma<<<gProj, 256, SMEM_DYN>>>(tAh, tAl, tBh, tBl, bk, kp, 16, 32768, 0);

    // V projection
    split_kernel<<<NA / 1024, 256>>>(value, ahi, alo, NA);
    split_kernel<<<NW / 1024, 256>>>(Wv, bhi, blo, NW);
    gemm_mma<<<gProj, 256, SMEM_DYN>>>(tAh, tAl, tBh, tBl, bv, vp, 16, 32768, 0);

    // per-head LayerNorm on K and V (in place)
    ln_kernel<<<dim3(NM, 2), 256>>>(kp, vp, gK, betaK, gV, betaV);

    // p_attn = Kc^T Vc / S
    cudaMemsetAsync(pa, 0, (size_t)32 * NE * NE * sizeof(float));
    pa_core<<<dim3(2, 2, 128), 256>>>(kp, vp, pa);
    pa_edges<<<dim3(32, 8), 256>>>(kp, vp, pos, pa);

    // G' = pa @ Wfc_h^T  (B, 1024, 1032)
    g_kernel<<<dim3(8, NH, NB), 256, (129 + 128) * 132 * sizeof(float)>>>(pa, Wfc, Gp);

    // Qcat (bf16 hi/lo) + split G
    qcat_hl_kernel<<<NM, 256>>>(qp, pos, ahi, alo);
    split_kernel<<<NG / 1024, 256>>>(Gp, bhi, blo, NG);

    // out = Qcat @ G'^T(per-batch) + bfc
    gemm_mma<<<dim3(8, 64, 4), 256, SMEM_DYN>>>(tA2h, tA2l, tB2h, tB2l, bfc, out,
                                                17, 8192, 1);
}

// round 4
// speedup vs baseline: 3.5795x; 1.2735x over previous
#include <cuda_runtime.h>
#include <cuda.h>
#include <cuda_fp16.h>
#include <cstdint>
#include <cstddef>

// Problem constants
#define NB 4
#define NS 8192
#define ND 1024
#define NH 8
#define NDK 128
#define NE 129
#define NM 32768
#define KFC 1032

// ---------------- scratch (static device globals; no allocations) ----------
static __device__ float g_qp[33554432];     // (M, D)  q projection
static __device__ float g_kp[33554432];     // (M, D)  k projection (pre-LN)
static __device__ float g_vp[33554432];     // (M, D)  v projection (pre-LN)
static __device__ float g_pa[532512];       // (32, 129, 129) p_attn
static __device__ float g_G [4227072];      // (B, 1024, 1032) G'
static __device__ __half g_a16[33816576];   // A operand fp16 (acts / qcat)
static __device__ __half g_bh16[4227072];   // B operand hi (weights / G)
static __device__ __half g_bl16[4227072];   // B operand lo
static __device__ __half g_k16[33554432];   // LN'd K, head-major (bh,s,d) fp16
static __device__ __half g_vh16[33554432];  // LN'd V hi, head-major
static __device__ __half g_vl16[33554432];  // LN'd V lo, head-major

// ============================ PTX helpers ==================================
__device__ __forceinline__ uint32_t smem_u32(const void* p) {
    uint32_t a;
    asm("{ .reg .u64 t; cvta.to.shared.u64 t, %1; cvt.u32.u64 %0, t; }"
        : "=r"(a) : "l"(p));
    return a;
}
__device__ __forceinline__ void mbar_init(uint32_t mbar, uint32_t cnt) {
    asm volatile("mbarrier.init.shared.b64 [%0], %1;" :: "r"(mbar), "r"(cnt) : "memory");
}
__device__ __forceinline__ void mbar_expect_tx(uint32_t mbar, uint32_t bytes) {
    asm volatile("mbarrier.arrive.expect_tx.shared.b64 _, [%0], %1;"
                 :: "r"(mbar), "r"(bytes) : "memory");
}
__device__ __forceinline__ void mbar_arrive(uint32_t mbar) {
    asm volatile("mbarrier.arrive.shared.b64 _, [%0];" :: "r"(mbar) : "memory");
}
__device__ __forceinline__ void mbar_wait(uint32_t mbar, uint32_t parity) {
    asm volatile(
        "{\n\t.reg .pred P;\n\t"
        "BWL_%=:\n\t"
        "mbarrier.try_wait.parity.acquire.cta.shared::cta.b64 P, [%0], %1, 0x989680;\n\t"
        "@P bra.uni BWD_%=;\n\t"
        "bra.uni BWL_%=;\n\t"
        "BWD_%=:\n\t}"
        :: "r"(mbar), "r"(parity) : "memory");
}
__device__ __forceinline__ void tma_load_3d(uint32_t dst, const CUtensorMap* tm,
                                            int x, int y, int z, uint32_t mbar) {
    asm volatile(
        "cp.async.bulk.tensor.3d.shared::cta.global.tile.mbarrier::complete_tx::bytes "
        "[%0], [%1, {%2, %3, %4}], [%5];"
        :: "r"(dst), "l"(tm), "r"(x), "r"(y), "r"(z), "r"(mbar) : "memory");
}
__device__ __forceinline__ void fence_async_shared() {
    asm volatile("fence.proxy.async.shared::cta;" ::: "memory");
}
__device__ __forceinline__ void ldsm4(uint32_t* r, uint32_t addr) {
    asm volatile("ldmatrix.sync.aligned.m8n8.x4.shared.b16 {%0,%1,%2,%3}, [%4];"
                 : "=r"(r[0]), "=r"(r[1]), "=r"(r[2]), "=r"(r[3]) : "r"(addr));
}
__device__ __forceinline__ void ldsm4t(uint32_t* r, uint32_t addr) {
    asm volatile("ldmatrix.sync.aligned.m8n8.x4.trans.shared.b16 {%0,%1,%2,%3}, [%4];"
                 : "=r"(r[0]), "=r"(r[1]), "=r"(r[2]), "=r"(r[3]) : "r"(addr));
}
__device__ __forceinline__ void mma_f16(float* c, const uint32_t* a, const uint32_t* b) {
    asm volatile(
        "mma.sync.aligned.m16n8k16.row.col.f32.f16.f16.f32 "
        "{%0,%1,%2,%3}, {%4,%5,%6,%7}, {%8,%9}, {%0,%1,%2,%3};"
        : "+f"(c[0]), "+f"(c[1]), "+f"(c[2]), "+f"(c[3])
        : "r"(a[0]), "r"(a[1]), "r"(a[2]), "r"(a[3]), "r"(b[0]), "r"(b[1]));
}
// SW128 swizzled smem address: tile row (128B wide) r, byte col c
__device__ __forceinline__ uint32_t swz(uint32_t base, int r, int c) {
    return base + r * 128 + (c ^ ((r & 7) << 4));
}

// ============================ fp16 2-pass tensor-core GEMM =================
// C[M,1024] = A(MxK) * B(1024xK)^T + bias, A single fp16, B fp16 hi+lo.
// CTA tile 128x128, BK=64, 8 warps (warp tile 64x32), 4-stage TMA pipeline.
static constexpr int ST = 4;
static constexpr uint32_t OP_BYTES = 128 * 64 * 2;      // 16 KB per operand tile
static constexpr uint32_t STG_BYTES = 3 * OP_BYTES;     // 48 KB per stage
static constexpr uint32_t CTRL_BYTES = 1024;
static constexpr uint32_t SMEM_DYN = CTRL_BYTES + ST * STG_BYTES;  // 197632

__global__ __launch_bounds__(256, 1) void gemm_mma(
    const __grid_constant__ CUtensorMap tmA,
    const __grid_constant__ CUtensorMap tmBhi,
    const __grid_constant__ CUtensorMap tmBlo,
    const float* __restrict__ bias,
    float* __restrict__ C,
    int KB, int mRowsPerZ, int bBatched)
{
    extern __shared__ __align__(1024) char smem[];
    const uint32_t sb = smem_u32(smem);
    const int tid = threadIdx.x;
    const int wid = tid >> 5, lane = tid & 31;
    const int warp_row = wid >> 2;     // 0..1
    const int warp_col = wid & 3;      // 0..3

    const uint32_t full0  = sb;        // ST mbarriers, 8B each
    const uint32_t empty0 = sb + 64;
    const uint32_t tiles  = sb + CTRL_BYTES;

    const int n0 = blockIdx.x * 128;
    const int m0 = blockIdx.z * mRowsPerZ + blockIdx.y * 128;
    const int zB = bBatched ? blockIdx.z : 0;

    if (tid == 0) {
        for (int s = 0; s < ST; s++) {
            mbar_init(full0 + s * 8, 1);
            mbar_init(empty0 + s * 8, 256);
        }
        fence_async_shared();
    }
    __syncthreads();

    if (tid == 0) {
        for (int s = 0; s < ST; s++) {
            uint32_t fb = full0 + s * 8;
            mbar_expect_tx(fb, STG_BYTES);
            uint32_t a0 = tiles + s * STG_BYTES;
            tma_load_3d(a0,                &tmA,   s * 64, m0, 0,  fb);
            tma_load_3d(a0 + OP_BYTES,     &tmBhi, s * 64, n0, zB, fb);
            tma_load_3d(a0 + 2 * OP_BYTES, &tmBlo, s * 64, n0, zB, fb);
        }
    }

    float acc[4][4][4];
#pragma unroll
    for (int mi = 0; mi < 4; mi++)
#pragma unroll
        for (int ni = 0; ni < 4; ni++)
#pragma unroll
            for (int q = 0; q < 4; q++) acc[mi][ni][q] = 0.f;

    const int aR = lane & 15;
    const int aC = (lane >> 4) << 4;
    const int bR = ((lane >> 4) << 3) + (lane & 7);
    const int bC = ((lane >> 3) & 1) << 4;

    for (int kb = 0; kb < KB; kb++) {
        const int s = kb % ST;
        const uint32_t ph = (uint32_t)((kb / ST) & 1);
        mbar_wait(full0 + s * 8, ph);

        const uint32_t A0 = tiles + s * STG_BYTES;
        const uint32_t B0 = A0 + OP_BYTES;

#pragma unroll
        for (int ki = 0; ki < 4; ki++) {
            const int kc = ki * 32;
            uint32_t af[4][4], bhi[4][2], blo[4][2];
#pragma unroll
            for (int mi = 0; mi < 4; mi++) {
                int r = warp_row * 64 + mi * 16 + aR;
                ldsm4(af[mi], swz(A0, r, kc + aC));
            }
#pragma unroll
            for (int g = 0; g < 2; g++) {
                int r = warp_col * 32 + g * 16 + bR;
                uint32_t bd = swz(B0, r, kc + bC);
                uint32_t t[4];
                ldsm4(t, bd);
                bhi[2 * g][0] = t[0]; bhi[2 * g][1] = t[1];
                bhi[2 * g + 1][0] = t[2]; bhi[2 * g + 1][1] = t[3];
                ldsm4(t, bd + OP_BYTES);
                blo[2 * g][0] = t[0]; blo[2 * g][1] = t[1];
                blo[2 * g + 1][0] = t[2]; blo[2 * g + 1][1] = t[3];
            }
#pragma unroll
            for (int mi = 0; mi < 4; mi++)
#pragma unroll
                for (int ni = 0; ni < 4; ni++) {
                    mma_f16(acc[mi][ni], af[mi], bhi[ni]);
                    mma_f16(acc[mi][ni], af[mi], blo[ni]);
                }
        }

        mbar_arrive(empty0 + s * 8);

        if (tid == 0 && kb + ST < KB) {
            mbar_wait(empty0 + s * 8, ph);
            uint32_t fb = full0 + s * 8;
            mbar_expect_tx(fb, STG_BYTES);
            uint32_t a0 = tiles + s * STG_BYTES;
            int kx = (kb + ST) * 64;
            tma_load_3d(a0,                &tmA,   kx, m0, 0,  fb);
            tma_load_3d(a0 + OP_BYTES,     &tmBhi, kx, n0, zB, fb);
            tma_load_3d(a0 + 2 * OP_BYTES, &tmBlo, kx, n0, zB, fb);
        }
    }

#pragma unroll
    for (int mi = 0; mi < 4; mi++) {
        int r = m0 + warp_row * 64 + mi * 16 + (lane >> 2);
#pragma unroll
        for (int ni = 0; ni < 4; ni++) {
            int cc = n0 + warp_col * 32 + ni * 8 + (lane & 3) * 2;
            float b0v = bias[cc], b1v = bias[cc + 1];
            float2 v0 = { acc[mi][ni][0] + b0v, acc[mi][ni][1] + b1v };
            float2 v1 = { acc[mi][ni][2] + b0v, acc[mi][ni][3] + b1v };
            *(float2*)(C + (size_t)r * 1024 + cc) = v0;
            *(float2*)(C + (size_t)(r + 8) * 1024 + cc) = v1;
        }
    }
}

// ---------------------------------------------------------------------------
// fp32 -> fp16 single convert (n multiple of 8)
// ---------------------------------------------------------------------------
__global__ __launch_bounds__(256) void cvt16_kernel(
    const float* __restrict__ src, __half* __restrict__ dst, int n)
{
    int i = (blockIdx.x * 256 + threadIdx.x) * 8;
    if (i >= n) return;
    float4 v0 = *(const float4*)(src + i);
    float4 v1 = *(const float4*)(src + i + 4);
    __half2 h[4];
    h[0] = __floats2half2_rn(v0.x, v0.y);
    h[1] = __floats2half2_rn(v0.z, v0.w);
    h[2] = __floats2half2_rn(v1.x, v1.y);
    h[3] = __floats2half2_rn(v1.z, v1.w);
    *(uint4*)(dst + i) = *(uint4*)h;
}

// ---------------------------------------------------------------------------
// fp32 -> fp16 hi/lo split (n multiple of 4)
// ---------------------------------------------------------------------------
__global__ __launch_bounds__(256) void split16_kernel(
    const float* __restrict__ src, __half* __restrict__ hi,
    __half* __restrict__ lo, int n)
{
    int i = (blockIdx.x * 256 + threadIdx.x) * 4;
    if (i >= n) return;
    float4 v = *(const float4*)(src + i);
    __half h0 = __float2half_rn(v.x);
    __half h1 = __float2half_rn(v.y);
    __half h2 = __float2half_rn(v.z);
    __half h3 = __float2half_rn(v.w);
    __half l0 = __float2half_rn(v.x - __half2float(h0));
    __half l1 = __float2half_rn(v.y - __half2float(h1));
    __half l2 = __float2half_rn(v.z - __half2float(h2));
    __half l3 = __float2half_rn(v.w - __half2float(h3));
    __half2 hp[2] = { __half2(h0, h1), __half2(h2, h3) };
    __half2 lp[2] = { __half2(l0, l1), __half2(l2, l3) };
    *(uint2*)(hi + i) = *(uint2*)hp;
    *(uint2*)(lo + i) = *(uint2*)lp;
}

// ---------------------------------------------------------------------------
// Per-head LayerNorm; writes head-major fp16: K single, V hi/lo.
// grid (M, 2), block 256: warp w = head w of row m. y=0 -> K, y=1 -> V.
// ---------------------------------------------------------------------------
__global__ __launch_bounds__(256) void ln_kernel(
    const float* __restrict__ kp, const float* __restrict__ vp,
    const float* __restrict__ gK, const float* __restrict__ bK,
    const float* __restrict__ gV, const float* __restrict__ bV,
    __half* __restrict__ k16, __half* __restrict__ vh16, __half* __restrict__ vl16)
{
    const int m = blockIdx.x;
    const int isV = blockIdx.y;
    const float* buf = isV ? vp : kp;
    const float* g   = isV ? gV : gK;
    const float* be  = isV ? bV : bK;

    const int w = threadIdx.x >> 5;
    const int lane = threadIdx.x & 31;

    const float* p = buf + (size_t)m * ND + w * NDK + lane * 4;
    float4 x = *(const float4*)p;
    float s  = x.x + x.y + x.z + x.w;
    float s2 = x.x * x.x + x.y * x.y + x.z * x.z + x.w * x.w;
#pragma unroll
    for (int o = 16; o > 0; o >>= 1) {
        s  += __shfl_xor_sync(0xffffffffu, s,  o);
        s2 += __shfl_xor_sync(0xffffffffu, s2, o);
    }
    const float mean = s * (1.f / 128.f);
    const float var  = s2 * (1.f / 128.f) - mean * mean;
    const float rstd = rsqrtf(var + 1e-5f);

    float4 gv = *(const float4*)(g  + w * NDK + lane * 4);
    float4 bv = *(const float4*)(be + w * NDK + lane * 4);
    float y0 = (x.x - mean) * rstd * gv.x + bv.x;
    float y1 = (x.y - mean) * rstd * gv.y + bv.y;
    float y2 = (x.z - mean) * rstd * gv.z + bv.z;
    float y3 = (x.w - mean) * rstd * gv.w + bv.w;

    const int b = m >> 13, sIdx = m & 8191;
    const size_t base = (((size_t)(b * NH + w)) * NS + sIdx) * NDK + lane * 4;

    __half h0 = __float2half_rn(y0), h1 = __float2half_rn(y1);
    __half h2 = __float2half_rn(y2), h3 = __float2half_rn(y3);
    __half2 hp[2] = { __half2(h0, h1), __half2(h2, h3) };
    if (!isV) {
        *(uint2*)(k16 + base) = *(uint2*)hp;
    } else {
        *(uint2*)(vh16 + base) = *(uint2*)hp;
        __half2 lp[2] = {
            __half2(__float2half_rn(y0 - __half2float(h0)),
                    __float2half_rn(y1 - __half2float(h1))),
            __half2(__float2half_rn(y2 - __half2float(h2)),
                    __float2half_rn(y3 - __half2float(h3))) };
        *(uint2*)(vl16 + base) = *(uint2*)lp;
    }
}

// ---------------------------------------------------------------------------
// p_attn core (tensor): pa[bh][1+d][1+e] += sum_s k[s,d]*v[s,e] / S
// grid (32 bh, 8 s-split), block 256 (8 warps, warp tile 64x32).
// Contraction dim s is the ROW dim of the head-major tiles -> trans ldmatrix.
// ---------------------------------------------------------------------------
__global__ __launch_bounds__(256) void pa_core_mma(
    const __half* __restrict__ k16, const __half* __restrict__ vh16,
    const __half* __restrict__ vl16, float* __restrict__ pa)
{
    __shared__ __half Ks[32 * 136];
    __shared__ __half Vh[32 * 136];
    __shared__ __half Vl[32 * 136];

    const int bh = blockIdx.x;
    const int sp = blockIdx.y;
    const int tid = threadIdx.x;
    const int wid = tid >> 5, lane = tid & 31;
    const int warp_row = wid >> 2;     // d-dim, 2 x 64
    const int warp_col = wid & 3;      // e-dim, 4 x 32

    const uint32_t ksb = smem_u32(Ks);
    const uint32_t vhb = smem_u32(Vh);
    const uint32_t vlb = smem_u32(Vl);

    const size_t gbase = ((size_t)bh * NS + sp * 1024) * NDK;

    float acc[4][4][4];
#pragma unroll
    for (int mi = 0; mi < 4; mi++)
#pragma unroll
        for (int ni = 0; ni < 4; ni++)
#pragma unroll
            for (int q = 0; q < 4; q++) acc[mi][ni][q] = 0.f;

    // trans-ldmatrix lane addressing
    const int aRow = (lane & 7) | ((lane >> 4) << 3);         // A: k-subrow
    const int aCol = ((lane >> 3) & 1) << 3;                  // A: m offset
    const int bRow = (lane & 7) | (((lane >> 3) & 1) << 3);   // B: k-subrow
    const int bCol = ((lane >> 4) & 1) << 3;                  // B: n offset

    for (int s0 = 0; s0 < 1024; s0 += 32) {
        // load 32 x 128 fp16 tiles (3 arrays), row stride 136 halves
#pragma unroll
        for (int it = 0; it < 2; it++) {
            int f = tid + it * 256;
            int row = f >> 4;
            int c8 = (f & 15) * 8;
            size_t ga = gbase + (size_t)(s0 + row) * NDK + c8;
            int so = row * 136 + c8;
            *(float4*)(Ks + so) = *(const float4*)(k16 + ga);
            *(float4*)(Vh + so) = *(const float4*)(vh16 + ga);
            *(float4*)(Vl + so) = *(const float4*)(vl16 + ga);
        }
        __syncthreads();

#pragma unroll
        for (int ki = 0; ki < 2; ki++) {
            const int kio = ki * 16;
            uint32_t af[4][4], bhi[4][2], blo[4][2];
#pragma unroll
            for (int mi = 0; mi < 4; mi++) {
                int mcol = warp_row * 64 + mi * 16 + aCol;
                ldsm4t(af[mi], ksb + (kio + aRow) * 272 + mcol * 2);
            }
#pragma unroll
            for (int g = 0; g < 2; g++) {
                int ecol = warp_col * 32 + g * 16 + bCol;
                uint32_t off = (kio + bRow) * 272 + ecol * 2;
                uint32_t t[4];
                ldsm4t(t, vhb + off);
                bhi[2 * g][0] = t[0]; bhi[2 * g][1] = t[1];
                bhi[2 * g + 1][0] = t[2]; bhi[2 * g + 1][1] = t[3];
                ldsm4t(t, vlb + off);
                blo[2 * g][0] = t[0]; blo[2 * g][1] = t[1];
                blo[2 * g + 1][0] = t[2]; blo[2 * g + 1][1] = t[3];
            }
#pragma unroll
            for (int mi = 0; mi < 4; mi++)
#pragma unroll
                for (int ni = 0; ni < 4; ni++) {
                    mma_f16(acc[mi][ni], af[mi], bhi[ni]);
                    mma_f16(acc[mi][ni], af[mi], blo[ni]);
                }
        }
        __syncthreads();
    }

    const float invS = 1.0f / (float)NS;
    float* pab = pa + (size_t)bh * NE * NE;
#pragma unroll
    for (int mi = 0; mi < 4; mi++) {
        int d0 = warp_row * 64 + mi * 16 + (lane >> 2);
#pragma unroll
        for (int ni = 0; ni < 4; ni++) {
            int e0 = warp_col * 32 + ni * 8 + (lane & 3) * 2;
            atomicAdd(&pab[(1 + d0) * NE + 1 + e0],     acc[mi][ni][0] * invS);
            atomicAdd(&pab[(1 + d0) * NE + 2 + e0],     acc[mi][ni][1] * invS);
            atomicAdd(&pab[(1 + d0 + 8) * NE + 1 + e0], acc[mi][ni][2] * invS);
            atomicAdd(&pab[(1 + d0 + 8) * NE + 2 + e0], acc[mi][ni][3] * invS);
        }
    }
}

// ---------------------------------------------------------------------------
// p_attn edges: row 0 (pos . V), col 0 (K . pos), corner (pos . pos), /S
// ---------------------------------------------------------------------------
__global__ __launch_bounds__(256) void pa_edges(
    const __half* __restrict__ k16, const __half* __restrict__ vh16,
    const __half* __restrict__ vl16, const float* __restrict__ pos,
    float* __restrict__ pa)
{
    const int bh = blockIdx.x;
    const int b = bh >> 3;
    const int sp = blockIdx.y;

    const float* posb = pos + (size_t)b * NS + sp * 1024;
    const size_t gbase = ((size_t)bh * NS + sp * 1024) * NDK;

    const int tid = threadIdx.x;
    const int col = tid & 127;
    const bool doV = tid < 128;

    __shared__ float ps[256];
    float acc = 0.f;
    for (int s0 = 0; s0 < 1024; s0 += 256) {
        __syncthreads();
        ps[tid] = posb[s0 + tid];
        __syncthreads();
        for (int t = 0; t < 256; t++) {
            size_t idx = gbase + (size_t)(s0 + t) * NDK + col;
            float v = doV ? (__half2float(vh16[idx]) + __half2float(vl16[idx]))
                          : __half2float(k16[idx]);
            acc = fmaf(ps[t], v, acc);
        }
    }

    float p2 = 0.f;
    for (int s = tid; s < 1024; s += 256) {
        float p = posb[s];
        p2 = fmaf(p, p, p2);
    }

    const float invS = 1.0f / (float)NS;
    float* pab = pa + (size_t)bh * NE * NE;
    if (doV) atomicAdd(&pab[0 * NE + (1 + col)], acc * invS);
    else     atomicAdd(&pab[(1 + col) * NE + 0], acc * invS);

    __shared__ float red[256];
    red[tid] = p2;
    __syncthreads();
    for (int o = 128; o > 0; o >>= 1) {
        if (tid < o) red[tid] += red[tid + o];
        __syncthreads();
    }
    if (tid == 0) atomicAdd(&pab[0], red[0] * invS);
}

// ---------------------------------------------------------------------------
// G'[b][n][h*129+d] = sum_e pa[b,h,d,e] * Wfc[n, h*129+e]
// ---------------------------------------------------------------------------
__global__ __launch_bounds__(256) void g_kernel(
    const float* __restrict__ pa, const float* __restrict__ Wfc,
    float* __restrict__ Gp)
{
    extern __shared__ float sm[];
    float* pas = sm;               // 129 rows x 132 stride
    float* ws  = sm + 129 * 132;   // 128 rows x 132 stride

    const int nt = blockIdx.x, h = blockIdx.y, b = blockIdx.z;
    const int tid = threadIdx.x;
    const int n0 = nt * 128;

    const float* pab = pa + ((size_t)(b * NH + h)) * NE * NE;
    for (int i = tid; i < NE * NE; i += 256) {
        int d = i / NE, e = i - d * NE;
        pas[d * 132 + e] = pab[i];
    }
    for (int i = tid; i < 128 * NE; i += 256) {
        int n = i / NE, e = i - n * NE;
        ws[n * 132 + e] = Wfc[(size_t)(n0 + n) * KFC + h * NE + e];
    }
    __syncthreads();

    for (int o = tid; o < 128 * NE; o += 256) {
        int n = o / NE, d = o - n * NE;
        const float* pr = &pas[d * 132];
        const float* wr = &ws[n * 132];
        float acc = 0.f;
#pragma unroll 8
        for (int e4 = 0; e4 < 128; e4 += 4) {
            float4 a = *(const float4*)(pr + e4);
            float4 w = *(const float4*)(wr + e4);
            acc = fmaf(a.x, w.x, acc);
            acc = fmaf(a.y, w.y, acc);
            acc = fmaf(a.z, w.z, acc);
            acc = fmaf(a.w, w.w, acc);
        }
        acc = fmaf(pr[128], wr[128], acc);
        Gp[((size_t)b * ND + n0 + n) * KFC + h * NE + d] = acc;
    }
}

// ---------------------------------------------------------------------------
// Build Qcat (M, 1032) directly as single fp16
// ---------------------------------------------------------------------------
__global__ __launch_bounds__(256) void qcat16_kernel(
    const float* __restrict__ qp, const float* __restrict__ pos,
    __half* __restrict__ out)
{
    const int m = blockIdx.x;
    const float* qr = qp + (size_t)m * ND;
    const float pv = pos[m];
    __half* o = out + (size_t)m * KFC;
    for (int kk = threadIdx.x; kk < KFC; kk += 256) {
        int h = kk / NE;
        int d = kk - h * NE;
        float v = d ? qr[h * NDK + d - 1] : pv;
        o[kk] = __float2half_rn(v);
    }
}

// ============================ host side ====================================
typedef CUresult (*EncodeFn)(CUtensorMap*, CUtensorMapDataType, cuuint32_t, void*,
                             const cuuint64_t*, const cuuint64_t*, const cuuint32_t*,
                             const cuuint32_t*, CUtensorMapInterleave, CUtensorMapSwizzle,
                             CUtensorMapL2promotion, CUtensorMapFloatOOBfill);

static EncodeFn get_encode() {
    static EncodeFn fn = nullptr;
    if (!fn) {
        void* p = nullptr;
        cudaDriverEntryPointQueryResult st;
        cudaGetDriverEntryPoint("cuTensorMapEncodeTiled", &p, cudaEnableDefault, &st);
        fn = (EncodeFn)p;
    }
    return fn;
}

static void encode_f16(CUtensorMap* m, const void* base,
                       uint64_t kdim, uint64_t rows, uint64_t nz) {
    cuuint64_t dims[3]    = { kdim, rows, nz };
    cuuint64_t strides[2] = { kdim * 2, rows * kdim * 2 };
    cuuint32_t box[3]     = { 64, 128, 1 };
    cuuint32_t est[3]     = { 1, 1, 1 };
    get_encode()(m, CU_TENSOR_MAP_DATA_TYPE_FLOAT16, 3, (void*)base,
                 dims, strides, box, est,
                 CU_TENSOR_MAP_INTERLEAVE_NONE, CU_TENSOR_MAP_SWIZZLE_128B,
                 CU_TENSOR_MAP_L2_PROMOTION_L2_128B, CU_TENSOR_MAP_FLOAT_OOB_FILL_NONE);
}

extern "C" void kernel_launch(void* const* d_in, const int* in_sizes, int n_in,
                              void* d_out, int out_size)
{
    (void)in_sizes; (void)n_in; (void)out_size;
    const float* query = (const float*)d_in[0];
    const float* key   = (const float*)d_in[1];
    const float* value = (const float*)d_in[2];
    const float* pos   = (const float*)d_in[3];
    const float* Wq    = (const float*)d_in[4];
    const float* bq    = (const float*)d_in[5];
    const float* Wk    = (const float*)d_in[6];
    const float* bk    = (const float*)d_in[7];
    const float* Wv    = (const float*)d_in[8];
    const float* bv    = (const float*)d_in[9];
    const float* gK    = (const float*)d_in[10];
    const float* betaK = (const float*)d_in[11];
    const float* gV    = (const float*)d_in[12];
    const float* betaV = (const float*)d_in[13];
    const float* Wfc   = (const float*)d_in[14];
    const float* bfc   = (const float*)d_in[15];
    float* out = (float*)d_out;

    float *qp, *kp, *vp, *pa, *Gp;
    __half *a16, *bh16, *bl16, *k16, *vh16, *vl16;
    cudaGetSymbolAddress((void**)&qp, g_qp);
    cudaGetSymbolAddress((void**)&kp, g_kp);
    cudaGetSymbolAddress((void**)&vp, g_vp);
    cudaGetSymbolAddress((void**)&pa, g_pa);
    cudaGetSymbolAddress((void**)&Gp, g_G);
    cudaGetSymbolAddress((void**)&a16, g_a16);
    cudaGetSymbolAddress((void**)&bh16, g_bh16);
    cudaGetSymbolAddress((void**)&bl16, g_bl16);
    cudaGetSymbolAddress((void**)&k16, g_k16);
    cudaGetSymbolAddress((void**)&vh16, g_vh16);
    cudaGetSymbolAddress((void**)&vl16, g_vl16);

    cudaFuncSetAttribute(gemm_mma, cudaFuncAttributeMaxDynamicSharedMemorySize,
                         (int)SMEM_DYN);
    cudaFuncSetAttribute(g_kernel, cudaFuncAttributeMaxDynamicSharedMemorySize,
                         (129 + 128) * 132 * (int)sizeof(float));

    CUtensorMap tA, tBh, tBl, tA2, tB2h, tB2l;
    encode_f16(&tA,  a16,  1024, 32768, 1);
    encode_f16(&tBh, bh16, 1024, 1024, 1);
    encode_f16(&tBl, bl16, 1024, 1024, 1);
    encode_f16(&tA2, a16,  1032, 32768, 1);
    encode_f16(&tB2h, bh16, 1032, 1024, 4);
    encode_f16(&tB2l, bl16, 1032, 1024, 4);

    dim3 gProj(8, 256, 1);
    const int NA = 33554432, NW = 1048576, NG = 4227072;

    // Q projection
    cvt16_kernel<<<NA / 2048, 256>>>(query, a16, NA);
    split16_kernel<<<NW / 1024, 256>>>(Wq, bh16, bl16, NW);
    gemm_mma<<<gProj, 256, SMEM_DYN>>>(tA, tBh, tBl, bq, qp, 16, 32768, 0);

    // K projection
    cvt16_kernel<<<NA / 2048, 256>>>(key, a16, NA);
    split16_kernel<<<NW / 1024, 256>>>(Wk, bh16, bl16, NW);
    gemm_mma<<<gProj, 256, SMEM_DYN>>>(tA, tBh, tBl, bk, kp, 16, 32768, 0);

    // V projection
    cvt16_kernel<<<NA / 2048, 256>>>(value, a16, NA);
    split16_kernel<<<NW / 1024, 256>>>(Wv, bh16, bl16, NW);
    gemm_mma<<<gProj, 256, SMEM_DYN>>>(tA, tBh, tBl, bv, vp, 16, 32768, 0);

    // per-head LayerNorm -> head-major fp16 (K single, V hi/lo)
    ln_kernel<<<dim3(NM, 2), 256>>>(kp, vp, gK, betaK, gV, betaV, k16, vh16, vl16);

    // p_attn = Kc^T Vc / S
    cudaMemsetAsync(pa, 0, (size_t)32 * NE * NE * sizeof(float));
    pa_core_mma<<<dim3(32, 8), 256>>>(k16, vh16, vl16, pa);
    pa_edges<<<dim3(32, 8), 256>>>(k16, vh16, vl16, pos, pa);

    // G' = pa @ Wfc_h^T  (B, 1024, 1032)
    g_kernel<<<dim3(8, NH, NB), 256, (129 + 128) * 132 * sizeof(float)>>>(pa, Wfc, Gp);

    // Qcat fp16 + split G to fp16 hi/lo
    qcat16_kernel<<<NM, 256>>>(qp, pos, a16);
    split16_kernel<<<NG / 1024, 256>>>(Gp, bh16, bl16, NG);

    // out = Qcat @ G'^T(per-batch) + bfc
    gemm_mma<<<dim3(8, 64, 4), 256, SMEM_DYN>>>(tA2, tB2h, tB2l, bfc, out,
                                                17, 8192, 1);
}

// round 6
// speedup vs baseline: 5.2776x; 1.4744x over previous
#include <cuda_runtime.h>
#include <cuda.h>
#include <cuda_fp16.h>
#include <cstdint>
#include <cstddef>

// Problem constants
#define NB 4
#define NS 8192
#define ND 1024
#define NH 8
#define NDK 128
#define NE 129
#define NM 32768
#define KFC 1032

// ---------------- scratch (static device globals; no allocations) ----------
static __device__ float g_kp[33554432];     // (M, D)  k projection (pre-LN)
static __device__ float g_vp[33554432];     // (M, D)  v proj (pre-LN); later Wcomb
static __device__ float g_pa[532512];       // (32, 129, 129) p_attn
static __device__ float g_G [4227072];      // (B, 1024, 1024) Gd (head cols only)
static __device__ float g_gpos[4096];       // (B, 1024) pos-column of G (summed over h)
static __device__ float g_bias2[4096];      // (B, 1024) folded bias
static __device__ __half g_a16[33554432];   // A operand fp16 (acts / Gd hi+lo)
static __device__ __half g_bh16[4227072];   // B operand hi
static __device__ __half g_bl16[4227072];   // B operand lo
static __device__ __half g_k16[33554432];   // LN'd K, head-major (bh,s,d) fp16
static __device__ __half g_vh16[33554432];  // LN'd V hi, head-major
static __device__ __half g_vl16[33554432];  // LN'd V lo, head-major

// ============================ PTX helpers ==================================
__device__ __forceinline__ uint32_t smem_u32(const void* p) {
    uint32_t a;
    asm("{ .reg .u64 t; cvta.to.shared.u64 t, %1; cvt.u32.u64 %0, t; }"
        : "=r"(a) : "l"(p));
    return a;
}
__device__ __forceinline__ void mbar_init(uint32_t mbar, uint32_t cnt) {
    asm volatile("mbarrier.init.shared.b64 [%0], %1;" :: "r"(mbar), "r"(cnt) : "memory");
}
__device__ __forceinline__ void mbar_expect_tx(uint32_t mbar, uint32_t bytes) {
    asm volatile("mbarrier.arrive.expect_tx.shared.b64 _, [%0], %1;"
                 :: "r"(mbar), "r"(bytes) : "memory");
}
__device__ __forceinline__ void mbar_arrive(uint32_t mbar) {
    asm volatile("mbarrier.arrive.shared.b64 _, [%0];" :: "r"(mbar) : "memory");
}
__device__ __forceinline__ void mbar_wait(uint32_t mbar, uint32_t parity) {
    asm volatile(
        "{\n\t.reg .pred P;\n\t"
        "BWL_%=:\n\t"
        "mbarrier.try_wait.parity.acquire.cta.shared::cta.b64 P, [%0], %1, 0x989680;\n\t"
        "@P bra.uni BWD_%=;\n\t"
        "bra.uni BWL_%=;\n\t"
        "BWD_%=:\n\t}"
        :: "r"(mbar), "r"(parity) : "memory");
}
__device__ __forceinline__ void tma_load_3d(uint32_t dst, const CUtensorMap* tm,
                                            int x, int y, int z, uint32_t mbar) {
    asm volatile(
        "cp.async.bulk.tensor.3d.shared::cta.global.tile.mbarrier::complete_tx::bytes "
        "[%0], [%1, {%2, %3, %4}], [%5];"
        :: "r"(dst), "l"(tm), "r"(x), "r"(y), "r"(z), "r"(mbar) : "memory");
}
__device__ __forceinline__ void fence_async_shared() {
    asm volatile("fence.proxy.async.shared::cta;" ::: "memory");
}
__device__ __forceinline__ void ldsm4(uint32_t* r, uint32_t addr) {
    asm volatile("ldmatrix.sync.aligned.m8n8.x4.shared.b16 {%0,%1,%2,%3}, [%4];"
                 : "=r"(r[0]), "=r"(r[1]), "=r"(r[2]), "=r"(r[3]) : "r"(addr));
}
__device__ __forceinline__ void ldsm4t(uint32_t* r, uint32_t addr) {
    asm volatile("ldmatrix.sync.aligned.m8n8.x4.trans.shared.b16 {%0,%1,%2,%3}, [%4];"
                 : "=r"(r[0]), "=r"(r[1]), "=r"(r[2]), "=r"(r[3]) : "r"(addr));
}
__device__ __forceinline__ void mma_f16(float* c, const uint32_t* a, const uint32_t* b) {
    asm volatile(
        "mma.sync.aligned.m16n8k16.row.col.f32.f16.f16.f32 "
        "{%0,%1,%2,%3}, {%4,%5,%6,%7}, {%8,%9}, {%0,%1,%2,%3};"
        : "+f"(c[0]), "+f"(c[1]), "+f"(c[2]), "+f"(c[3])
        : "r"(a[0]), "r"(a[1]), "r"(a[2]), "r"(a[3]), "r"(b[0]), "r"(b[1]));
}
__device__ __forceinline__ uint32_t swz(uint32_t base, int r, int c) {
    return base + r * 128 + (c ^ ((r & 7) << 4));
}

// ============================ fp16 2-pass tensor-core GEMM =================
// C[M,1024] = A(MxK) * B(1024xK)^T + bias(+ optional rank-1 pos term).
// CTA tile 128x128, BK=64, 8 warps (warp tile 64x32), 4-stage TMA pipeline.
static constexpr int ST = 4;
static constexpr uint32_t OP_BYTES = 128 * 64 * 2;      // 16 KB per operand tile
static constexpr uint32_t STG_BYTES = 3 * OP_BYTES;     // 48 KB per stage
static constexpr uint32_t CTRL_BYTES = 1024;
static constexpr uint32_t SMEM_DYN = CTRL_BYTES + ST * STG_BYTES;  // 197632

__global__ __launch_bounds__(256, 1) void gemm_mma(
    const __grid_constant__ CUtensorMap tmA,
    const __grid_constant__ CUtensorMap tmBhi,
    const __grid_constant__ CUtensorMap tmBlo,
    const float* __restrict__ bias,
    float* __restrict__ C,
    int KB, int mRowsPerZ, int bBatched,
    const float* __restrict__ posv,   // nullptr or per-row scalar
    const float* __restrict__ gposv)  // nullptr or (B,1024)
{
    extern __shared__ __align__(1024) char smem[];
    const uint32_t sb = smem_u32(smem);
    const int tid = threadIdx.x;
    const int wid = tid >> 5, lane = tid & 31;
    const int warp_row = wid >> 2;
    const int warp_col = wid & 3;

    const uint32_t full0  = sb;
    const uint32_t empty0 = sb + 64;
    const uint32_t tiles  = sb + CTRL_BYTES;

    const int n0 = blockIdx.x * 128;
    const int m0 = blockIdx.z * mRowsPerZ + blockIdx.y * 128;
    const int zB = bBatched ? blockIdx.z : 0;

    if (tid == 0) {
        for (int s = 0; s < ST; s++) {
            mbar_init(full0 + s * 8, 1);
            mbar_init(empty0 + s * 8, 256);
        }
        fence_async_shared();
    }
    __syncthreads();

    if (tid == 0) {
        for (int s = 0; s < ST; s++) {
            uint32_t fb = full0 + s * 8;
            mbar_expect_tx(fb, STG_BYTES);
            uint32_t a0 = tiles + s * STG_BYTES;
            tma_load_3d(a0,                &tmA,   s * 64, m0, 0,  fb);
            tma_load_3d(a0 + OP_BYTES,     &tmBhi, s * 64, n0, zB, fb);
            tma_load_3d(a0 + 2 * OP_BYTES, &tmBlo, s * 64, n0, zB, fb);
        }
    }

    float acc[4][4][4];
#pragma unroll
    for (int mi = 0; mi < 4; mi++)
#pragma unroll
        for (int ni = 0; ni < 4; ni++)
#pragma unroll
            for (int q = 0; q < 4; q++) acc[mi][ni][q] = 0.f;

    const int aR = lane & 15;
    const int aC = (lane >> 4) << 4;
    const int bR = ((lane >> 4) << 3) + (lane & 7);
    const int bC = ((lane >> 3) & 1) << 4;

    for (int kb = 0; kb < KB; kb++) {
        const int s = kb % ST;
        const uint32_t ph = (uint32_t)((kb / ST) & 1);
        mbar_wait(full0 + s * 8, ph);

        const uint32_t A0 = tiles + s * STG_BYTES;
        const uint32_t B0 = A0 + OP_BYTES;

#pragma unroll
        for (int ki = 0; ki < 4; ki++) {
            const int kc = ki * 32;
            uint32_t af[4][4], bhi[4][2], blo[4][2];
#pragma unroll
            for (int mi = 0; mi < 4; mi++) {
                int r = warp_row * 64 + mi * 16 + aR;
                ldsm4(af[mi], swz(A0, r, kc + aC));
            }
#pragma unroll
            for (int g = 0; g < 2; g++) {
                int r = warp_col * 32 + g * 16 + bR;
                uint32_t bd = swz(B0, r, kc + bC);
                uint32_t t[4];
                ldsm4(t, bd);
                bhi[2 * g][0] = t[0]; bhi[2 * g][1] = t[1];
                bhi[2 * g + 1][0] = t[2]; bhi[2 * g + 1][1] = t[3];
                ldsm4(t, bd + OP_BYTES);
                blo[2 * g][0] = t[0]; blo[2 * g][1] = t[1];
                blo[2 * g + 1][0] = t[2]; blo[2 * g + 1][1] = t[3];
            }
#pragma unroll
            for (int mi = 0; mi < 4; mi++)
#pragma unroll
                for (int ni = 0; ni < 4; ni++) {
                    mma_f16(acc[mi][ni], af[mi], bhi[ni]);
                    mma_f16(acc[mi][ni], af[mi], blo[ni]);
                }
        }

        mbar_arrive(empty0 + s * 8);

        if (tid == 0 && kb + ST < KB) {
            mbar_wait(empty0 + s * 8, ph);
            uint32_t fb = full0 + s * 8;
            mbar_expect_tx(fb, STG_BYTES);
            uint32_t a0 = tiles + s * STG_BYTES;
            int kx = (kb + ST) * 64;
            tma_load_3d(a0,                &tmA,   kx, m0, 0,  fb);
            tma_load_3d(a0 + OP_BYTES,     &tmBhi, kx, n0, zB, fb);
            tma_load_3d(a0 + 2 * OP_BYTES, &tmBlo, kx, n0, zB, fb);
        }
    }

    const float* biasp = gposv ? (bias + zB * 1024) : bias;
    const float* gpp   = gposv ? (gposv + zB * 1024) : nullptr;

#pragma unroll
    for (int mi = 0; mi < 4; mi++) {
        int r = m0 + warp_row * 64 + mi * 16 + (lane >> 2);
        float pv = posv ? posv[r] : 0.f;
        float pv2 = posv ? posv[r + 8] : 0.f;
#pragma unroll
        for (int ni = 0; ni < 4; ni++) {
            int cc = n0 + warp_col * 32 + ni * 8 + (lane & 3) * 2;
            float b0v = biasp[cc], b1v = biasp[cc + 1];
            float g0 = gpp ? gpp[cc] : 0.f;
            float g1 = gpp ? gpp[cc + 1] : 0.f;
            float2 v0 = { acc[mi][ni][0] + b0v + pv * g0,
                          acc[mi][ni][1] + b1v + pv * g1 };
            float2 v1 = { acc[mi][ni][2] + b0v + pv2 * g0,
                          acc[mi][ni][3] + b1v + pv2 * g1 };
            *(float2*)(C + (size_t)r * 1024 + cc) = v0;
            *(float2*)(C + (size_t)(r + 8) * 1024 + cc) = v1;
        }
    }
}

// ============================ 3-pass GEMM (A hi/lo, B hi/lo) ===============
// Wcomb[b] = Gd[b] (1024x1024) * WqT (as B, rows = Wq columns), near-fp32.
static constexpr int ST3 = 3;
static constexpr uint32_t STG3_BYTES = 4 * OP_BYTES;    // 64 KB per stage
static constexpr uint32_t SMEM3_DYN = CTRL_BYTES + ST3 * STG3_BYTES;  // 197632

__global__ __launch_bounds__(256, 1) void gemm_mma3(
    const __grid_constant__ CUtensorMap tmAhi,
    const __grid_constant__ CUtensorMap tmAlo,
    const __grid_constant__ CUtensorMap tmBhi,
    const __grid_constant__ CUtensorMap tmBlo,
    float* __restrict__ C, int KB)
{
    extern __shared__ __align__(1024) char smem[];
    const uint32_t sb = smem_u32(smem);
    const int tid = threadIdx.x;
    const int wid = tid >> 5, lane = tid & 31;
    const int warp_row = wid >> 2;
    const int warp_col = wid & 3;

    const uint32_t full0  = sb;
    const uint32_t empty0 = sb + 64;
    const uint32_t tiles  = sb + CTRL_BYTES;

    const int n0 = blockIdx.x * 128;
    const int aY = blockIdx.y * 128;
    const int aZ = blockIdx.z;
    const int m0 = blockIdx.z * 1024 + aY;

    if (tid == 0) {
        for (int s = 0; s < ST3; s++) {
            mbar_init(full0 + s * 8, 1);
            mbar_init(empty0 + s * 8, 256);
        }
        fence_async_shared();
    }
    __syncthreads();

    if (tid == 0) {
        for (int s = 0; s < ST3; s++) {
            uint32_t fb = full0 + s * 8;
            mbar_expect_tx(fb, STG3_BYTES);
            uint32_t a0 = tiles + s * STG3_BYTES;
            tma_load_3d(a0,                &tmAhi, s * 64, aY, aZ, fb);
            tma_load_3d(a0 + OP_BYTES,     &tmAlo, s * 64, aY, aZ, fb);
            tma_load_3d(a0 + 2 * OP_BYTES, &tmBhi, s * 64, n0, 0,  fb);
            tma_load_3d(a0 + 3 * OP_BYTES, &tmBlo, s * 64, n0, 0,  fb);
        }
    }

    float acc[4][4][4];
#pragma unroll
    for (int mi = 0; mi < 4; mi++)
#pragma unroll
        for (int ni = 0; ni < 4; ni++)
#pragma unroll
            for (int q = 0; q < 4; q++) acc[mi][ni][q] = 0.f;

    const int aR = lane & 15;
    const int aC = (lane >> 4) << 4;
    const int bR = ((lane >> 4) << 3) + (lane & 7);
    const int bC = ((lane >> 3) & 1) << 4;

    for (int kb = 0; kb < KB; kb++) {
        const int s = kb % ST3;
        const uint32_t ph = (uint32_t)((kb / ST3) & 1);
        mbar_wait(full0 + s * 8, ph);

        const uint32_t A0 = tiles + s * STG3_BYTES;
        const uint32_t B0 = A0 + 2 * OP_BYTES;

#pragma unroll
        for (int ki = 0; ki < 4; ki++) {
            const int kc = ki * 32;
            uint32_t ahi[4][4], alo[4][4], bhi[4][2], blo[4][2];
#pragma unroll
            for (int mi = 0; mi < 4; mi++) {
                int r = warp_row * 64 + mi * 16 + aR;
                uint32_t ad = swz(A0, r, kc + aC);
                ldsm4(ahi[mi], ad);
                ldsm4(alo[mi], ad + OP_BYTES);
            }
#pragma unroll
            for (int g = 0; g < 2; g++) {
                int r = warp_col * 32 + g * 16 + bR;
                uint32_t bd = swz(B0, r, kc + bC);
                uint32_t t[4];
                ldsm4(t, bd);
                bhi[2 * g][0] = t[0]; bhi[2 * g][1] = t[1];
                bhi[2 * g + 1][0] = t[2]; bhi[2 * g + 1][1] = t[3];
                ldsm4(t, bd + OP_BYTES);
                blo[2 * g][0] = t[0]; blo[2 * g][1] = t[1];
                blo[2 * g + 1][0] = t[2]; blo[2 * g + 1][1] = t[3];
            }
#pragma unroll
            for (int mi = 0; mi < 4; mi++)
#pragma unroll
                for (int ni = 0; ni < 4; ni++) {
                    mma_f16(acc[mi][ni], ahi[mi], bhi[ni]);
                    mma_f16(acc[mi][ni], ahi[mi], blo[ni]);
                    mma_f16(acc[mi][ni], alo[mi], bhi[ni]);
                }
        }

        mbar_arrive(empty0 + s * 8);

        if (tid == 0 && kb + ST3 < KB) {
            mbar_wait(empty0 + s * 8, ph);
            uint32_t fb = full0 + s * 8;
            mbar_expect_tx(fb, STG3_BYTES);
            uint32_t a0 = tiles + s * STG3_BYTES;
            int kx = (kb + ST3) * 64;
            tma_load_3d(a0,                &tmAhi, kx, aY, aZ, fb);
            tma_load_3d(a0 + OP_BYTES,     &tmAlo, kx, aY, aZ, fb);
            tma_load_3d(a0 + 2 * OP_BYTES, &tmBhi, kx, n0, 0,  fb);
            tma_load_3d(a0 + 3 * OP_BYTES, &tmBlo, kx, n0, 0,  fb);
        }
    }

#pragma unroll
    for (int mi = 0; mi < 4; mi++) {
        int r = m0 + warp_row * 64 + mi * 16 + (lane >> 2);
#pragma unroll
        for (int ni = 0; ni < 4; ni++) {
            int cc = n0 + warp_col * 32 + ni * 8 + (lane & 3) * 2;
            float2 v0 = { acc[mi][ni][0], acc[mi][ni][1] };
            float2 v1 = { acc[mi][ni][2], acc[mi][ni][3] };
            *(float2*)(C + (size_t)r * 1024 + cc) = v0;
            *(float2*)(C + (size_t)(r + 8) * 1024 + cc) = v1;
        }
    }
}

// ---------------------------------------------------------------------------
// fp32 -> fp16 single convert (n multiple of 8)
// ---------------------------------------------------------------------------
__global__ __launch_bounds__(256) void cvt16_kernel(
    const float* __restrict__ src, __half* __restrict__ dst, int n)
{
    int i = (blockIdx.x * 256 + threadIdx.x) * 8;
    if (i >= n) return;
    float4 v0 = *(const float4*)(src + i);
    float4 v1 = *(const float4*)(src + i + 4);
    __half2 h[4];
    h[0] = __floats2half2_rn(v0.x, v0.y);
    h[1] = __floats2half2_rn(v0.z, v0.w);
    h[2] = __floats2half2_rn(v1.x, v1.y);
    h[3] = __floats2half2_rn(v1.z, v1.w);
    *(uint4*)(dst + i) = *(uint4*)h;
}

// ---------------------------------------------------------------------------
// fp32 -> fp16 hi/lo split (n multiple of 4)
// ---------------------------------------------------------------------------
__global__ __launch_bounds__(256) void split16_kernel(
    const float* __restrict__ src, __half* __restrict__ hi,
    __half* __restrict__ lo, int n)
{
    int i = (blockIdx.x * 256 + threadIdx.x) * 4;
    if (i >= n) return;
    float4 v = *(const float4*)(src + i);
    __half h0 = __float2half_rn(v.x);
    __half h1 = __float2half_rn(v.y);
    __half h2 = __float2half_rn(v.z);
    __half h3 = __float2half_rn(v.w);
    __half l0 = __float2half_rn(v.x - __half2float(h0));
    __half l1 = __float2half_rn(v.y - __half2float(h1));
    __half l2 = __float2half_rn(v.z - __half2float(h2));
    __half l3 = __float2half_rn(v.w - __half2float(h3));
    __half2 hp[2] = { __half2(h0, h1), __half2(h2, h3) };
    __half2 lp[2] = { __half2(l0, l1), __half2(l2, l3) };
    *(uint2*)(hi + i) = *(uint2*)hp;
    *(uint2*)(lo + i) = *(uint2*)lp;
}

// ---------------------------------------------------------------------------
// Transposed fp32 -> fp16 hi/lo split: hi[j*1024+i] = fp16(W[i*1024+j])
// ---------------------------------------------------------------------------
__global__ __launch_bounds__(256) void tsplit16_kernel(
    const float* __restrict__ W, __half* __restrict__ hi, __half* __restrict__ lo)
{
    __shared__ float t[32][33];
    const int o0 = blockIdx.y * 32, i0 = blockIdx.x * 32;
    const int c = threadIdx.x & 31;
    const int r0 = threadIdx.x >> 5;
#pragma unroll
    for (int it = 0; it < 4; it++) {
        int r = r0 + it * 8;
        t[r][c] = W[(size_t)(o0 + r) * 1024 + i0 + c];
    }
    __syncthreads();
#pragma unroll
    for (int it = 0; it < 4; it++) {
        int r = r0 + it * 8;
        float v = t[c][r];
        __half h = __float2half_rn(v);
        size_t idx = (size_t)(i0 + r) * 1024 + o0 + c;
        hi[idx] = h;
        lo[idx] = __float2half_rn(v - __half2float(h));
    }
}

// ---------------------------------------------------------------------------
// Per-head LayerNorm; writes head-major fp16: K single, V hi/lo.
// ---------------------------------------------------------------------------
__global__ __launch_bounds__(256) void ln_kernel(
    const float* __restrict__ kp, const float* __restrict__ vp,
    const float* __restrict__ gK, const float* __restrict__ bK,
    const float* __restrict__ gV, const float* __restrict__ bV,
    __half* __restrict__ k16, __half* __restrict__ vh16, __half* __restrict__ vl16)
{
    const int m = blockIdx.x;
    const int isV = blockIdx.y;
    const float* buf = isV ? vp : kp;
    const float* g   = isV ? gV : gK;
    const float* be  = isV ? bV : bK;

    const int w = threadIdx.x >> 5;
    const int lane = threadIdx.x & 31;

    const float* p = buf + (size_t)m * ND + w * NDK + lane * 4;
    float4 x = *(const float4*)p;
    float s  = x.x + x.y + x.z + x.w;
    float s2 = x.x * x.x + x.y * x.y + x.z * x.z + x.w * x.w;
#pragma unroll
    for (int o = 16; o > 0; o >>= 1) {
        s  += __shfl_xor_sync(0xffffffffu, s,  o);
        s2 += __shfl_xor_sync(0xffffffffu, s2, o);
    }
    const float mean = s * (1.f / 128.f);
    const float var  = s2 * (1.f / 128.f) - mean * mean;
    const float rstd = rsqrtf(var + 1e-5f);

    float4 gv = *(const float4*)(g  + w * NDK + lane * 4);
    float4 bv = *(const float4*)(be + w * NDK + lane * 4);
    float y0 = (x.x - mean) * rstd * gv.x + bv.x;
    float y1 = (x.y - mean) * rstd * gv.y + bv.y;
    float y2 = (x.z - mean) * rstd * gv.z + bv.z;
    float y3 = (x.w - mean) * rstd * gv.w + bv.w;

    const int b = m >> 13, sIdx = m & 8191;
    const size_t base = (((size_t)(b * NH + w)) * NS + sIdx) * NDK + lane * 4;

    __half h0 = __float2half_rn(y0), h1 = __float2half_rn(y1);
    __half h2 = __float2half_rn(y2), h3 = __float2half_rn(y3);
    __half2 hp[2] = { __half2(h0, h1), __half2(h2, h3) };
    if (!isV) {
        *(uint2*)(k16 + base) = *(uint2*)hp;
    } else {
        *(uint2*)(vh16 + base) = *(uint2*)hp;
        __half2 lp[2] = {
            __half2(__float2half_rn(y0 - __half2float(h0)),
                    __float2half_rn(y1 - __half2float(h1))),
            __half2(__float2half_rn(y2 - __half2float(h2)),
                    __float2half_rn(y3 - __half2float(h3))) };
        *(uint2*)(vl16 + base) = *(uint2*)lp;
    }
}

// ---------------------------------------------------------------------------
// p_attn core + edges fused. grid (32 bh, 8 s-split), block 256.
// ---------------------------------------------------------------------------
__global__ __launch_bounds__(256) void pa_core_mma(
    const __half* __restrict__ k16, const __half* __restrict__ vh16,
    const __half* __restrict__ vl16, const float* __restrict__ pos,
    float* __restrict__ pa)
{
    __shared__ __half Ks[32 * 136];
    __shared__ __half Vh[32 * 136];
    __shared__ __half Vl[32 * 136];
    __shared__ float ps[32];

    const int bh = blockIdx.x;
    const int b = bh >> 3;
    const int sp = blockIdx.y;
    const int tid = threadIdx.x;
    const int wid = tid >> 5, lane = tid & 31;
    const int warp_row = wid >> 2;
    const int warp_col = wid & 3;

    const uint32_t ksb = smem_u32(Ks);
    const uint32_t vhb = smem_u32(Vh);
    const uint32_t vlb = smem_u32(Vl);

    const size_t gbase = ((size_t)bh * NS + sp * 1024) * NDK;
    const float* posb = pos + (size_t)b * NS + sp * 1024;

    float acc[4][4][4];
#pragma unroll
    for (int mi = 0; mi < 4; mi++)
#pragma unroll
        for (int ni = 0; ni < 4; ni++)
#pragma unroll
            for (int q = 0; q < 4; q++) acc[mi][ni][q] = 0.f;

    float eacc = 0.f;
    float p2 = 0.f;

    const int aRow = (lane & 7) | ((lane >> 4) << 3);
    const int aCol = ((lane >> 3) & 1) << 3;
    const int bRow = (lane & 7) | (((lane >> 3) & 1) << 3);
    const int bCol = ((lane >> 4) & 1) << 3;
    const int ecol = tid & 127;

    for (int s0 = 0; s0 < 1024; s0 += 32) {
#pragma unroll
        for (int it = 0; it < 2; it++) {
            int f = tid + it * 256;
            int row = f >> 4;
            int c8 = (f & 15) * 8;
            size_t ga = gbase + (size_t)(s0 + row) * NDK + c8;
            int so = row * 136 + c8;
            *(float4*)(Ks + so) = *(const float4*)(k16 + ga);
            *(float4*)(Vh + so) = *(const float4*)(vh16 + ga);
            *(float4*)(Vl + so) = *(const float4*)(vl16 + ga);
        }
        if (tid < 32) ps[tid] = posb[s0 + tid];
        __syncthreads();

#pragma unroll
        for (int ki = 0; ki < 2; ki++) {
            const int kio = ki * 16;
            uint32_t af[4][4], bhi[4][2], blo[4][2];
#pragma unroll
            for (int mi = 0; mi < 4; mi++) {
                int mcol = warp_row * 64 + mi * 16 + aCol;
                ldsm4t(af[mi], ksb + (kio + aRow) * 272 + mcol * 2);
            }
#pragma unroll
            for (int g = 0; g < 2; g++) {
                int ec = warp_col * 32 + g * 16 + bCol;
                uint32_t off = (kio + bRow) * 272 + ec * 2;
                uint32_t t[4];
                ldsm4t(t, vhb + off);
                bhi[2 * g][0] = t[0]; bhi[2 * g][1] = t[1];
                bhi[2 * g + 1][0] = t[2]; bhi[2 * g + 1][1] = t[3];
                ldsm4t(t, vlb + off);
                blo[2 * g][0] = t[0]; blo[2 * g][1] = t[1];
                blo[2 * g + 1][0] = t[2]; blo[2 * g + 1][1] = t[3];
            }
#pragma unroll
            for (int mi = 0; mi < 4; mi++)
#pragma unroll
                for (int ni = 0; ni < 4; ni++) {
                    mma_f16(acc[mi][ni], af[mi], bhi[ni]);
                    mma_f16(acc[mi][ni], af[mi], blo[ni]);
                }
        }

        if (tid < 128) {
#pragma unroll 8
            for (int r = 0; r < 32; r++) {
                float v = __half2float(Vh[r * 136 + ecol]) +
                          __half2float(Vl[r * 136 + ecol]);
                eacc = fmaf(ps[r], v, eacc);
            }
        } else {
#pragma unroll 8
            for (int r = 0; r < 32; r++)
                eacc = fmaf(ps[r], __half2float(Ks[r * 136 + ecol]), eacc);
        }
        if (wid == 0) { float pv = ps[lane]; p2 = fmaf(pv, pv, p2); }
        __syncthreads();
    }

    const float invS = 1.0f / (float)NS;
    float* pab = pa + (size_t)bh * NE * NE;
#pragma unroll
    for (int mi = 0; mi < 4; mi++) {
        int d0 = warp_row * 64 + mi * 16 + (lane >> 2);
#pragma unroll
        for (int ni = 0; ni < 4; ni++) {
            int e0 = warp_col * 32 + ni * 8 + (lane & 3) * 2;
            atomicAdd(&pab[(1 + d0) * NE + 1 + e0],     acc[mi][ni][0] * invS);
            atomicAdd(&pab[(1 + d0) * NE + 2 + e0],     acc[mi][ni][1] * invS);
            atomicAdd(&pab[(1 + d0 + 8) * NE + 1 + e0], acc[mi][ni][2] * invS);
            atomicAdd(&pab[(1 + d0 + 8) * NE + 2 + e0], acc[mi][ni][3] * invS);
        }
    }
    if (tid < 128) atomicAdd(&pab[0 * NE + 1 + ecol], eacc * invS);
    else           atomicAdd(&pab[(1 + ecol) * NE + 0], eacc * invS);
    if (wid == 0) {
#pragma unroll
        for (int o = 16; o > 0; o >>= 1)
            p2 += __shfl_xor_sync(0xffffffffu, p2, o);
        if (lane == 0) atomicAdd(&pab[0], p2 * invS);
    }
}

// ---------------------------------------------------------------------------
// Gd[b][n][h*128+d-1] = sum_e pa[b,h,d,e]*Wfc[n, h*129+e]
// d==0 col -> atomicAdd into gpos (summed over heads; gpos pre-zeroed!)
// ---------------------------------------------------------------------------
__global__ __launch_bounds__(256) void g_kernel(
    const float* __restrict__ pa, const float* __restrict__ Wfc,
    float* __restrict__ Gd, float* __restrict__ gpos)
{
    extern __shared__ float sm[];
    float* pas = sm;               // 129 rows x 132 stride
    float* ws  = sm + 129 * 132;   // 128 rows x 132 stride

    const int nt = blockIdx.x, h = blockIdx.y, b = blockIdx.z;
    const int tid = threadIdx.x;
    const int n0 = nt * 128;

    const float* pab = pa + ((size_t)(b * NH + h)) * NE * NE;
    for (int i = tid; i < NE * NE; i += 256) {
        int d = i / NE, e = i - d * NE;
        pas[d * 132 + e] = pab[i];
    }
    for (int i = tid; i < 128 * NE; i += 256) {
        int n = i / NE, e = i - n * NE;
        ws[n * 132 + e] = Wfc[(size_t)(n0 + n) * KFC + h * NE + e];
    }
    __syncthreads();

    for (int o = tid; o < 128 * NE; o += 256) {
        int n = o / NE, d = o - n * NE;
        const float* pr = &pas[d * 132];
        const float* wr = &ws[n * 132];
        float acc = 0.f;
#pragma unroll 8
        for (int e4 = 0; e4 < 128; e4 += 4) {
            float4 a = *(const float4*)(pr + e4);
            float4 w = *(const float4*)(wr + e4);
            acc = fmaf(a.x, w.x, acc);
            acc = fmaf(a.y, w.y, acc);
            acc = fmaf(a.z, w.z, acc);
            acc = fmaf(a.w, w.w, acc);
        }
        acc = fmaf(pr[128], wr[128], acc);
        if (d == 0)
            atomicAdd(&gpos[b * 1024 + n0 + n], acc);   // SUM over heads
        else
            Gd[((size_t)b * 1024 + n0 + n) * 1024 + h * NDK + d - 1] = acc;
    }
}

// ---------------------------------------------------------------------------
// bias2[b][n] = bfc[n] + sum_o bq[o] * Gd[b][n][o]
// ---------------------------------------------------------------------------
__global__ __launch_bounds__(256) void bias2_kernel(
    const float* __restrict__ Gd, const float* __restrict__ bq,
    const float* __restrict__ bfc, float* __restrict__ bias2)
{
    const int n = blockIdx.x, b = blockIdx.y;
    const int tid = threadIdx.x;
    const float* row = Gd + ((size_t)b * 1024 + n) * 1024;
    float acc = 0.f;
    for (int o = tid; o < 1024; o += 256) acc = fmaf(bq[o], row[o], acc);
    __shared__ float red[256];
    red[tid] = acc;
    __syncthreads();
    for (int o = 128; o > 0; o >>= 1) {
        if (tid < o) red[tid] += red[tid + o];
        __syncthreads();
    }
    if (tid == 0) bias2[b * 1024 + n] = red[0] + bfc[n];
}

// ============================ host side ====================================
typedef CUresult (*EncodeFn)(CUtensorMap*, CUtensorMapDataType, cuuint32_t, void*,
                             const cuuint64_t*, const cuuint64_t*, const cuuint32_t*,
                             const cuuint32_t*, CUtensorMapInterleave, CUtensorMapSwizzle,
                             CUtensorMapL2promotion, CUtensorMapFloatOOBfill);

static EncodeFn get_encode() {
    static EncodeFn fn = nullptr;
    if (!fn) {
        void* p = nullptr;
        cudaDriverEntryPointQueryResult st;
        cudaGetDriverEntryPoint("cuTensorMapEncodeTiled", &p, cudaEnableDefault, &st);
        fn = (EncodeFn)p;
    }
    return fn;
}

static void encode_f16(CUtensorMap* m, const void* base,
                       uint64_t kdim, uint64_t rows, uint64_t nz) {
    cuuint64_t dims[3]    = { kdim, rows, nz };
    cuuint64_t strides[2] = { kdim * 2, rows * kdim * 2 };
    cuuint32_t box[3]     = { 64, 128, 1 };
    cuuint32_t est[3]     = { 1, 1, 1 };
    get_encode()(m, CU_TENSOR_MAP_DATA_TYPE_FLOAT16, 3, (void*)base,
                 dims, strides, box, est,
                 CU_TENSOR_MAP_INTERLEAVE_NONE, CU_TENSOR_MAP_SWIZZLE_128B,
                 CU_TENSOR_MAP_L2_PROMOTION_L2_128B, CU_TENSOR_MAP_FLOAT_OOB_FILL_NONE);
}

extern "C" void kernel_launch(void* const* d_in, const int* in_sizes, int n_in,
                              void* d_out, int out_size)
{
    (void)in_sizes; (void)n_in; (void)out_size;
    const float* query = (const float*)d_in[0];
    const float* key   = (const float*)d_in[1];
    const float* value = (const float*)d_in[2];
    const float* pos   = (const float*)d_in[3];
    const float* Wq    = (const float*)d_in[4];
    const float* bq    = (const float*)d_in[5];
    const float* Wk    = (const float*)d_in[6];
    const float* bk    = (const float*)d_in[7];
    const float* Wv    = (const float*)d_in[8];
    const float* bv    = (const float*)d_in[9];
    const float* gK    = (const float*)d_in[10];
    const float* betaK = (const float*)d_in[11];
    const float* gV    = (const float*)d_in[12];
    const float* betaV = (const float*)d_in[13];
    const float* Wfc   = (const float*)d_in[14];
    const float* bfc   = (const float*)d_in[15];
    float* out = (float*)d_out;

    float *kp, *vp, *pa, *Gd, *gpos, *bias2;
    __half *a16, *bh16, *bl16, *k16, *vh16, *vl16;
    cudaGetSymbolAddress((void**)&kp, g_kp);
    cudaGetSymbolAddress((void**)&vp, g_vp);
    cudaGetSymbolAddress((void**)&pa, g_pa);
    cudaGetSymbolAddress((void**)&Gd, g_G);
    cudaGetSymbolAddress((void**)&gpos, g_gpos);
    cudaGetSymbolAddress((void**)&bias2, g_bias2);
    cudaGetSymbolAddress((void**)&a16, g_a16);
    cudaGetSymbolAddress((void**)&bh16, g_bh16);
    cudaGetSymbolAddress((void**)&bl16, g_bl16);
    cudaGetSymbolAddress((void**)&k16, g_k16);
    cudaGetSymbolAddress((void**)&vh16, g_vh16);
    cudaGetSymbolAddress((void**)&vl16, g_vl16);

    cudaFuncSetAttribute(gemm_mma, cudaFuncAttributeMaxDynamicSharedMemorySize,
                         (int)SMEM_DYN);
    cudaFuncSetAttribute(gemm_mma3, cudaFuncAttributeMaxDynamicSharedMemorySize,
                         (int)SMEM3_DYN);
    cudaFuncSetAttribute(g_kernel, cudaFuncAttributeMaxDynamicSharedMemorySize,
                         (129 + 128) * 132 * (int)sizeof(float));

    CUtensorMap tAct, tB1h, tB1l, tGh, tGl, tB4h, tB4l;
    encode_f16(&tAct, a16,  1024, 32768, 1);
    encode_f16(&tB1h, bh16, 1024, 1024, 1);
    encode_f16(&tB1l, bl16, 1024, 1024, 1);
    encode_f16(&tGh,  a16,           1024, 1024, 4);
    encode_f16(&tGl,  a16 + 4194304, 1024, 1024, 4);
    encode_f16(&tB4h, bh16, 1024, 1024, 4);
    encode_f16(&tB4l, bl16, 1024, 1024, 4);

    dim3 gProj(8, 256, 1);
    const int NA = 33554432, NW = 1048576, NGD = 4194304;

    // K projection
    cvt16_kernel<<<NA / 2048, 256>>>(key, a16, NA);
    split16_kernel<<<NW / 1024, 256>>>(Wk, bh16, bl16, NW);
    gemm_mma<<<gProj, 256, SMEM_DYN>>>(tAct, tB1h, tB1l, bk, kp, 16, 32768, 0,
                                       nullptr, nullptr);

    // V projection
    cvt16_kernel<<<NA / 2048, 256>>>(value, a16, NA);
    split16_kernel<<<NW / 1024, 256>>>(Wv, bh16, bl16, NW);
    gemm_mma<<<gProj, 256, SMEM_DYN>>>(tAct, tB1h, tB1l, bv, vp, 16, 32768, 0,
                                       nullptr, nullptr);

    // per-head LayerNorm -> head-major fp16 (K single, V hi/lo)
    ln_kernel<<<dim3(NM, 2), 256>>>(kp, vp, gK, betaK, gV, betaV, k16, vh16, vl16);

    // p_attn = Kc^T Vc / S  (core + edges fused)
    cudaMemsetAsync(pa, 0, (size_t)32 * NE * NE * sizeof(float));
    pa_core_mma<<<dim3(32, 8), 256>>>(k16, vh16, vl16, pos, pa);

    // Gd = pa @ Wfc_h^T (head cols), gpos = SUM over heads of pos col
    cudaMemsetAsync(gpos, 0, 4096 * sizeof(float));
    g_kernel<<<dim3(8, NH, NB), 256, (129 + 128) * 132 * sizeof(float)>>>(
        pa, Wfc, Gd, gpos);

    // bias2 = bfc + bq @ Gd^T
    bias2_kernel<<<dim3(1024, 4), 256>>>(Gd, bq, bfc, bias2);

    // Split Gd (A of gemm3, into a16) and Wq^T (B of gemm3, into bh/bl)
    split16_kernel<<<NGD / 1024, 256>>>(Gd, a16, a16 + 4194304, NGD);
    tsplit16_kernel<<<dim3(32, 32), 256>>>(Wq, bh16, bl16);

    // Wcomb[b] = Gd[b] @ Wq (3-pass, near-fp32) -> vp
    gemm_mma3<<<dim3(8, 8, 4), 256, SMEM3_DYN>>>(tGh, tGl, tB4h, tB4l, vp, 16);

    // Split Wcomb into B hi/lo, convert query to fp16
    split16_kernel<<<NGD / 1024, 256>>>(vp, bh16, bl16, NGD);
    cvt16_kernel<<<NA / 2048, 256>>>(query, a16, NA);

    // out[b] = query[b] @ Wcomb[b]^T + pos (x) gpos[b] + bias2[b]
    gemm_mma<<<dim3(8, 64, 4), 256, SMEM_DYN>>>(tAct, tB4h, tB4l, bias2, out,
                                                16, 8192, 1, pos, gpos);
}

// round 7
// speedup vs baseline: 5.4708x; 1.0366x over previous
#include <cuda_runtime.h>
#include <cuda.h>
#include <cuda_fp16.h>
#include <cstdint>
#include <cstddef>

// Problem constants
#define NB 4
#define NS 8192
#define ND 1024
#define NH 8
#define NDK 128
#define NE 129
#define NM 32768
#define KFC 1032

// ---------------- scratch (static device globals; no allocations) ----------
static __device__ float g_wc[4194304];      // (B, 1024, 1024) Wcomb
static __device__ float g_pa[532512];       // (32, 129, 129) p_attn
static __device__ float g_G [4194304];      // (B, 1024, 1024) Gd (head cols only)
static __device__ float g_gpos[4096];       // (B, 1024) pos-column of G (sum over h)
static __device__ float g_bias2[4096];      // (B, 1024) folded bias
static __device__ __half g_a16[33554432];   // key fp16 / Gd hi+lo / query fp16
static __device__ __half g_c16[33554432];   // value fp16
static __device__ __half g_bh16[4227072];   // B operand hi (Wk+Wv / Wq / Wcomb)
static __device__ __half g_bl16[4227072];   // B operand lo
static __device__ __half g_k16[33554432];   // LN'd K, head-major (bh,s,d) fp16
static __device__ __half g_vh16[33554432];  // LN'd V hi, head-major
static __device__ __half g_vl16[33554432];  // LN'd V lo, head-major

// ============================ PTX helpers ==================================
__device__ __forceinline__ uint32_t smem_u32(const void* p) {
    uint32_t a;
    asm("{ .reg .u64 t; cvta.to.shared.u64 t, %1; cvt.u32.u64 %0, t; }"
        : "=r"(a) : "l"(p));
    return a;
}
__device__ __forceinline__ void mbar_init(uint32_t mbar, uint32_t cnt) {
    asm volatile("mbarrier.init.shared.b64 [%0], %1;" :: "r"(mbar), "r"(cnt) : "memory");
}
__device__ __forceinline__ void mbar_expect_tx(uint32_t mbar, uint32_t bytes) {
    asm volatile("mbarrier.arrive.expect_tx.shared.b64 _, [%0], %1;"
                 :: "r"(mbar), "r"(bytes) : "memory");
}
__device__ __forceinline__ void mbar_arrive(uint32_t mbar) {
    asm volatile("mbarrier.arrive.shared.b64 _, [%0];" :: "r"(mbar) : "memory");
}
__device__ __forceinline__ void mbar_wait(uint32_t mbar, uint32_t parity) {
    asm volatile(
        "{\n\t.reg .pred P;\n\t"
        "BWL_%=:\n\t"
        "mbarrier.try_wait.parity.acquire.cta.shared::cta.b64 P, [%0], %1, 0x989680;\n\t"
        "@P bra.uni BWD_%=;\n\t"
        "bra.uni BWL_%=;\n\t"
        "BWD_%=:\n\t}"
        :: "r"(mbar), "r"(parity) : "memory");
}
__device__ __forceinline__ void tma_load_3d(uint32_t dst, const CUtensorMap* tm,
                                            int x, int y, int z, uint32_t mbar) {
    asm volatile(
        "cp.async.bulk.tensor.3d.shared::cta.global.tile.mbarrier::complete_tx::bytes "
        "[%0], [%1, {%2, %3, %4}], [%5];"
        :: "r"(dst), "l"(tm), "r"(x), "r"(y), "r"(z), "r"(mbar) : "memory");
}
__device__ __forceinline__ void fence_async_shared() {
    asm volatile("fence.proxy.async.shared::cta;" ::: "memory");
}
__device__ __forceinline__ void ldsm4(uint32_t* r, uint32_t addr) {
    asm volatile("ldmatrix.sync.aligned.m8n8.x4.shared.b16 {%0,%1,%2,%3}, [%4];"
                 : "=r"(r[0]), "=r"(r[1]), "=r"(r[2]), "=r"(r[3]) : "r"(addr));
}
__device__ __forceinline__ void ldsm4t(uint32_t* r, uint32_t addr) {
    asm volatile("ldmatrix.sync.aligned.m8n8.x4.trans.shared.b16 {%0,%1,%2,%3}, [%4];"
                 : "=r"(r[0]), "=r"(r[1]), "=r"(r[2]), "=r"(r[3]) : "r"(addr));
}
__device__ __forceinline__ void mma_f16(float* c, const uint32_t* a, const uint32_t* b) {
    asm volatile(
        "mma.sync.aligned.m16n8k16.row.col.f32.f16.f16.f32 "
        "{%0,%1,%2,%3}, {%4,%5,%6,%7}, {%8,%9}, {%0,%1,%2,%3};"
        : "+f"(c[0]), "+f"(c[1]), "+f"(c[2]), "+f"(c[3])
        : "r"(a[0]), "r"(a[1]), "r"(a[2]), "r"(a[3]), "r"(b[0]), "r"(b[1]));
}
__device__ __forceinline__ uint32_t swz(uint32_t base, int r, int c) {
    return base + r * 128 + (c ^ ((r & 7) << 4));
}

// ============================ shared GEMM constants ========================
static constexpr int ST = 4;
static constexpr uint32_t OP_BYTES = 128 * 64 * 2;      // 16 KB per operand tile
static constexpr uint32_t STG_BYTES = 3 * OP_BYTES;     // 48 KB per stage
static constexpr uint32_t CTRL_BYTES = 1024;
static constexpr uint32_t SMEM_DYN = CTRL_BYTES + ST * STG_BYTES;  // 197632

// ============================ K/V projection + fused LN ====================
// grid (8 heads, 256 m-tiles, 2 kv), 288 threads (8 compute warps + producer).
// z=0: K -> k16 (single fp16). z=1: V -> vh16/vl16.
__global__ __launch_bounds__(288, 1) void gemm_kv(
    const __grid_constant__ CUtensorMap tmAK,
    const __grid_constant__ CUtensorMap tmAV,
    const __grid_constant__ CUtensorMap tmB,    // batched hi (z: 0=Wk, 1=Wv)
    const __grid_constant__ CUtensorMap tmBlo,  // batched lo
    const float* __restrict__ bk, const float* __restrict__ bv,
    const float* __restrict__ gK, const float* __restrict__ betaK,
    const float* __restrict__ gV, const float* __restrict__ betaV,
    __half* __restrict__ k16, __half* __restrict__ vh16, __half* __restrict__ vl16)
{
    extern __shared__ __align__(1024) char smem[];
    const uint32_t sb = smem_u32(smem);
    const int tid = threadIdx.x;
    const int wid = tid >> 5, lane = tid & 31;
    const int warp_row = wid >> 2;
    const int warp_col = wid & 3;
    const bool producer = (wid == 8);

    const uint32_t full0  = sb;
    const uint32_t empty0 = sb + 64;
    const uint32_t tiles  = sb + CTRL_BYTES;

    const int h  = blockIdx.x;
    const int n0 = h * 128;
    const int m0 = blockIdx.y * 128;
    const int zKV = blockIdx.z;
    const CUtensorMap* tmA = zKV ? &tmAV : &tmAK;
    const int KB = 16;

    if (tid == 0) {
        for (int s = 0; s < ST; s++) {
            mbar_init(full0 + s * 8, 1);
            mbar_init(empty0 + s * 8, 256);
        }
        fence_async_shared();
    }
    __syncthreads();

    float acc[4][4][4];
#pragma unroll
    for (int mi = 0; mi < 4; mi++)
#pragma unroll
        for (int ni = 0; ni < 4; ni++)
#pragma unroll
            for (int q = 0; q < 4; q++) acc[mi][ni][q] = 0.f;

    if (producer) {
        if (tid == 288 - 32) {
            for (int s = 0; s < ST; s++) {
                uint32_t fb = full0 + s * 8;
                mbar_expect_tx(fb, STG_BYTES);
                uint32_t a0 = tiles + s * STG_BYTES;
                tma_load_3d(a0,                tmA,    s * 64, m0, 0,   fb);
                tma_load_3d(a0 + OP_BYTES,     &tmB,   s * 64, n0, zKV, fb);
                tma_load_3d(a0 + 2 * OP_BYTES, &tmBlo, s * 64, n0, zKV, fb);
            }
            for (int kb = ST; kb < KB; kb++) {
                int s = kb % ST;
                mbar_wait(empty0 + s * 8, (uint32_t)(((kb - ST) / ST) & 1));
                uint32_t fb = full0 + s * 8;
                mbar_expect_tx(fb, STG_BYTES);
                uint32_t a0 = tiles + s * STG_BYTES;
                tma_load_3d(a0,                tmA,    kb * 64, m0, 0,   fb);
                tma_load_3d(a0 + OP_BYTES,     &tmB,   kb * 64, n0, zKV, fb);
                tma_load_3d(a0 + 2 * OP_BYTES, &tmBlo, kb * 64, n0, zKV, fb);
            }
        }
    } else {
        const int aR = lane & 15;
        const int aC = (lane >> 4) << 4;
        const int bR = ((lane >> 4) << 3) + (lane & 7);
        const int bC = ((lane >> 3) & 1) << 4;

        for (int kb = 0; kb < KB; kb++) {
            const int s = kb % ST;
            mbar_wait(full0 + s * 8, (uint32_t)((kb / ST) & 1));

            const uint32_t A0 = tiles + s * STG_BYTES;
            const uint32_t B0 = A0 + OP_BYTES;

#pragma unroll
            for (int ki = 0; ki < 4; ki++) {
                const int kc = ki * 32;
                uint32_t af[4][4], bhi[4][2], blo[4][2];
#pragma unroll
                for (int mi = 0; mi < 4; mi++) {
                    int r = warp_row * 64 + mi * 16 + aR;
                    ldsm4(af[mi], swz(A0, r, kc + aC));
                }
#pragma unroll
                for (int g = 0; g < 2; g++) {
                    int r = warp_col * 32 + g * 16 + bR;
                    uint32_t bd = swz(B0, r, kc + bC);
                    uint32_t t[4];
                    ldsm4(t, bd);
                    bhi[2 * g][0] = t[0]; bhi[2 * g][1] = t[1];
                    bhi[2 * g + 1][0] = t[2]; bhi[2 * g + 1][1] = t[3];
                    ldsm4(t, bd + OP_BYTES);
                    blo[2 * g][0] = t[0]; blo[2 * g][1] = t[1];
                    blo[2 * g + 1][0] = t[2]; blo[2 * g + 1][1] = t[3];
                }
                if (ki == 3) mbar_arrive(empty0 + s * 8);   // smem fully read
#pragma unroll
                for (int mi = 0; mi < 4; mi++)
#pragma unroll
                    for (int ni = 0; ni < 4; ni++) {
                        mma_f16(acc[mi][ni], af[mi], bhi[ni]);
                        mma_f16(acc[mi][ni], af[mi], blo[ni]);
                    }
            }
        }
    }

    // ---- fused LN epilogue ----
    __syncthreads();   // all stage reads done; safe to reuse tile smem

    float2* part  = (float2*)(smem + CTRL_BYTES);            // [128][16]
    float2* stats = (float2*)(smem + CTRL_BYTES + 16384);    // [128]

    const float* biasp = zKV ? bv : bk;
    const float* gsel  = zKV ? gV : gK;
    const float* besel = zKV ? betaV : betaK;

    if (!producer) {
        // add bias, emit per-row partial sums
        const int slot = warp_col * 4 + (lane & 3);
#pragma unroll
        for (int mi = 0; mi < 4; mi++) {
#pragma unroll
            for (int ni = 0; ni < 4; ni++) {
                int col = warp_col * 32 + ni * 8 + (lane & 3) * 2;
                float b0v = biasp[n0 + col], b1v = biasp[n0 + col + 1];
                acc[mi][ni][0] += b0v; acc[mi][ni][1] += b1v;
                acc[mi][ni][2] += b0v; acc[mi][ni][3] += b1v;
            }
#pragma unroll
            for (int half = 0; half < 2; half++) {
                float s = 0.f, sq = 0.f;
#pragma unroll
                for (int ni = 0; ni < 4; ni++) {
                    float v0 = acc[mi][ni][half * 2 + 0];
                    float v1 = acc[mi][ni][half * 2 + 1];
                    s += v0 + v1;
                    sq += v0 * v0 + v1 * v1;
                }
                int r = warp_row * 64 + mi * 16 + (lane >> 2) + half * 8;
                part[r * 16 + slot] = make_float2(s, sq);
            }
        }
    }
    __syncthreads();
    if (tid < 128) {
        float s = 0.f, sq = 0.f;
#pragma unroll
        for (int i = 0; i < 16; i++) {
            float2 p = part[tid * 16 + i];
            s += p.x; sq += p.y;
        }
        float mean = s * (1.f / 128.f);
        float var  = sq * (1.f / 128.f) - mean * mean;
        stats[tid] = make_float2(mean, rsqrtf(var + 1e-5f));
    }
    __syncthreads();

    if (!producer) {
#pragma unroll
        for (int mi = 0; mi < 4; mi++) {
#pragma unroll
            for (int half = 0; half < 2; half++) {
                int r = warp_row * 64 + mi * 16 + (lane >> 2) + half * 8;
                float2 st = stats[r];
                int m = m0 + r;
                int b = m >> 13, sIdx = m & 8191;
                size_t base = (((size_t)(b * NH + h)) * NS + sIdx) * NDK;
#pragma unroll
                for (int ni = 0; ni < 4; ni++) {
                    int col = warp_col * 32 + ni * 8 + (lane & 3) * 2;
                    float gg0 = gsel[n0 + col],  gg1 = gsel[n0 + col + 1];
                    float be0 = besel[n0 + col], be1 = besel[n0 + col + 1];
                    float y0 = (acc[mi][ni][half * 2 + 0] - st.x) * st.y * gg0 + be0;
                    float y1 = (acc[mi][ni][half * 2 + 1] - st.x) * st.y * gg1 + be1;
                    __half h0 = __float2half_rn(y0);
                    __half h1 = __float2half_rn(y1);
                    if (!zKV) {
                        *(__half2*)(k16 + base + col) = __half2(h0, h1);
                    } else {
                        *(__half2*)(vh16 + base + col) = __half2(h0, h1);
                        __half l0 = __float2half_rn(y0 - __half2float(h0));
                        __half l1 = __float2half_rn(y1 - __half2float(h1));
                        *(__half2*)(vl16 + base + col) = __half2(l0, l1);
                    }
                }
            }
        }
    }
}

// ============================ final GEMM (fp16 2-pass) =====================
// out[b] = query[b] @ Wcomb[b]^T + pos (x) gpos[b] + bias2[b]
// grid (8, 64, 4), 288 threads (producer warp).
__global__ __launch_bounds__(288, 1) void gemm_out(
    const __grid_constant__ CUtensorMap tmA,
    const __grid_constant__ CUtensorMap tmBhi,
    const __grid_constant__ CUtensorMap tmBlo,
    const float* __restrict__ bias2,
    const float* __restrict__ posv,
    const float* __restrict__ gposv,
    float* __restrict__ C)
{
    extern __shared__ __align__(1024) char smem[];
    const uint32_t sb = smem_u32(smem);
    const int tid = threadIdx.x;
    const int wid = tid >> 5, lane = tid & 31;
    const int warp_row = wid >> 2;
    const int warp_col = wid & 3;
    const bool producer = (wid == 8);

    const uint32_t full0  = sb;
    const uint32_t empty0 = sb + 64;
    const uint32_t tiles  = sb + CTRL_BYTES;

    const int n0 = blockIdx.x * 128;
    const int zB = blockIdx.z;
    const int m0 = zB * 8192 + blockIdx.y * 128;
    const int KB = 16;

    if (tid == 0) {
        for (int s = 0; s < ST; s++) {
            mbar_init(full0 + s * 8, 1);
            mbar_init(empty0 + s * 8, 256);
        }
        fence_async_shared();
    }
    __syncthreads();

    float acc[4][4][4];
#pragma unroll
    for (int mi = 0; mi < 4; mi++)
#pragma unroll
        for (int ni = 0; ni < 4; ni++)
#pragma unroll
            for (int q = 0; q < 4; q++) acc[mi][ni][q] = 0.f;

    if (producer) {
        if (tid == 288 - 32) {
            for (int s = 0; s < ST; s++) {
                uint32_t fb = full0 + s * 8;
                mbar_expect_tx(fb, STG_BYTES);
                uint32_t a0 = tiles + s * STG_BYTES;
                tma_load_3d(a0,                &tmA,   s * 64, m0, 0,  fb);
                tma_load_3d(a0 + OP_BYTES,     &tmBhi, s * 64, n0, zB, fb);
                tma_load_3d(a0 + 2 * OP_BYTES, &tmBlo, s * 64, n0, zB, fb);
            }
            for (int kb = ST; kb < KB; kb++) {
                int s = kb % ST;
                mbar_wait(empty0 + s * 8, (uint32_t)(((kb - ST) / ST) & 1));
                uint32_t fb = full0 + s * 8;
                mbar_expect_tx(fb, STG_BYTES);
                uint32_t a0 = tiles + s * STG_BYTES;
                tma_load_3d(a0,                &tmA,   kb * 64, m0, 0,  fb);
                tma_load_3d(a0 + OP_BYTES,     &tmBhi, kb * 64, n0, zB, fb);
                tma_load_3d(a0 + 2 * OP_BYTES, &tmBlo, kb * 64, n0, zB, fb);
            }
        }
        return;
    }

    const int aR = lane & 15;
    const int aC = (lane >> 4) << 4;
    const int bR = ((lane >> 4) << 3) + (lane & 7);
    const int bC = ((lane >> 3) & 1) << 4;

    for (int kb = 0; kb < KB; kb++) {
        const int s = kb % ST;
        mbar_wait(full0 + s * 8, (uint32_t)((kb / ST) & 1));

        const uint32_t A0 = tiles + s * STG_BYTES;
        const uint32_t B0 = A0 + OP_BYTES;

#pragma unroll
        for (int ki = 0; ki < 4; ki++) {
            const int kc = ki * 32;
            uint32_t af[4][4], bhi[4][2], blo[4][2];
#pragma unroll
            for (int mi = 0; mi < 4; mi++) {
                int r = warp_row * 64 + mi * 16 + aR;
                ldsm4(af[mi], swz(A0, r, kc + aC));
            }
#pragma unroll
            for (int g = 0; g < 2; g++) {
                int r = warp_col * 32 + g * 16 + bR;
                uint32_t bd = swz(B0, r, kc + bC);
                uint32_t t[4];
                ldsm4(t, bd);
                bhi[2 * g][0] = t[0]; bhi[2 * g][1] = t[1];
                bhi[2 * g + 1][0] = t[2]; bhi[2 * g + 1][1] = t[3];
                ldsm4(t, bd + OP_BYTES);
                blo[2 * g][0] = t[0]; blo[2 * g][1] = t[1];
                blo[2 * g + 1][0] = t[2]; blo[2 * g + 1][1] = t[3];
            }
            if (ki == 3) mbar_arrive(empty0 + s * 8);
#pragma unroll
            for (int mi = 0; mi < 4; mi++)
#pragma unroll
                for (int ni = 0; ni < 4; ni++) {
                    mma_f16(acc[mi][ni], af[mi], bhi[ni]);
                    mma_f16(acc[mi][ni], af[mi], blo[ni]);
                }
        }
    }

    const float* biasp = bias2 + zB * 1024;
    const float* gpp   = gposv + zB * 1024;

#pragma unroll
    for (int mi = 0; mi < 4; mi++) {
        int r = m0 + warp_row * 64 + mi * 16 + (lane >> 2);
        float pv = posv[r];
        float pv2 = posv[r + 8];
#pragma unroll
        for (int ni = 0; ni < 4; ni++) {
            int cc = n0 + warp_col * 32 + ni * 8 + (lane & 3) * 2;
            float b0v = biasp[cc], b1v = biasp[cc + 1];
            float g0 = gpp[cc], g1 = gpp[cc + 1];
            float2 v0 = { acc[mi][ni][0] + b0v + pv * g0,
                          acc[mi][ni][1] + b1v + pv * g1 };
            float2 v1 = { acc[mi][ni][2] + b0v + pv2 * g0,
                          acc[mi][ni][3] + b1v + pv2 * g1 };
            *(float2*)(C + (size_t)r * 1024 + cc) = v0;
            *(float2*)(C + (size_t)(r + 8) * 1024 + cc) = v1;
        }
    }
}

// ============================ 3-pass GEMM (A hi/lo, B hi/lo) ===============
static constexpr int ST3 = 3;
static constexpr uint32_t STG3_BYTES = 4 * OP_BYTES;
static constexpr uint32_t SMEM3_DYN = CTRL_BYTES + ST3 * STG3_BYTES;

__global__ __launch_bounds__(256, 1) void gemm_mma3(
    const __grid_constant__ CUtensorMap tmAhi,
    const __grid_constant__ CUtensorMap tmAlo,
    const __grid_constant__ CUtensorMap tmBhi,
    const __grid_constant__ CUtensorMap tmBlo,
    float* __restrict__ C, int KB)
{
    extern __shared__ __align__(1024) char smem[];
    const uint32_t sb = smem_u32(smem);
    const int tid = threadIdx.x;
    const int wid = tid >> 5, lane = tid & 31;
    const int warp_row = wid >> 2;
    const int warp_col = wid & 3;

    const uint32_t full0  = sb;
    const uint32_t empty0 = sb + 64;
    const uint32_t tiles  = sb + CTRL_BYTES;

    const int n0 = blockIdx.x * 128;
    const int aY = blockIdx.y * 128;
    const int aZ = blockIdx.z;
    const int m0 = blockIdx.z * 1024 + aY;

    if (tid == 0) {
        for (int s = 0; s < ST3; s++) {
            mbar_init(full0 + s * 8, 1);
            mbar_init(empty0 + s * 8, 256);
        }
        fence_async_shared();
    }
    __syncthreads();

    if (tid == 0) {
        for (int s = 0; s < ST3; s++) {
            uint32_t fb = full0 + s * 8;
            mbar_expect_tx(fb, STG3_BYTES);
            uint32_t a0 = tiles + s * STG3_BYTES;
            tma_load_3d(a0,                &tmAhi, s * 64, aY, aZ, fb);
            tma_load_3d(a0 + OP_BYTES,     &tmAlo, s * 64, aY, aZ, fb);
            tma_load_3d(a0 + 2 * OP_BYTES, &tmBhi, s * 64, n0, 0,  fb);
            tma_load_3d(a0 + 3 * OP_BYTES, &tmBlo, s * 64, n0, 0,  fb);
        }
    }

    float acc[4][4][4];
#pragma unroll
    for (int mi = 0; mi < 4; mi++)
#pragma unroll
        for (int ni = 0; ni < 4; ni++)
#pragma unroll
            for (int q = 0; q < 4; q++) acc[mi][ni][q] = 0.f;

    const int aR = lane & 15;
    const int aC = (lane >> 4) << 4;
    const int bR = ((lane >> 4) << 3) + (lane & 7);
    const int bC = ((lane >> 3) & 1) << 4;

    for (int kb = 0; kb < KB; kb++) {
        const int s = kb % ST3;
        const uint32_t ph = (uint32_t)((kb / ST3) & 1);
        mbar_wait(full0 + s * 8, ph);

        const uint32_t A0 = tiles + s * STG3_BYTES;
        const uint32_t B0 = A0 + 2 * OP_BYTES;

#pragma unroll
        for (int ki = 0; ki < 4; ki++) {
            const int kc = ki * 32;
            uint32_t ahi[4][4], alo[4][4], bhi[4][2], blo[4][2];
#pragma unroll
            for (int mi = 0; mi < 4; mi++) {
                int r = warp_row * 64 + mi * 16 + aR;
                uint32_t ad = swz(A0, r, kc + aC);
                ldsm4(ahi[mi], ad);
                ldsm4(alo[mi], ad + OP_BYTES);
            }
#pragma unroll
            for (int g = 0; g < 2; g++) {
                int r = warp_col * 32 + g * 16 + bR;
                uint32_t bd = swz(B0, r, kc + bC);
                uint32_t t[4];
                ldsm4(t, bd);
                bhi[2 * g][0] = t[0]; bhi[2 * g][1] = t[1];
                bhi[2 * g + 1][0] = t[2]; bhi[2 * g + 1][1] = t[3];
                ldsm4(t, bd + OP_BYTES);
                blo[2 * g][0] = t[0]; blo[2 * g][1] = t[1];
                blo[2 * g + 1][0] = t[2]; blo[2 * g + 1][1] = t[3];
            }
#pragma unroll
            for (int mi = 0; mi < 4; mi++)
#pragma unroll
                for (int ni = 0; ni < 4; ni++) {
                    mma_f16(acc[mi][ni], ahi[mi], bhi[ni]);
                    mma_f16(acc[mi][ni], ahi[mi], blo[ni]);
                    mma_f16(acc[mi][ni], alo[mi], bhi[ni]);
                }
        }

        mbar_arrive(empty0 + s * 8);

        if (tid == 0 && kb + ST3 < KB) {
            mbar_wait(empty0 + s * 8, ph);
            uint32_t fb = full0 + s * 8;
            mbar_expect_tx(fb, STG3_BYTES);
            uint32_t a0 = tiles + s * STG3_BYTES;
            int kx = (kb + ST3) * 64;
            tma_load_3d(a0,                &tmAhi, kx, aY, aZ, fb);
            tma_load_3d(a0 + OP_BYTES,     &tmAlo, kx, aY, aZ, fb);
            tma_load_3d(a0 + 2 * OP_BYTES, &tmBhi, kx, n0, 0,  fb);
            tma_load_3d(a0 + 3 * OP_BYTES, &tmBlo, kx, n0, 0,  fb);
        }
    }

#pragma unroll
    for (int mi = 0; mi < 4; mi++) {
        int r = m0 + warp_row * 64 + mi * 16 + (lane >> 2);
#pragma unroll
        for (int ni = 0; ni < 4; ni++) {
            int cc = n0 + warp_col * 32 + ni * 8 + (lane & 3) * 2;
            float2 v0 = { acc[mi][ni][0], acc[mi][ni][1] };
            float2 v1 = { acc[mi][ni][2], acc[mi][ni][3] };
            *(float2*)(C + (size_t)r * 1024 + cc) = v0;
            *(float2*)(C + (size_t)(r + 8) * 1024 + cc) = v1;
        }
    }
}

// ---------------------------------------------------------------------------
__global__ __launch_bounds__(256) void cvt16_kernel(
    const float* __restrict__ src, __half* __restrict__ dst, int n)
{
    int i = (blockIdx.x * 256 + threadIdx.x) * 8;
    if (i >= n) return;
    float4 v0 = *(const float4*)(src + i);
    float4 v1 = *(const float4*)(src + i + 4);
    __half2 h[4];
    h[0] = __floats2half2_rn(v0.x, v0.y);
    h[1] = __floats2half2_rn(v0.z, v0.w);
    h[2] = __floats2half2_rn(v1.x, v1.y);
    h[3] = __floats2half2_rn(v1.z, v1.w);
    *(uint4*)(dst + i) = *(uint4*)h;
}

__global__ __launch_bounds__(256) void split16_kernel(
    const float* __restrict__ src, __half* __restrict__ hi,
    __half* __restrict__ lo, int n)
{
    int i = (blockIdx.x * 256 + threadIdx.x) * 4;
    if (i >= n) return;
    float4 v = *(const float4*)(src + i);
    __half h0 = __float2half_rn(v.x);
    __half h1 = __float2half_rn(v.y);
    __half h2 = __float2half_rn(v.z);
    __half h3 = __float2half_rn(v.w);
    __half l0 = __float2half_rn(v.x - __half2float(h0));
    __half l1 = __float2half_rn(v.y - __half2float(h1));
    __half l2 = __float2half_rn(v.z - __half2float(h2));
    __half l3 = __float2half_rn(v.w - __half2float(h3));
    __half2 hp[2] = { __half2(h0, h1), __half2(h2, h3) };
    __half2 lp[2] = { __half2(l0, l1), __half2(l2, l3) };
    *(uint2*)(hi + i) = *(uint2*)hp;
    *(uint2*)(lo + i) = *(uint2*)lp;
}

__global__ __launch_bounds__(256) void tsplit16_kernel(
    const float* __restrict__ W, __half* __restrict__ hi, __half* __restrict__ lo)
{
    __shared__ float t[32][33];
    const int o0 = blockIdx.y * 32, i0 = blockIdx.x * 32;
    const int c = threadIdx.x & 31;
    const int r0 = threadIdx.x >> 5;
#pragma unroll
    for (int it = 0; it < 4; it++) {
        int r = r0 + it * 8;
        t[r][c] = W[(size_t)(o0 + r) * 1024 + i0 + c];
    }
    __syncthreads();
#pragma unroll
    for (int it = 0; it < 4; it++) {
        int r = r0 + it * 8;
        float v = t[c][r];
        __half h = __float2half_rn(v);
        size_t idx = (size_t)(i0 + r) * 1024 + o0 + c;
        hi[idx] = h;
        lo[idx] = __float2half_rn(v - __half2float(h));
    }
}

// ---------------------------------------------------------------------------
// p_attn core + edges fused. grid (32 bh, 8 s-split), block 256.
// ---------------------------------------------------------------------------
__global__ __launch_bounds__(256) void pa_core_mma(
    const __half* __restrict__ k16, const __half* __restrict__ vh16,
    const __half* __restrict__ vl16, const float* __restrict__ pos,
    float* __restrict__ pa)
{
    __shared__ __half Ks[32 * 136];
    __shared__ __half Vh[32 * 136];
    __shared__ __half Vl[32 * 136];
    __shared__ float ps[32];

    const int bh = blockIdx.x;
    const int b = bh >> 3;
    const int sp = blockIdx.y;
    const int tid = threadIdx.x;
    const int wid = tid >> 5, lane = tid & 31;
    const int warp_row = wid >> 2;
    const int warp_col = wid & 3;

    const uint32_t ksb = smem_u32(Ks);
    const uint32_t vhb = smem_u32(Vh);
    const uint32_t vlb = smem_u32(Vl);

    const size_t gbase = ((size_t)bh * NS + sp * 1024) * NDK;
    const float* posb = pos + (size_t)b * NS + sp * 1024;

    float acc[4][4][4];
#pragma unroll
    for (int mi = 0; mi < 4; mi++)
#pragma unroll
        for (int ni = 0; ni < 4; ni++)
#pragma unroll
            for (int q = 0; q < 4; q++) acc[mi][ni][q] = 0.f;

    float eacc = 0.f;
    float p2 = 0.f;

    const int aRow = (lane & 7) | ((lane >> 4) << 3);
    const int aCol = ((lane >> 3) & 1) << 3;
    const int bRow = (lane & 7) | (((lane >> 3) & 1) << 3);
    const int bCol = ((lane >> 4) & 1) << 3;
    const int ecol = tid & 127;

    for (int s0 = 0; s0 < 1024; s0 += 32) {
#pragma unroll
        for (int it = 0; it < 2; it++) {
            int f = tid + it * 256;
            int row = f >> 4;
            int c8 = (f & 15) * 8;
            size_t ga = gbase + (size_t)(s0 + row) * NDK + c8;
            int so = row * 136 + c8;
            *(float4*)(Ks + so) = *(const float4*)(k16 + ga);
            *(float4*)(Vh + so) = *(const float4*)(vh16 + ga);
            *(float4*)(Vl + so) = *(const float4*)(vl16 + ga);
        }
        if (tid < 32) ps[tid] = posb[s0 + tid];
        __syncthreads();

#pragma unroll
        for (int ki = 0; ki < 2; ki++) {
            const int kio = ki * 16;
            uint32_t af[4][4], bhi[4][2], blo[4][2];
#pragma unroll
            for (int mi = 0; mi < 4; mi++) {
                int mcol = warp_row * 64 + mi * 16 + aCol;
                ldsm4t(af[mi], ksb + (kio + aRow) * 272 + mcol * 2);
            }
#pragma unroll
            for (int g = 0; g < 2; g++) {
                int ec = warp_col * 32 + g * 16 + bCol;
                uint32_t off = (kio + bRow) * 272 + ec * 2;
                uint32_t t[4];
                ldsm4t(t, vhb + off);
                bhi[2 * g][0] = t[0]; bhi[2 * g][1] = t[1];
                bhi[2 * g + 1][0] = t[2]; bhi[2 * g + 1][1] = t[3];
                ldsm4t(t, vlb + off);
                blo[2 * g][0] = t[0]; blo[2 * g][1] = t[1];
                blo[2 * g + 1][0] = t[2]; blo[2 * g + 1][1] = t[3];
            }
#pragma unroll
            for (int mi = 0; mi < 4; mi++)
#pragma unroll
                for (int ni = 0; ni < 4; ni++) {
                    mma_f16(acc[mi][ni], af[mi], bhi[ni]);
                    mma_f16(acc[mi][ni], af[mi], blo[ni]);
                }
        }

        if (tid < 128) {
#pragma unroll 8
            for (int r = 0; r < 32; r++) {
                float v = __half2float(Vh[r * 136 + ecol]) +
                          __half2float(Vl[r * 136 + ecol]);
                eacc = fmaf(ps[r], v, eacc);
            }
        } else {
#pragma unroll 8
            for (int r = 0; r < 32; r++)
                eacc = fmaf(ps[r], __half2float(Ks[r * 136 + ecol]), eacc);
        }
        if (wid == 0) { float pv = ps[lane]; p2 = fmaf(pv, pv, p2); }
        __syncthreads();
    }

    const float invS = 1.0f / (float)NS;
    float* pab = pa + (size_t)bh * NE * NE;
#pragma unroll
    for (int mi = 0; mi < 4; mi++) {
        int d0 = warp_row * 64 + mi * 16 + (lane >> 2);
#pragma unroll
        for (int ni = 0; ni < 4; ni++) {
            int e0 = warp_col * 32 + ni * 8 + (lane & 3) * 2;
            atomicAdd(&pab[(1 + d0) * NE + 1 + e0],     acc[mi][ni][0] * invS);
            atomicAdd(&pab[(1 + d0) * NE + 2 + e0],     acc[mi][ni][1] * invS);
            atomicAdd(&pab[(1 + d0 + 8) * NE + 1 + e0], acc[mi][ni][2] * invS);
            atomicAdd(&pab[(1 + d0 + 8) * NE + 2 + e0], acc[mi][ni][3] * invS);
        }
    }
    if (tid < 128) atomicAdd(&pab[0 * NE + 1 + ecol], eacc * invS);
    else           atomicAdd(&pab[(1 + ecol) * NE + 0], eacc * invS);
    if (wid == 0) {
#pragma unroll
        for (int o = 16; o > 0; o >>= 1)
            p2 += __shfl_xor_sync(0xffffffffu, p2, o);
        if (lane == 0) atomicAdd(&pab[0], p2 * invS);
    }
}

// ---------------------------------------------------------------------------
__global__ __launch_bounds__(256) void g_kernel(
    const float* __restrict__ pa, const float* __restrict__ Wfc,
    float* __restrict__ Gd, float* __restrict__ gpos)
{
    extern __shared__ float sm[];
    float* pas = sm;
    float* ws  = sm + 129 * 132;

    const int nt = blockIdx.x, h = blockIdx.y, b = blockIdx.z;
    const int tid = threadIdx.x;
    const int n0 = nt * 128;

    const float* pab = pa + ((size_t)(b * NH + h)) * NE * NE;
    for (int i = tid; i < NE * NE; i += 256) {
        int d = i / NE, e = i - d * NE;
        pas[d * 132 + e] = pab[i];
    }
    for (int i = tid; i < 128 * NE; i += 256) {
        int n = i / NE, e = i - n * NE;
        ws[n * 132 + e] = Wfc[(size_t)(n0 + n) * KFC + h * NE + e];
    }
    __syncthreads();

    for (int o = tid; o < 128 * NE; o += 256) {
        int n = o / NE, d = o - n * NE;
        const float* pr = &pas[d * 132];
        const float* wr = &ws[n * 132];
        float acc = 0.f;
#pragma unroll 8
        for (int e4 = 0; e4 < 128; e4 += 4) {
            float4 a = *(const float4*)(pr + e4);
            float4 w = *(const float4*)(wr + e4);
            acc = fmaf(a.x, w.x, acc);
            acc = fmaf(a.y, w.y, acc);
            acc = fmaf(a.z, w.z, acc);
            acc = fmaf(a.w, w.w, acc);
        }
        acc = fmaf(pr[128], wr[128], acc);
        if (d == 0)
            atomicAdd(&gpos[b * 1024 + n0 + n], acc);
        else
            Gd[((size_t)b * 1024 + n0 + n) * 1024 + h * NDK + d - 1] = acc;
    }
}

// ---------------------------------------------------------------------------
__global__ __launch_bounds__(256) void bias2_kernel(
    const float* __restrict__ Gd, const float* __restrict__ bq,
    const float* __restrict__ bfc, float* __restrict__ bias2)
{
    const int n = blockIdx.x, b = blockIdx.y;
    const int tid = threadIdx.x;
    const float* row = Gd + ((size_t)b * 1024 + n) * 1024;
    float acc = 0.f;
    for (int o = tid; o < 1024; o += 256) acc = fmaf(bq[o], row[o], acc);
    __shared__ float red[256];
    red[tid] = acc;
    __syncthreads();
    for (int o = 128; o > 0; o >>= 1) {
        if (tid < o) red[tid] += red[tid + o];
        __syncthreads();
    }
    if (tid == 0) bias2[b * 1024 + n] = red[0] + bfc[n];
}

// ============================ host side ====================================
typedef CUresult (*EncodeFn)(CUtensorMap*, CUtensorMapDataType, cuuint32_t, void*,
                             const cuuint64_t*, const cuuint64_t*, const cuuint32_t*,
                             const cuuint32_t*, CUtensorMapInterleave, CUtensorMapSwizzle,
                             CUtensorMapL2promotion, CUtensorMapFloatOOBfill);

static EncodeFn get_encode() {
    static EncodeFn fn = nullptr;
    if (!fn) {
        void* p = nullptr;
        cudaDriverEntryPointQueryResult st;
        cudaGetDriverEntryPoint("cuTensorMapEncodeTiled", &p, cudaEnableDefault, &st);
        fn = (EncodeFn)p;
    }
    return fn;
}

static void encode_f16(CUtensorMap* m, const void* base,
                       uint64_t kdim, uint64_t rows, uint64_t nz) {
    cuuint64_t dims[3]    = { kdim, rows, nz };
    cuuint64_t strides[2] = { kdim * 2, rows * kdim * 2 };
    cuuint32_t box[3]     = { 64, 128, 1 };
    cuuint32_t est[3]     = { 1, 1, 1 };
    get_encode()(m, CU_TENSOR_MAP_DATA_TYPE_FLOAT16, 3, (void*)base,
                 dims, strides, box, est,
                 CU_TENSOR_MAP_INTERLEAVE_NONE, CU_TENSOR_MAP_SWIZZLE_128B,
                 CU_TENSOR_MAP_L2_PROMOTION_L2_128B, CU_TENSOR_MAP_FLOAT_OOB_FILL_NONE);
}

extern "C" void kernel_launch(void* const* d_in, const int* in_sizes, int n_in,
                              void* d_out, int out_size)
{
    (void)in_sizes; (void)n_in; (void)out_size;
    const float* query = (const float*)d_in[0];
    const float* key   = (const float*)d_in[1];
    const float* value = (const float*)d_in[2];
    const float* pos   = (const float*)d_in[3];
    const float* Wq    = (const float*)d_in[4];
    const float* bq    = (const float*)d_in[5];
    const float* Wk    = (const float*)d_in[6];
    const float* bk    = (const float*)d_in[7];
    const float* Wv    = (const float*)d_in[8];
    const float* bv    = (const float*)d_in[9];
    const float* gK    = (const float*)d_in[10];
    const float* betaK = (const float*)d_in[11];
    const float* gV    = (const float*)d_in[12];
    const float* betaV = (const float*)d_in[13];
    const float* Wfc   = (const float*)d_in[14];
    const float* bfc   = (const float*)d_in[15];
    float* out = (float*)d_out;

    float *wc, *pa, *Gd, *gpos, *bias2;
    __half *a16, *c16, *bh16, *bl16, *k16, *vh16, *vl16;
    cudaGetSymbolAddress((void**)&wc, g_wc);
    cudaGetSymbolAddress((void**)&pa, g_pa);
    cudaGetSymbolAddress((void**)&Gd, g_G);
    cudaGetSymbolAddress((void**)&gpos, g_gpos);
    cudaGetSymbolAddress((void**)&bias2, g_bias2);
    cudaGetSymbolAddress((void**)&a16, g_a16);
    cudaGetSymbolAddress((void**)&c16, g_c16);
    cudaGetSymbolAddress((void**)&bh16, g_bh16);
    cudaGetSymbolAddress((void**)&bl16, g_bl16);
    cudaGetSymbolAddress((void**)&k16, g_k16);
    cudaGetSymbolAddress((void**)&vh16, g_vh16);
    cudaGetSymbolAddress((void**)&vl16, g_vl16);

    cudaFuncSetAttribute(gemm_kv, cudaFuncAttributeMaxDynamicSharedMemorySize,
                         (int)SMEM_DYN);
    cudaFuncSetAttribute(gemm_out, cudaFuncAttributeMaxDynamicSharedMemorySize,
                         (int)SMEM_DYN);
    cudaFuncSetAttribute(gemm_mma3, cudaFuncAttributeMaxDynamicSharedMemorySize,
                         (int)SMEM3_DYN);
    cudaFuncSetAttribute(g_kernel, cudaFuncAttributeMaxDynamicSharedMemorySize,
                         (129 + 128) * 132 * (int)sizeof(float));

    CUtensorMap tAK, tAV, tBkv_h, tBkv_l, tGh, tGl, tWqh, tWql, tAq, tWch, tWcl;
    encode_f16(&tAK, a16, 1024, 32768, 1);
    encode_f16(&tAV, c16, 1024, 32768, 1);
    encode_f16(&tBkv_h, bh16, 1024, 1024, 2);   // z: 0=Wk, 1=Wv
    encode_f16(&tBkv_l, bl16, 1024, 1024, 2);
    encode_f16(&tGh,  a16,           1024, 1024, 4);
    encode_f16(&tGl,  a16 + 4194304, 1024, 1024, 4);
    encode_f16(&tWqh, bh16, 1024, 1024, 1);
    encode_f16(&tWql, bl16, 1024, 1024, 1);
    encode_f16(&tAq,  a16,  1024, 32768, 1);
    encode_f16(&tWch, bh16, 1024, 1024, 4);
    encode_f16(&tWcl, bl16, 1024, 1024, 4);

    const int NA = 33554432, NW = 1048576, NGD = 4194304;

    // Inputs to fp16
    cvt16_kernel<<<NA / 2048, 256>>>(key, a16, NA);
    cvt16_kernel<<<NA / 2048, 256>>>(value, c16, NA);
    split16_kernel<<<NW / 1024, 256>>>(Wk, bh16, bl16, NW);
    split16_kernel<<<NW / 1024, 256>>>(Wv, bh16 + NW, bl16 + NW, NW);

    // K+V projection with fused per-head LN -> k16 / vh16+vl16 (head-major)
    gemm_kv<<<dim3(8, 256, 2), 288, SMEM_DYN>>>(
        tAK, tAV, tBkv_h, tBkv_l, bk, bv, gK, betaK, gV, betaV, k16, vh16, vl16);

    // p_attn = Kc^T Vc / S  (core + edges fused)
    cudaMemsetAsync(pa, 0, (size_t)32 * NE * NE * sizeof(float));
    pa_core_mma<<<dim3(32, 8), 256>>>(k16, vh16, vl16, pos, pa);

    // Gd = pa @ Wfc_h^T (head cols), gpos = SUM over heads of pos col
    cudaMemsetAsync(gpos, 0, 4096 * sizeof(float));
    g_kernel<<<dim3(8, NH, NB), 256, (129 + 128) * 132 * sizeof(float)>>>(
        pa, Wfc, Gd, gpos);

    // bias2 = bfc + bq @ Gd^T
    bias2_kernel<<<dim3(1024, 4), 256>>>(Gd, bq, bfc, bias2);

    // Split Gd (A of gemm3) and Wq^T (B of gemm3)
    split16_kernel<<<NGD / 1024, 256>>>(Gd, a16, a16 + 4194304, NGD);
    tsplit16_kernel<<<dim3(32, 32), 256>>>(Wq, bh16, bl16);

    // Wcomb[b] = Gd[b] @ Wq (3-pass, near-fp32)
    gemm_mma3<<<dim3(8, 8, 4), 256, SMEM3_DYN>>>(tGh, tGl, tWqh, tWql, wc, 16);

    // Split Wcomb into B hi/lo, convert query to fp16 (reuses a16)
    split16_kernel<<<NGD / 1024, 256>>>(wc, bh16, bl16, NGD);
    cvt16_kernel<<<NA / 2048, 256>>>(query, a16, NA);

    // out[b] = query[b] @ Wcomb[b]^T + pos (x) gpos[b] + bias2[b]
    gemm_out<<<dim3(8, 64, 4), 288, SMEM_DYN>>>(tAq, tWch, tWcl, bias2, pos,
                                                gpos, out);
}

// round 8
// speedup vs baseline: 7.3866x; 1.3502x over previous
#include <cuda_runtime.h>
#include <cuda.h>
#include <cuda_fp16.h>
#include <cstdint>
#include <cstddef>

// Problem constants
#define NB 4
#define NS 8192
#define ND 1024
#define NH 8
#define NDK 128
#define NE 129
#define NM 32768
#define KFC 1032

// ---------------- scratch (static device globals; no allocations) ----------
static __device__ float g_wc[4194304];      // (B, 1024, 1024) Wcomb
static __device__ float g_pa[532512];       // (32, 129, 129) p_attn
static __device__ float g_G [4194304];      // (B, 1024, 1024) Gd (head cols only)
static __device__ float g_gpos[4096];       // (B, 1024) pos-column of G (sum over h)
static __device__ float g_bias2[4096];      // (B, 1024) folded bias
static __device__ __half g_a16[33554432];   // key fp16 / Gd hi+lo / query fp16
static __device__ __half g_c16[33554432];   // value fp16
static __device__ __half g_bh16[4227072];   // B hi (Wk+Wv / Wq / Wcomb)
static __device__ __half g_bl16[4227072];   // B lo (Wq lo for gemm3)
static __device__ __half g_k16[33554432];   // LN'd K, head-major (bh,s,d) fp16
static __device__ __half g_vh16[33554432];  // LN'd V hi, head-major
static __device__ __half g_vl16[33554432];  // LN'd V lo, head-major

// ============================ PTX helpers ==================================
__device__ __forceinline__ uint32_t smem_u32(const void* p) {
    uint32_t a;
    asm("{ .reg .u64 t; cvta.to.shared.u64 t, %1; cvt.u32.u64 %0, t; }"
        : "=r"(a) : "l"(p));
    return a;
}
__device__ __forceinline__ void mbar_init(uint32_t mbar, uint32_t cnt) {
    asm volatile("mbarrier.init.shared.b64 [%0], %1;" :: "r"(mbar), "r"(cnt) : "memory");
}
__device__ __forceinline__ void mbar_expect_tx(uint32_t mbar, uint32_t bytes) {
    asm volatile("mbarrier.arrive.expect_tx.shared.b64 _, [%0], %1;"
                 :: "r"(mbar), "r"(bytes) : "memory");
}
__device__ __forceinline__ void mbar_arrive(uint32_t mbar) {
    asm volatile("mbarrier.arrive.shared.b64 _, [%0];" :: "r"(mbar) : "memory");
}
__device__ __forceinline__ void mbar_wait(uint32_t mbar, uint32_t parity) {
    asm volatile(
        "{\n\t.reg .pred P;\n\t"
        "BWL_%=:\n\t"
        "mbarrier.try_wait.parity.acquire.cta.shared::cta.b64 P, [%0], %1, 0x989680;\n\t"
        "@P bra.uni BWD_%=;\n\t"
        "bra.uni BWL_%=;\n\t"
        "BWD_%=:\n\t}"
        :: "r"(mbar), "r"(parity) : "memory");
}
__device__ __forceinline__ void tma_load_3d(uint32_t dst, const CUtensorMap* tm,
                                            int x, int y, int z, uint32_t mbar) {
    asm volatile(
        "cp.async.bulk.tensor.3d.shared::cta.global.tile.mbarrier::complete_tx::bytes "
        "[%0], [%1, {%2, %3, %4}], [%5];"
        :: "r"(dst), "l"(tm), "r"(x), "r"(y), "r"(z), "r"(mbar) : "memory");
}
__device__ __forceinline__ void fence_async_shared() {
    asm volatile("fence.proxy.async.shared::cta;" ::: "memory");
}
__device__ __forceinline__ void ldsm4(uint32_t* r, uint32_t addr) {
    asm volatile("ldmatrix.sync.aligned.m8n8.x4.shared.b16 {%0,%1,%2,%3}, [%4];"
                 : "=r"(r[0]), "=r"(r[1]), "=r"(r[2]), "=r"(r[3]) : "r"(addr));
}
__device__ __forceinline__ void ldsm4t(uint32_t* r, uint32_t addr) {
    asm volatile("ldmatrix.sync.aligned.m8n8.x4.trans.shared.b16 {%0,%1,%2,%3}, [%4];"
                 : "=r"(r[0]), "=r"(r[1]), "=r"(r[2]), "=r"(r[3]) : "r"(addr));
}
__device__ __forceinline__ void mma_f16(float* c, const uint32_t* a, const uint32_t* b) {
    asm volatile(
        "mma.sync.aligned.m16n8k16.row.col.f32.f16.f16.f32 "
        "{%0,%1,%2,%3}, {%4,%5,%6,%7}, {%8,%9}, {%0,%1,%2,%3};"
        : "+f"(c[0]), "+f"(c[1]), "+f"(c[2]), "+f"(c[3])
        : "r"(a[0]), "r"(a[1]), "r"(a[2]), "r"(a[3]), "r"(b[0]), "r"(b[1]));
}
__device__ __forceinline__ uint32_t swz(uint32_t base, int r, int c) {
    return base + r * 128 + (c ^ ((r & 7) << 4));
}

// ============================ GEMM constants ===============================
static constexpr uint32_t OP_BYTES = 128 * 64 * 2;      // 16 KB per operand tile
static constexpr uint32_t CTRL_BYTES = 1024;

// single-pass pipeline: A + Bhi = 32 KB/stage, 6 stages
static constexpr int ST1 = 6;
static constexpr uint32_t STG1_BYTES = 2 * OP_BYTES;
static constexpr uint32_t SMEM1_DYN = CTRL_BYTES + ST1 * STG1_BYTES;  // 197632

// ============================ K/V projection + fused LN ====================
// grid (8 heads, 256 m-tiles, 2 kv), 288 threads (8 compute + producer warp).
// Single-pass B (weights fp16). z=0: K -> k16. z=1: V -> vh16/vl16.
__global__ __launch_bounds__(288, 1) void gemm_kv(
    const __grid_constant__ CUtensorMap tmAK,
    const __grid_constant__ CUtensorMap tmAV,
    const __grid_constant__ CUtensorMap tmB,    // batched (z: 0=Wk, 1=Wv)
    const float* __restrict__ bk, const float* __restrict__ bv,
    const float* __restrict__ gK, const float* __restrict__ betaK,
    const float* __restrict__ gV, const float* __restrict__ betaV,
    __half* __restrict__ k16, __half* __restrict__ vh16, __half* __restrict__ vl16)
{
    extern __shared__ __align__(1024) char smem[];
    const uint32_t sb = smem_u32(smem);
    const int tid = threadIdx.x;
    const int wid = tid >> 5, lane = tid & 31;
    const int warp_row = wid >> 2;
    const int warp_col = wid & 3;
    const bool producer = (wid == 8);

    const uint32_t full0  = sb;
    const uint32_t empty0 = sb + 128;
    const uint32_t tiles  = sb + CTRL_BYTES;

    const int h  = blockIdx.x;
    const int n0 = h * 128;
    const int m0 = blockIdx.y * 128;
    const int zKV = blockIdx.z;
    const CUtensorMap* tmA = zKV ? &tmAV : &tmAK;
    const int KB = 16;

    if (tid == 0) {
        for (int s = 0; s < ST1; s++) {
            mbar_init(full0 + s * 8, 1);
            mbar_init(empty0 + s * 8, 256);
        }
        fence_async_shared();
    }
    __syncthreads();

    float acc[4][4][4];
#pragma unroll
    for (int mi = 0; mi < 4; mi++)
#pragma unroll
        for (int ni = 0; ni < 4; ni++)
#pragma unroll
            for (int q = 0; q < 4; q++) acc[mi][ni][q] = 0.f;

    if (producer) {
        if (lane == 0) {
            for (int s = 0; s < ST1; s++) {
                uint32_t fb = full0 + s * 8;
                mbar_expect_tx(fb, STG1_BYTES);
                uint32_t a0 = tiles + s * STG1_BYTES;
                tma_load_3d(a0,            tmA,  s * 64, m0, 0,   fb);
                tma_load_3d(a0 + OP_BYTES, &tmB, s * 64, n0, zKV, fb);
            }
            for (int kb = ST1; kb < KB; kb++) {
                int s = kb % ST1;
                mbar_wait(empty0 + s * 8, (uint32_t)(((kb - ST1) / ST1) & 1));
                uint32_t fb = full0 + s * 8;
                mbar_expect_tx(fb, STG1_BYTES);
                uint32_t a0 = tiles + s * STG1_BYTES;
                tma_load_3d(a0,            tmA,  kb * 64, m0, 0,   fb);
                tma_load_3d(a0 + OP_BYTES, &tmB, kb * 64, n0, zKV, fb);
            }
        }
    } else {
        const int aR = lane & 15;
        const int aC = (lane >> 4) << 4;
        const int bR = ((lane >> 4) << 3) + (lane & 7);
        const int bC = ((lane >> 3) & 1) << 4;

        for (int kb = 0; kb < KB; kb++) {
            const int s = kb % ST1;
            mbar_wait(full0 + s * 8, (uint32_t)((kb / ST1) & 1));

            const uint32_t A0 = tiles + s * STG1_BYTES;
            const uint32_t B0 = A0 + OP_BYTES;

#pragma unroll
            for (int ki = 0; ki < 4; ki++) {
                const int kc = ki * 32;
                uint32_t af[4][4], bhi[4][2];
#pragma unroll
                for (int mi = 0; mi < 4; mi++) {
                    int r = warp_row * 64 + mi * 16 + aR;
                    ldsm4(af[mi], swz(A0, r, kc + aC));
                }
#pragma unroll
                for (int g = 0; g < 2; g++) {
                    int r = warp_col * 32 + g * 16 + bR;
                    uint32_t t[4];
                    ldsm4(t, swz(B0, r, kc + bC));
                    bhi[2 * g][0] = t[0]; bhi[2 * g][1] = t[1];
                    bhi[2 * g + 1][0] = t[2]; bhi[2 * g + 1][1] = t[3];
                }
                if (ki == 3) mbar_arrive(empty0 + s * 8);
#pragma unroll
                for (int mi = 0; mi < 4; mi++)
#pragma unroll
                    for (int ni = 0; ni < 4; ni++)
                        mma_f16(acc[mi][ni], af[mi], bhi[ni]);
            }
        }
    }

    // ---- fused LN epilogue ----
    __syncthreads();

    float2* part  = (float2*)(smem + CTRL_BYTES);            // [128][16]
    float2* stats = (float2*)(smem + CTRL_BYTES + 16384);    // [128]

    const float* biasp = zKV ? bv : bk;
    const float* gsel  = zKV ? gV : gK;
    const float* besel = zKV ? betaV : betaK;

    if (!producer) {
        const int slot = warp_col * 4 + (lane & 3);
#pragma unroll
        for (int mi = 0; mi < 4; mi++) {
#pragma unroll
            for (int ni = 0; ni < 4; ni++) {
                int col = warp_col * 32 + ni * 8 + (lane & 3) * 2;
                float b0v = biasp[n0 + col], b1v = biasp[n0 + col + 1];
                acc[mi][ni][0] += b0v; acc[mi][ni][1] += b1v;
                acc[mi][ni][2] += b0v; acc[mi][ni][3] += b1v;
            }
#pragma unroll
            for (int half = 0; half < 2; half++) {
                float s = 0.f, sq = 0.f;
#pragma unroll
                for (int ni = 0; ni < 4; ni++) {
                    float v0 = acc[mi][ni][half * 2 + 0];
                    float v1 = acc[mi][ni][half * 2 + 1];
                    s += v0 + v1;
                    sq += v0 * v0 + v1 * v1;
                }
                int r = warp_row * 64 + mi * 16 + (lane >> 2) + half * 8;
                part[r * 16 + slot] = make_float2(s, sq);
            }
        }
    }
    __syncthreads();
    if (tid < 128) {
        float s = 0.f, sq = 0.f;
#pragma unroll
        for (int i = 0; i < 16; i++) {
            float2 p = part[tid * 16 + i];
            s += p.x; sq += p.y;
        }
        float mean = s * (1.f / 128.f);
        float var  = sq * (1.f / 128.f) - mean * mean;
        stats[tid] = make_float2(mean, rsqrtf(var + 1e-5f));
    }
    __syncthreads();

    if (!producer) {
#pragma unroll
        for (int mi = 0; mi < 4; mi++) {
#pragma unroll
            for (int half = 0; half < 2; half++) {
                int r = warp_row * 64 + mi * 16 + (lane >> 2) + half * 8;
                float2 st = stats[r];
                int m = m0 + r;
                int b = m >> 13, sIdx = m & 8191;
                size_t base = (((size_t)(b * NH + h)) * NS + sIdx) * NDK;
#pragma unroll
                for (int ni = 0; ni < 4; ni++) {
                    int col = warp_col * 32 + ni * 8 + (lane & 3) * 2;
                    float gg0 = gsel[n0 + col],  gg1 = gsel[n0 + col + 1];
                    float be0 = besel[n0 + col], be1 = besel[n0 + col + 1];
                    float y0 = (acc[mi][ni][half * 2 + 0] - st.x) * st.y * gg0 + be0;
                    float y1 = (acc[mi][ni][half * 2 + 1] - st.x) * st.y * gg1 + be1;
                    __half h0 = __float2half_rn(y0);
                    __half h1 = __float2half_rn(y1);
                    if (!zKV) {
                        *(__half2*)(k16 + base + col) = __half2(h0, h1);
                    } else {
                        *(__half2*)(vh16 + base + col) = __half2(h0, h1);
                        __half l0 = __float2half_rn(y0 - __half2float(h0));
                        __half l1 = __float2half_rn(y1 - __half2float(h1));
                        *(__half2*)(vl16 + base + col) = __half2(l0, l1);
                    }
                }
            }
        }
    }
}

// ============================ final GEMM (single-pass) =====================
// out[b] = query[b] @ Wcomb[b]^T + pos (x) gpos[b] + bias2[b]
__global__ __launch_bounds__(288, 1) void gemm_out(
    const __grid_constant__ CUtensorMap tmA,
    const __grid_constant__ CUtensorMap tmB,
    const float* __restrict__ bias2,
    const float* __restrict__ posv,
    const float* __restrict__ gposv,
    float* __restrict__ C)
{
    extern __shared__ __align__(1024) char smem[];
    const uint32_t sb = smem_u32(smem);
    const int tid = threadIdx.x;
    const int wid = tid >> 5, lane = tid & 31;
    const int warp_row = wid >> 2;
    const int warp_col = wid & 3;
    const bool producer = (wid == 8);

    const uint32_t full0  = sb;
    const uint32_t empty0 = sb + 128;
    const uint32_t tiles  = sb + CTRL_BYTES;

    const int n0 = blockIdx.x * 128;
    const int zB = blockIdx.z;
    const int m0 = zB * 8192 + blockIdx.y * 128;
    const int KB = 16;

    if (tid == 0) {
        for (int s = 0; s < ST1; s++) {
            mbar_init(full0 + s * 8, 1);
            mbar_init(empty0 + s * 8, 256);
        }
        fence_async_shared();
    }
    __syncthreads();

    if (producer) {
        if (lane == 0) {
            for (int s = 0; s < ST1; s++) {
                uint32_t fb = full0 + s * 8;
                mbar_expect_tx(fb, STG1_BYTES);
                uint32_t a0 = tiles + s * STG1_BYTES;
                tma_load_3d(a0,            &tmA, s * 64, m0, 0,  fb);
                tma_load_3d(a0 + OP_BYTES, &tmB, s * 64, n0, zB, fb);
            }
            for (int kb = ST1; kb < KB; kb++) {
                int s = kb % ST1;
                mbar_wait(empty0 + s * 8, (uint32_t)(((kb - ST1) / ST1) & 1));
                uint32_t fb = full0 + s * 8;
                mbar_expect_tx(fb, STG1_BYTES);
                uint32_t a0 = tiles + s * STG1_BYTES;
                tma_load_3d(a0,            &tmA, kb * 64, m0, 0,  fb);
                tma_load_3d(a0 + OP_BYTES, &tmB, kb * 64, n0, zB, fb);
            }
        }
        return;
    }

    float acc[4][4][4];
#pragma unroll
    for (int mi = 0; mi < 4; mi++)
#pragma unroll
        for (int ni = 0; ni < 4; ni++)
#pragma unroll
            for (int q = 0; q < 4; q++) acc[mi][ni][q] = 0.f;

    const int aR = lane & 15;
    const int aC = (lane >> 4) << 4;
    const int bR = ((lane >> 4) << 3) + (lane & 7);
    const int bC = ((lane >> 3) & 1) << 4;

    for (int kb = 0; kb < KB; kb++) {
        const int s = kb % ST1;
        mbar_wait(full0 + s * 8, (uint32_t)((kb / ST1) & 1));

        const uint32_t A0 = tiles + s * STG1_BYTES;
        const uint32_t B0 = A0 + OP_BYTES;

#pragma unroll
        for (int ki = 0; ki < 4; ki++) {
            const int kc = ki * 32;
            uint32_t af[4][4], bhi[4][2];
#pragma unroll
            for (int mi = 0; mi < 4; mi++) {
                int r = warp_row * 64 + mi * 16 + aR;
                ldsm4(af[mi], swz(A0, r, kc + aC));
            }
#pragma unroll
            for (int g = 0; g < 2; g++) {
                int r = warp_col * 32 + g * 16 + bR;
                uint32_t t[4];
                ldsm4(t, swz(B0, r, kc + bC));
                bhi[2 * g][0] = t[0]; bhi[2 * g][1] = t[1];
                bhi[2 * g + 1][0] = t[2]; bhi[2 * g + 1][1] = t[3];
            }
            if (ki == 3) mbar_arrive(empty0 + s * 8);
#pragma unroll
            for (int mi = 0; mi < 4; mi++)
#pragma unroll
                for (int ni = 0; ni < 4; ni++)
                    mma_f16(acc[mi][ni], af[mi], bhi[ni]);
        }
    }

    const float* biasp = bias2 + zB * 1024;
    const float* gpp   = gposv + zB * 1024;

#pragma unroll
    for (int mi = 0; mi < 4; mi++) {
        int r = m0 + warp_row * 64 + mi * 16 + (lane >> 2);
        float pv = posv[r];
        float pv2 = posv[r + 8];
#pragma unroll
        for (int ni = 0; ni < 4; ni++) {
            int cc = n0 + warp_col * 32 + ni * 8 + (lane & 3) * 2;
            float b0v = biasp[cc], b1v = biasp[cc + 1];
            float g0 = gpp[cc], g1 = gpp[cc + 1];
            float2 v0 = { acc[mi][ni][0] + b0v + pv * g0,
                          acc[mi][ni][1] + b1v + pv * g1 };
            float2 v1 = { acc[mi][ni][2] + b0v + pv2 * g0,
                          acc[mi][ni][3] + b1v + pv2 * g1 };
            *(float2*)(C + (size_t)r * 1024 + cc) = v0;
            *(float2*)(C + (size_t)(r + 8) * 1024 + cc) = v1;
        }
    }
}

// ============================ 3-pass GEMM (A hi/lo, B hi/lo) ===============
static constexpr int ST3 = 3;
static constexpr uint32_t STG3_BYTES = 4 * OP_BYTES;
static constexpr uint32_t SMEM3_DYN = CTRL_BYTES + ST3 * STG3_BYTES;

__global__ __launch_bounds__(256, 1) void gemm_mma3(
    const __grid_constant__ CUtensorMap tmAhi,
    const __grid_constant__ CUtensorMap tmAlo,
    const __grid_constant__ CUtensorMap tmBhi,
    const __grid_constant__ CUtensorMap tmBlo,
    float* __restrict__ C, int KB)
{
    extern __shared__ __align__(1024) char smem[];
    const uint32_t sb = smem_u32(smem);
    const int tid = threadIdx.x;
    const int wid = tid >> 5, lane = tid & 31;
    const int warp_row = wid >> 2;
    const int warp_col = wid & 3;

    const uint32_t full0  = sb;
    const uint32_t empty0 = sb + 128;
    const uint32_t tiles  = sb + CTRL_BYTES;

    const int n0 = blockIdx.x * 128;
    const int aY = blockIdx.y * 128;
    const int aZ = blockIdx.z;
    const int m0 = blockIdx.z * 1024 + aY;

    if (tid == 0) {
        for (int s = 0; s < ST3; s++) {
            mbar_init(full0 + s * 8, 1);
            mbar_init(empty0 + s * 8, 256);
        }
        fence_async_shared();
    }
    __syncthreads();

    if (tid == 0) {
        for (int s = 0; s < ST3; s++) {
            uint32_t fb = full0 + s * 8;
            mbar_expect_tx(fb, STG3_BYTES);
            uint32_t a0 = tiles + s * STG3_BYTES;
            tma_load_3d(a0,                &tmAhi, s * 64, aY, aZ, fb);
            tma_load_3d(a0 + OP_BYTES,     &tmAlo, s * 64, aY, aZ, fb);
            tma_load_3d(a0 + 2 * OP_BYTES, &tmBhi, s * 64, n0, 0,  fb);
            tma_load_3d(a0 + 3 * OP_BYTES, &tmBlo, s * 64, n0, 0,  fb);
        }
    }

    float acc[4][4][4];
#pragma unroll
    for (int mi = 0; mi < 4; mi++)
#pragma unroll
        for (int ni = 0; ni < 4; ni++)
#pragma unroll
            for (int q = 0; q < 4; q++) acc[mi][ni][q] = 0.f;

    const int aR = lane & 15;
    const int aC = (lane >> 4) << 4;
    const int bR = ((lane >> 4) << 3) + (lane & 7);
    const int bC = ((lane >> 3) & 1) << 4;

    for (int kb = 0; kb < KB; kb++) {
        const int s = kb % ST3;
        const uint32_t ph = (uint32_t)((kb / ST3) & 1);
        mbar_wait(full0 + s * 8, ph);

        const uint32_t A0 = tiles + s * STG3_BYTES;
        const uint32_t B0 = A0 + 2 * OP_BYTES;

#pragma unroll
        for (int ki = 0; ki < 4; ki++) {
            const int kc = ki * 32;
            uint32_t ahi[4][4], alo[4][4], bhi[4][2], blo[4][2];
#pragma unroll
            for (int mi = 0; mi < 4; mi++) {
                int r = warp_row * 64 + mi * 16 + aR;
                uint32_t ad = swz(A0, r, kc + aC);
                ldsm4(ahi[mi], ad);
                ldsm4(alo[mi], ad + OP_BYTES);
            }
#pragma unroll
            for (int g = 0; g < 2; g++) {
                int r = warp_col * 32 + g * 16 + bR;
                uint32_t bd = swz(B0, r, kc + bC);
                uint32_t t[4];
                ldsm4(t, bd);
                bhi[2 * g][0] = t[0]; bhi[2 * g][1] = t[1];
                bhi[2 * g + 1][0] = t[2]; bhi[2 * g + 1][1] = t[3];
                ldsm4(t, bd + OP_BYTES);
                blo[2 * g][0] = t[0]; blo[2 * g][1] = t[1];
                blo[2 * g + 1][0] = t[2]; blo[2 * g + 1][1] = t[3];
            }
#pragma unroll
            for (int mi = 0; mi < 4; mi++)
#pragma unroll
                for (int ni = 0; ni < 4; ni++) {
                    mma_f16(acc[mi][ni], ahi[mi], bhi[ni]);
                    mma_f16(acc[mi][ni], ahi[mi], blo[ni]);
                    mma_f16(acc[mi][ni], alo[mi], bhi[ni]);
                }
        }

        mbar_arrive(empty0 + s * 8);

        if (tid == 0 && kb + ST3 < KB) {
            mbar_wait(empty0 + s * 8, ph);
            uint32_t fb = full0 + s * 8;
            mbar_expect_tx(fb, STG3_BYTES);
            uint32_t a0 = tiles + s * STG3_BYTES;
            int kx = (kb + ST3) * 64;
            tma_load_3d(a0,                &tmAhi, kx, aY, aZ, fb);
            tma_load_3d(a0 + OP_BYTES,     &tmAlo, kx, aY, aZ, fb);
            tma_load_3d(a0 + 2 * OP_BYTES, &tmBhi, kx, n0, 0,  fb);
            tma_load_3d(a0 + 3 * OP_BYTES, &tmBlo, kx, n0, 0,  fb);
        }
    }

#pragma unroll
    for (int mi = 0; mi < 4; mi++) {
        int r = m0 + warp_row * 64 + mi * 16 + (lane >> 2);
#pragma unroll
        for (int ni = 0; ni < 4; ni++) {
            int cc = n0 + warp_col * 32 + ni * 8 + (lane & 3) * 2;
            float2 v0 = { acc[mi][ni][0], acc[mi][ni][1] };
            float2 v1 = { acc[mi][ni][2], acc[mi][ni][3] };
            *(float2*)(C + (size_t)r * 1024 + cc) = v0;
            *(float2*)(C + (size_t)(r + 8) * 1024 + cc) = v1;
        }
    }
}

// ---------------------------------------------------------------------------
__global__ __launch_bounds__(256) void cvt16_kernel(
    const float* __restrict__ src, __half* __restrict__ dst, int n)
{
    int i = (blockIdx.x * 256 + threadIdx.x) * 8;
    if (i >= n) return;
    float4 v0 = *(const float4*)(src + i);
    float4 v1 = *(const float4*)(src + i + 4);
    __half2 h[4];
    h[0] = __floats2half2_rn(v0.x, v0.y);
    h[1] = __floats2half2_rn(v0.z, v0.w);
    h[2] = __floats2half2_rn(v1.x, v1.y);
    h[3] = __floats2half2_rn(v1.z, v1.w);
    *(uint4*)(dst + i) = *(uint4*)h;
}

__global__ __launch_bounds__(256) void split16_kernel(
    const float* __restrict__ src, __half* __restrict__ hi,
    __half* __restrict__ lo, int n)
{
    int i = (blockIdx.x * 256 + threadIdx.x) * 4;
    if (i >= n) return;
    float4 v = *(const float4*)(src + i);
    __half h0 = __float2half_rn(v.x);
    __half h1 = __float2half_rn(v.y);
    __half h2 = __float2half_rn(v.z);
    __half h3 = __float2half_rn(v.w);
    __half l0 = __float2half_rn(v.x - __half2float(h0));
    __half l1 = __float2half_rn(v.y - __half2float(h1));
    __half l2 = __float2half_rn(v.z - __half2float(h2));
    __half l3 = __float2half_rn(v.w - __half2float(h3));
    __half2 hp[2] = { __half2(h0, h1), __half2(h2, h3) };
    __half2 lp[2] = { __half2(l0, l1), __half2(l2, l3) };
    *(uint2*)(hi + i) = *(uint2*)hp;
    *(uint2*)(lo + i) = *(uint2*)lp;
}

__global__ __launch_bounds__(256) void tsplit16_kernel(
    const float* __restrict__ W, __half* __restrict__ hi, __half* __restrict__ lo)
{
    __shared__ float t[32][33];
    const int o0 = blockIdx.y * 32, i0 = blockIdx.x * 32;
    const int c = threadIdx.x & 31;
    const int r0 = threadIdx.x >> 5;
#pragma unroll
    for (int it = 0; it < 4; it++) {
        int r = r0 + it * 8;
        t[r][c] = W[(size_t)(o0 + r) * 1024 + i0 + c];
    }
    __syncthreads();
#pragma unroll
    for (int it = 0; it < 4; it++) {
        int r = r0 + it * 8;
        float v = t[c][r];
        __half h = __float2half_rn(v);
        size_t idx = (size_t)(i0 + r) * 1024 + o0 + c;
        hi[idx] = h;
        lo[idx] = __float2half_rn(v - __half2float(h));
    }
}

// ---------------------------------------------------------------------------
// p_attn core + edges fused. grid (32 bh, 8 s-split), block 256.
// ---------------------------------------------------------------------------
__global__ __launch_bounds__(256) void pa_core_mma(
    const __half* __restrict__ k16, const __half* __restrict__ vh16,
    const __half* __restrict__ vl16, const float* __restrict__ pos,
    float* __restrict__ pa)
{
    __shared__ __half Ks[32 * 136];
    __shared__ __half Vh[32 * 136];
    __shared__ __half Vl[32 * 136];
    __shared__ float ps[32];

    const int bh = blockIdx.x;
    const int b = bh >> 3;
    const int sp = blockIdx.y;
    const int tid = threadIdx.x;
    const int wid = tid >> 5, lane = tid & 31;
    const int warp_row = wid >> 2;
    const int warp_col = wid & 3;

    const uint32_t ksb = smem_u32(Ks);
    const uint32_t vhb = smem_u32(Vh);
    const uint32_t vlb = smem_u32(Vl);

    const size_t gbase = ((size_t)bh * NS + sp * 1024) * NDK;
    const float* posb = pos + (size_t)b * NS + sp * 1024;

    float acc[4][4][4];
#pragma unroll
    for (int mi = 0; mi < 4; mi++)
#pragma unroll
        for (int ni = 0; ni < 4; ni++)
#pragma unroll
            for (int q = 0; q < 4; q++) acc[mi][ni][q] = 0.f;

    float eacc = 0.f;
    float p2 = 0.f;

    const int aRow = (lane & 7) | ((lane >> 4) << 3);
    const int aCol = ((lane >> 3) & 1) << 3;
    const int bRow = (lane & 7) | (((lane >> 3) & 1) << 3);
    const int bCol = ((lane >> 4) & 1) << 3;
    const int ecol = tid & 127;

    for (int s0 = 0; s0 < 1024; s0 += 32) {
#pragma unroll
        for (int it = 0; it < 2; it++) {
            int f = tid + it * 256;
            int row = f >> 4;
            int c8 = (f & 15) * 8;
            size_t ga = gbase + (size_t)(s0 + row) * NDK + c8;
            int so = row * 136 + c8;
            *(float4*)(Ks + so) = *(const float4*)(k16 + ga);
            *(float4*)(Vh + so) = *(const float4*)(vh16 + ga);
            *(float4*)(Vl + so) = *(const float4*)(vl16 + ga);
        }
        if (tid < 32) ps[tid] = posb[s0 + tid];
        __syncthreads();

#pragma unroll
        for (int ki = 0; ki < 2; ki++) {
            const int kio = ki * 16;
            uint32_t af[4][4], bhi[4][2], blo[4][2];
#pragma unroll
            for (int mi = 0; mi < 4; mi++) {
                int mcol = warp_row * 64 + mi * 16 + aCol;
                ldsm4t(af[mi], ksb + (kio + aRow) * 272 + mcol * 2);
            }
#pragma unroll
            for (int g = 0; g < 2; g++) {
                int ec = warp_col * 32 + g * 16 + bCol;
                uint32_t off = (kio + bRow) * 272 + ec * 2;
                uint32_t t[4];
                ldsm4t(t, vhb + off);
                bhi[2 * g][0] = t[0]; bhi[2 * g][1] = t[1];
                bhi[2 * g + 1][0] = t[2]; bhi[2 * g + 1][1] = t[3];
                ldsm4t(t, vlb + off);
                blo[2 * g][0] = t[0]; blo[2 * g][1] = t[1];
                blo[2 * g + 1][0] = t[2]; blo[2 * g + 1][1] = t[3];
            }
#pragma unroll
            for (int mi = 0; mi < 4; mi++)
#pragma unroll
                for (int ni = 0; ni < 4; ni++) {
                    mma_f16(acc[mi][ni], af[mi], bhi[ni]);
                    mma_f16(acc[mi][ni], af[mi], blo[ni]);
                }
        }

        if (tid < 128) {
#pragma unroll 8
            for (int r = 0; r < 32; r++) {
                float v = __half2float(Vh[r * 136 + ecol]) +
                          __half2float(Vl[r * 136 + ecol]);
                eacc = fmaf(ps[r], v, eacc);
            }
        } else {
#pragma unroll 8
            for (int r = 0; r < 32; r++)
                eacc = fmaf(ps[r], __half2float(Ks[r * 136 + ecol]), eacc);
        }
        if (wid == 0) { float pv = ps[lane]; p2 = fmaf(pv, pv, p2); }
        __syncthreads();
    }

    const float invS = 1.0f / (float)NS;
    float* pab = pa + (size_t)bh * NE * NE;
#pragma unroll
    for (int mi = 0; mi < 4; mi++) {
        int d0 = warp_row * 64 + mi * 16 + (lane >> 2);
#pragma unroll
        for (int ni = 0; ni < 4; ni++) {
            int e0 = warp_col * 32 + ni * 8 + (lane & 3) * 2;
            atomicAdd(&pab[(1 + d0) * NE + 1 + e0],     acc[mi][ni][0] * invS);
            atomicAdd(&pab[(1 + d0) * NE + 2 + e0],     acc[mi][ni][1] * invS);
            atomicAdd(&pab[(1 + d0 + 8) * NE + 1 + e0], acc[mi][ni][2] * invS);
            atomicAdd(&pab[(1 + d0 + 8) * NE + 2 + e0], acc[mi][ni][3] * invS);
        }
    }
    if (tid < 128) atomicAdd(&pab[0 * NE + 1 + ecol], eacc * invS);
    else           atomicAdd(&pab[(1 + ecol) * NE + 0], eacc * invS);
    if (wid == 0) {
#pragma unroll
        for (int o = 16; o > 0; o >>= 1)
            p2 += __shfl_xor_sync(0xffffffffu, p2, o);
        if (lane == 0) atomicAdd(&pab[0], p2 * invS);
    }
}

// ---------------------------------------------------------------------------
__global__ __launch_bounds__(256) void g_kernel(
    const float* __restrict__ pa, const float* __restrict__ Wfc,
    float* __restrict__ Gd, float* __restrict__ gpos)
{
    extern __shared__ float sm[];
    float* pas = sm;
    float* ws  = sm + 129 * 132;

    const int nt = blockIdx.x, h = blockIdx.y, b = blockIdx.z;
    const int tid = threadIdx.x;
    const int n0 = nt * 128;

    const float* pab = pa + ((size_t)(b * NH + h)) * NE * NE;
    for (int i = tid; i < NE * NE; i += 256) {
        int d = i / NE, e = i - d * NE;
        pas[d * 132 + e] = pab[i];
    }
    for (int i = tid; i < 128 * NE; i += 256) {
        int n = i / NE, e = i - n * NE;
        ws[n * 132 + e] = Wfc[(size_t)(n0 + n) * KFC + h * NE + e];
    }
    __syncthreads();

    for (int o = tid; o < 128 * NE; o += 256) {
        int n = o / NE, d = o - n * NE;
        const float* pr = &pas[d * 132];
        const float* wr = &ws[n * 132];
        float acc = 0.f;
#pragma unroll 8
        for (int e4 = 0; e4 < 128; e4 += 4) {
            float4 a = *(const float4*)(pr + e4);
            float4 w = *(const float4*)(wr + e4);
            acc = fmaf(a.x, w.x, acc);
            acc = fmaf(a.y, w.y, acc);
            acc = fmaf(a.z, w.z, acc);
            acc = fmaf(a.w, w.w, acc);
        }
        acc = fmaf(pr[128], wr[128], acc);
        if (d == 0)
            atomicAdd(&gpos[b * 1024 + n0 + n], acc);
        else
            Gd[((size_t)b * 1024 + n0 + n) * 1024 + h * NDK + d - 1] = acc;
    }
}

// ---------------------------------------------------------------------------
__global__ __launch_bounds__(256) void bias2_kernel(
    const float* __restrict__ Gd, const float* __restrict__ bq,
    const float* __restrict__ bfc, float* __restrict__ bias2)
{
    const int n = blockIdx.x, b = blockIdx.y;
    const int tid = threadIdx.x;
    const float* row = Gd + ((size_t)b * 1024 + n) * 1024;
    float acc = 0.f;
    for (int o = tid; o < 1024; o += 256) acc = fmaf(bq[o], row[o], acc);
    __shared__ float red[256];
    red[tid] = acc;
    __syncthreads();
    for (int o = 128; o > 0; o >>= 1) {
        if (tid < o) red[tid] += red[tid + o];
        __syncthreads();
    }
    if (tid == 0) bias2[b * 1024 + n] = red[0] + bfc[n];
}

// ============================ host side ====================================
typedef CUresult (*EncodeFn)(CUtensorMap*, CUtensorMapDataType, cuuint32_t, void*,
                             const cuuint64_t*, const cuuint64_t*, const cuuint32_t*,
                             const cuuint32_t*, CUtensorMapInterleave, CUtensorMapSwizzle,
                             CUtensorMapL2promotion, CUtensorMapFloatOOBfill);

static EncodeFn get_encode() {
    static EncodeFn fn = nullptr;
    if (!fn) {
        void* p = nullptr;
        cudaDriverEntryPointQueryResult st;
        cudaGetDriverEntryPoint("cuTensorMapEncodeTiled", &p, cudaEnableDefault, &st);
        fn = (EncodeFn)p;
    }
    return fn;
}

static void encode_f16(CUtensorMap* m, const void* base,
                       uint64_t kdim, uint64_t rows, uint64_t nz) {
    cuuint64_t dims[3]    = { kdim, rows, nz };
    cuuint64_t strides[2] = { kdim * 2, rows * kdim * 2 };
    cuuint32_t box[3]     = { 64, 128, 1 };
    cuuint32_t est[3]     = { 1, 1, 1 };
    get_encode()(m, CU_TENSOR_MAP_DATA_TYPE_FLOAT16, 3, (void*)base,
                 dims, strides, box, est,
                 CU_TENSOR_MAP_INTERLEAVE_NONE, CU_TENSOR_MAP_SWIZZLE_128B,
                 CU_TENSOR_MAP_L2_PROMOTION_L2_128B, CU_TENSOR_MAP_FLOAT_OOB_FILL_NONE);
}

extern "C" void kernel_launch(void* const* d_in, const int* in_sizes, int n_in,
                              void* d_out, int out_size)
{
    (void)in_sizes; (void)n_in; (void)out_size;
    const float* query = (const float*)d_in[0];
    const float* key   = (const float*)d_in[1];
    const float* value = (const float*)d_in[2];
    const float* pos   = (const float*)d_in[3];
    const float* Wq    = (const float*)d_in[4];
    const float* bq    = (const float*)d_in[5];
    const float* Wk    = (const float*)d_in[6];
    const float* bk    = (const float*)d_in[7];
    const float* Wv    = (const float*)d_in[8];
    const float* bv    = (const float*)d_in[9];
    const float* gK    = (const float*)d_in[10];
    const float* betaK = (const float*)d_in[11];
    const float* gV    = (const float*)d_in[12];
    const float* betaV = (const float*)d_in[13];
    const float* Wfc   = (const float*)d_in[14];
    const float* bfc   = (const float*)d_in[15];
    float* out = (float*)d_out;

    float *wc, *pa, *Gd, *gpos, *bias2;
    __half *a16, *c16, *bh16, *bl16, *k16, *vh16, *vl16;
    cudaGetSymbolAddress((void**)&wc, g_wc);
    cudaGetSymbolAddress((void**)&pa, g_pa);
    cudaGetSymbolAddress((void**)&Gd, g_G);
    cudaGetSymbolAddress((void**)&gpos, g_gpos);
    cudaGetSymbolAddress((void**)&bias2, g_bias2);
    cudaGetSymbolAddress((void**)&a16, g_a16);
    cudaGetSymbolAddress((void**)&c16, g_c16);
    cudaGetSymbolAddress((void**)&bh16, g_bh16);
    cudaGetSymbolAddress((void**)&bl16, g_bl16);
    cudaGetSymbolAddress((void**)&k16, g_k16);
    cudaGetSymbolAddress((void**)&vh16, g_vh16);
    cudaGetSymbolAddress((void**)&vl16, g_vl16);

    cudaFuncSetAttribute(gemm_kv, cudaFuncAttributeMaxDynamicSharedMemorySize,
                         (int)SMEM1_DYN);
    cudaFuncSetAttribute(gemm_out, cudaFuncAttributeMaxDynamicSharedMemorySize,
                         (int)SMEM1_DYN);
    cudaFuncSetAttribute(gemm_mma3, cudaFuncAttributeMaxDynamicSharedMemorySize,
                         (int)SMEM3_DYN);
    cudaFuncSetAttribute(g_kernel, cudaFuncAttributeMaxDynamicSharedMemorySize,
                         (129 + 128) * 132 * (int)sizeof(float));

    CUtensorMap tAK, tAV, tBkv, tGh, tGl, tWqh, tWql, tAq, tWc;
    encode_f16(&tAK, a16, 1024, 32768, 1);
    encode_f16(&tAV, c16, 1024, 32768, 1);
    encode_f16(&tBkv, bh16, 1024, 1024, 2);     // z: 0=Wk, 1=Wv
    encode_f16(&tGh,  a16,           1024, 1024, 4);
    encode_f16(&tGl,  a16 + 4194304, 1024, 1024, 4);
    encode_f16(&tWqh, bh16, 1024, 1024, 1);
    encode_f16(&tWql, bl16, 1024, 1024, 1);
    encode_f16(&tAq,  a16,  1024, 32768, 1);
    encode_f16(&tWc,  bh16, 1024, 1024, 4);

    const int NA = 33554432, NW = 1048576, NGD = 4194304;

    // Inputs to fp16 (weights single-pass now)
    cvt16_kernel<<<NA / 2048, 256>>>(key, a16, NA);
    cvt16_kernel<<<NA / 2048, 256>>>(value, c16, NA);
    cvt16_kernel<<<NW / 2048, 256>>>(Wk, bh16, NW);
    cvt16_kernel<<<NW / 2048, 256>>>(Wv, bh16 + NW, NW);

    // K+V projection (single-pass B) with fused per-head LN
    gemm_kv<<<dim3(8, 256, 2), 288, SMEM1_DYN>>>(
        tAK, tAV, tBkv, bk, bv, gK, betaK, gV, betaV, k16, vh16, vl16);

    // p_attn = Kc^T Vc / S  (core + edges fused; V hi/lo kept)
    cudaMemsetAsync(pa, 0, (size_t)32 * NE * NE * sizeof(float));
    pa_core_mma<<<dim3(32, 8), 256>>>(k16, vh16, vl16, pos, pa);

    // Gd = pa @ Wfc_h^T (head cols), gpos = SUM over heads of pos col
    cudaMemsetAsync(gpos, 0, 4096 * sizeof(float));
    g_kernel<<<dim3(8, NH, NB), 256, (129 + 128) * 132 * sizeof(float)>>>(
        pa, Wfc, Gd, gpos);

    // bias2 = bfc + bq @ Gd^T
    bias2_kernel<<<dim3(1024, 4), 256>>>(Gd, bq, bfc, bias2);

    // Split Gd (A of gemm3) and Wq^T (B of gemm3, hi/lo)
    split16_kernel<<<NGD / 1024, 256>>>(Gd, a16, a16 + 4194304, NGD);
    tsplit16_kernel<<<dim3(32, 32), 256>>>(Wq, bh16, bl16);

    // Wcomb[b] = Gd[b] @ Wq (3-pass, near-fp32)
    gemm_mma3<<<dim3(8, 8, 4), 256, SMEM3_DYN>>>(tGh, tGl, tWqh, tWql, wc, 16);

    // Wcomb -> single fp16, query -> fp16 (reuses a16)
    cvt16_kernel<<<NGD / 2048, 256>>>(wc, bh16, NGD);
    cvt16_kernel<<<NA / 2048, 256>>>(query, a16, NA);

    // out[b] = query[b] @ Wcomb[b]^T + pos (x) gpos[b] + bias2[b]  (single-pass)
    gemm_out<<<dim3(8, 64, 4), 288, SMEM1_DYN>>>(tAq, tWc, bias2, pos, gpos, out);
}

// round 9
// speedup vs baseline: 7.6585x; 1.0368x over previous
#include <cuda_runtime.h>
#include <cuda.h>
#include <cuda_fp16.h>
#include <cstdint>
#include <cstddef>

// Problem constants
#define NB 4
#define NS 8192
#define ND 1024
#define NH 8
#define NDK 128
#define NE 129
#define NM 32768
#define KFC 1032

// ---------------- scratch (static device globals; no allocations) ----------
static __device__ float g_pa[532512];       // (32, 129, 129) p_attn
static __device__ float g_gpos[4096];       // (B, 1024) pos-column of G (sum over h)
static __device__ float g_bias2[4096];      // (B, 1024) folded bias
static __device__ __half g_a16[33554432];   // key fp16 / Gd hi+lo / query fp16
static __device__ __half g_c16[33554432];   // value fp16
static __device__ __half g_bh16[4227072];   // B hi (Wk+Wv / Wq hi)
static __device__ __half g_bl16[4227072];   // B lo (Wq lo for gemm3)
static __device__ __half g_k16[33554432];   // LN'd K, head-major (bh,s,d) fp16
static __device__ __half g_vh16[33554432];  // LN'd V, head-major fp16
static __device__ __half g_wc16[4194304];   // Wcomb fp16 (B,1024,1024)

// ============================ PTX helpers ==================================
__device__ __forceinline__ uint32_t smem_u32(const void* p) {
    uint32_t a;
    asm("{ .reg .u64 t; cvta.to.shared.u64 t, %1; cvt.u32.u64 %0, t; }"
        : "=r"(a) : "l"(p));
    return a;
}
__device__ __forceinline__ void mbar_init(uint32_t mbar, uint32_t cnt) {
    asm volatile("mbarrier.init.shared.b64 [%0], %1;" :: "r"(mbar), "r"(cnt) : "memory");
}
__device__ __forceinline__ void mbar_expect_tx(uint32_t mbar, uint32_t bytes) {
    asm volatile("mbarrier.arrive.expect_tx.shared.b64 _, [%0], %1;"
                 :: "r"(mbar), "r"(bytes) : "memory");
}
__device__ __forceinline__ void mbar_arrive(uint32_t mbar) {
    asm volatile("mbarrier.arrive.shared.b64 _, [%0];" :: "r"(mbar) : "memory");
}
__device__ __forceinline__ void mbar_wait(uint32_t mbar, uint32_t parity) {
    asm volatile(
        "{\n\t.reg .pred P;\n\t"
        "BWL_%=:\n\t"
        "mbarrier.try_wait.parity.acquire.cta.shared::cta.b64 P, [%0], %1, 0x989680;\n\t"
        "@P bra.uni BWD_%=;\n\t"
        "bra.uni BWL_%=;\n\t"
        "BWD_%=:\n\t}"
        :: "r"(mbar), "r"(parity) : "memory");
}
__device__ __forceinline__ void tma_load_3d(uint32_t dst, const CUtensorMap* tm,
                                            int x, int y, int z, uint32_t mbar) {
    asm volatile(
        "cp.async.bulk.tensor.3d.shared::cta.global.tile.mbarrier::complete_tx::bytes "
        "[%0], [%1, {%2, %3, %4}], [%5];"
        :: "r"(dst), "l"(tm), "r"(x), "r"(y), "r"(z), "r"(mbar) : "memory");
}
__device__ __forceinline__ void fence_async_shared() {
    asm volatile("fence.proxy.async.shared::cta;" ::: "memory");
}
__device__ __forceinline__ void ldsm4(uint32_t* r, uint32_t addr) {
    asm volatile("ldmatrix.sync.aligned.m8n8.x4.shared.b16 {%0,%1,%2,%3}, [%4];"
                 : "=r"(r[0]), "=r"(r[1]), "=r"(r[2]), "=r"(r[3]) : "r"(addr));
}
__device__ __forceinline__ void ldsm4t(uint32_t* r, uint32_t addr) {
    asm volatile("ldmatrix.sync.aligned.m8n8.x4.trans.shared.b16 {%0,%1,%2,%3}, [%4];"
                 : "=r"(r[0]), "=r"(r[1]), "=r"(r[2]), "=r"(r[3]) : "r"(addr));
}
__device__ __forceinline__ void mma_f16(float* c, const uint32_t* a, const uint32_t* b) {
    asm volatile(
        "mma.sync.aligned.m16n8k16.row.col.f32.f16.f16.f32 "
        "{%0,%1,%2,%3}, {%4,%5,%6,%7}, {%8,%9}, {%0,%1,%2,%3};"
        : "+f"(c[0]), "+f"(c[1]), "+f"(c[2]), "+f"(c[3])
        : "r"(a[0]), "r"(a[1]), "r"(a[2]), "r"(a[3]), "r"(b[0]), "r"(b[1]));
}
__device__ __forceinline__ uint32_t swz(uint32_t base, int r, int c) {
    return base + r * 128 + (c ^ ((r & 7) << 4));
}

// ============================ GEMM constants ===============================
static constexpr uint32_t OP_BYTES = 128 * 64 * 2;      // 16 KB per operand tile
static constexpr uint32_t CTRL_BYTES = 1024;

// single-pass pipeline: A + B = 32 KB/stage, 6 stages
static constexpr int ST1 = 6;
static constexpr uint32_t STG1_BYTES = 2 * OP_BYTES;
static constexpr uint32_t SMEM1_DYN = CTRL_BYTES + ST1 * STG1_BYTES;  // 197632

// ============================ K/V projection + fused LN ====================
// grid (8 heads, 256 m-tiles, 2 kv), 288 threads (8 compute + producer warp).
// z=0: K -> k16. z=1: V -> vh16 (single fp16 now).
__global__ __launch_bounds__(288, 1) void gemm_kv(
    const __grid_constant__ CUtensorMap tmAK,
    const __grid_constant__ CUtensorMap tmAV,
    const __grid_constant__ CUtensorMap tmB,    // batched (z: 0=Wk, 1=Wv)
    const float* __restrict__ bk, const float* __restrict__ bv,
    const float* __restrict__ gK, const float* __restrict__ betaK,
    const float* __restrict__ gV, const float* __restrict__ betaV,
    __half* __restrict__ k16, __half* __restrict__ vh16)
{
    extern __shared__ __align__(1024) char smem[];
    const uint32_t sb = smem_u32(smem);
    const int tid = threadIdx.x;
    const int wid = tid >> 5, lane = tid & 31;
    const int warp_row = wid >> 2;
    const int warp_col = wid & 3;
    const bool producer = (wid == 8);

    const uint32_t full0  = sb;
    const uint32_t empty0 = sb + 128;
    const uint32_t tiles  = sb + CTRL_BYTES;

    const int h  = blockIdx.x;
    const int n0 = h * 128;
    const int m0 = blockIdx.y * 128;
    const int zKV = blockIdx.z;
    const CUtensorMap* tmA = zKV ? &tmAV : &tmAK;
    const int KB = 16;

    if (tid == 0) {
        for (int s = 0; s < ST1; s++) {
            mbar_init(full0 + s * 8, 1);
            mbar_init(empty0 + s * 8, 256);
        }
        fence_async_shared();
    }
    __syncthreads();

    float acc[4][4][4];
#pragma unroll
    for (int mi = 0; mi < 4; mi++)
#pragma unroll
        for (int ni = 0; ni < 4; ni++)
#pragma unroll
            for (int q = 0; q < 4; q++) acc[mi][ni][q] = 0.f;

    if (producer) {
        if (lane == 0) {
            for (int s = 0; s < ST1; s++) {
                uint32_t fb = full0 + s * 8;
                mbar_expect_tx(fb, STG1_BYTES);
                uint32_t a0 = tiles + s * STG1_BYTES;
                tma_load_3d(a0,            tmA,  s * 64, m0, 0,   fb);
                tma_load_3d(a0 + OP_BYTES, &tmB, s * 64, n0, zKV, fb);
            }
            for (int kb = ST1; kb < KB; kb++) {
                int s = kb % ST1;
                mbar_wait(empty0 + s * 8, (uint32_t)(((kb - ST1) / ST1) & 1));
                uint32_t fb = full0 + s * 8;
                mbar_expect_tx(fb, STG1_BYTES);
                uint32_t a0 = tiles + s * STG1_BYTES;
                tma_load_3d(a0,            tmA,  kb * 64, m0, 0,   fb);
                tma_load_3d(a0 + OP_BYTES, &tmB, kb * 64, n0, zKV, fb);
            }
        }
    } else {
        const int aR = lane & 15;
        const int aC = (lane >> 4) << 4;
        const int bR = ((lane >> 4) << 3) + (lane & 7);
        const int bC = ((lane >> 3) & 1) << 4;

        for (int kb = 0; kb < KB; kb++) {
            const int s = kb % ST1;
            mbar_wait(full0 + s * 8, (uint32_t)((kb / ST1) & 1));

            const uint32_t A0 = tiles + s * STG1_BYTES;
            const uint32_t B0 = A0 + OP_BYTES;

#pragma unroll
            for (int ki = 0; ki < 4; ki++) {
                const int kc = ki * 32;
                uint32_t af[4][4], bhi[4][2];
#pragma unroll
                for (int mi = 0; mi < 4; mi++) {
                    int r = warp_row * 64 + mi * 16 + aR;
                    ldsm4(af[mi], swz(A0, r, kc + aC));
                }
#pragma unroll
                for (int g = 0; g < 2; g++) {
                    int r = warp_col * 32 + g * 16 + bR;
                    uint32_t t[4];
                    ldsm4(t, swz(B0, r, kc + bC));
                    bhi[2 * g][0] = t[0]; bhi[2 * g][1] = t[1];
                    bhi[2 * g + 1][0] = t[2]; bhi[2 * g + 1][1] = t[3];
                }
                if (ki == 3) mbar_arrive(empty0 + s * 8);
#pragma unroll
                for (int mi = 0; mi < 4; mi++)
#pragma unroll
                    for (int ni = 0; ni < 4; ni++)
                        mma_f16(acc[mi][ni], af[mi], bhi[ni]);
            }
        }
    }

    // ---- fused LN epilogue ----
    __syncthreads();

    float2* part  = (float2*)(smem + CTRL_BYTES);            // [128][16]
    float2* stats = (float2*)(smem + CTRL_BYTES + 16384);    // [128]

    const float* biasp = zKV ? bv : bk;
    const float* gsel  = zKV ? gV : gK;
    const float* besel = zKV ? betaV : betaK;
    __half* outp = zKV ? vh16 : k16;

    if (!producer) {
        const int slot = warp_col * 4 + (lane & 3);
#pragma unroll
        for (int mi = 0; mi < 4; mi++) {
#pragma unroll
            for (int ni = 0; ni < 4; ni++) {
                int col = warp_col * 32 + ni * 8 + (lane & 3) * 2;
                float b0v = biasp[n0 + col], b1v = biasp[n0 + col + 1];
                acc[mi][ni][0] += b0v; acc[mi][ni][1] += b1v;
                acc[mi][ni][2] += b0v; acc[mi][ni][3] += b1v;
            }
#pragma unroll
            for (int half = 0; half < 2; half++) {
                float s = 0.f, sq = 0.f;
#pragma unroll
                for (int ni = 0; ni < 4; ni++) {
                    float v0 = acc[mi][ni][half * 2 + 0];
                    float v1 = acc[mi][ni][half * 2 + 1];
                    s += v0 + v1;
                    sq += v0 * v0 + v1 * v1;
                }
                int r = warp_row * 64 + mi * 16 + (lane >> 2) + half * 8;
                part[r * 16 + slot] = make_float2(s, sq);
            }
        }
    }
    __syncthreads();
    if (tid < 128) {
        float s = 0.f, sq = 0.f;
#pragma unroll
        for (int i = 0; i < 16; i++) {
            float2 p = part[tid * 16 + i];
            s += p.x; sq += p.y;
        }
        float mean = s * (1.f / 128.f);
        float var  = sq * (1.f / 128.f) - mean * mean;
        stats[tid] = make_float2(mean, rsqrtf(var + 1e-5f));
    }
    __syncthreads();

    if (!producer) {
#pragma unroll
        for (int mi = 0; mi < 4; mi++) {
#pragma unroll
            for (int half = 0; half < 2; half++) {
                int r = warp_row * 64 + mi * 16 + (lane >> 2) + half * 8;
                float2 st = stats[r];
                int m = m0 + r;
                int b = m >> 13, sIdx = m & 8191;
                size_t base = (((size_t)(b * NH + h)) * NS + sIdx) * NDK;
#pragma unroll
                for (int ni = 0; ni < 4; ni++) {
                    int col = warp_col * 32 + ni * 8 + (lane & 3) * 2;
                    float gg0 = gsel[n0 + col],  gg1 = gsel[n0 + col + 1];
                    float be0 = besel[n0 + col], be1 = besel[n0 + col + 1];
                    float y0 = (acc[mi][ni][half * 2 + 0] - st.x) * st.y * gg0 + be0;
                    float y1 = (acc[mi][ni][half * 2 + 1] - st.x) * st.y * gg1 + be1;
                    *(__half2*)(outp + base + col) =
                        __half2(__float2half_rn(y0), __float2half_rn(y1));
                }
            }
        }
    }
}

// ============================ final GEMM (single-pass) =====================
// out[b] = query[b] @ Wcomb[b]^T + pos (x) gpos[b] + bias2[b]
__global__ __launch_bounds__(288, 1) void gemm_out(
    const __grid_constant__ CUtensorMap tmA,
    const __grid_constant__ CUtensorMap tmB,
    const float* __restrict__ bias2,
    const float* __restrict__ posv,
    const float* __restrict__ gposv,
    float* __restrict__ C)
{
    extern __shared__ __align__(1024) char smem[];
    const uint32_t sb = smem_u32(smem);
    const int tid = threadIdx.x;
    const int wid = tid >> 5, lane = tid & 31;
    const int warp_row = wid >> 2;
    const int warp_col = wid & 3;
    const bool producer = (wid == 8);

    const uint32_t full0  = sb;
    const uint32_t empty0 = sb + 128;
    const uint32_t tiles  = sb + CTRL_BYTES;

    const int n0 = blockIdx.x * 128;
    const int zB = blockIdx.z;
    const int m0 = zB * 8192 + blockIdx.y * 128;
    const int KB = 16;

    if (tid == 0) {
        for (int s = 0; s < ST1; s++) {
            mbar_init(full0 + s * 8, 1);
            mbar_init(empty0 + s * 8, 256);
        }
        fence_async_shared();
    }
    __syncthreads();

    if (producer) {
        if (lane == 0) {
            for (int s = 0; s < ST1; s++) {
                uint32_t fb = full0 + s * 8;
                mbar_expect_tx(fb, STG1_BYTES);
                uint32_t a0 = tiles + s * STG1_BYTES;
                tma_load_3d(a0,            &tmA, s * 64, m0, 0,  fb);
                tma_load_3d(a0 + OP_BYTES, &tmB, s * 64, n0, zB, fb);
            }
            for (int kb = ST1; kb < KB; kb++) {
                int s = kb % ST1;
                mbar_wait(empty0 + s * 8, (uint32_t)(((kb - ST1) / ST1) & 1));
                uint32_t fb = full0 + s * 8;
                mbar_expect_tx(fb, STG1_BYTES);
                uint32_t a0 = tiles + s * STG1_BYTES;
                tma_load_3d(a0,            &tmA, kb * 64, m0, 0,  fb);
                tma_load_3d(a0 + OP_BYTES, &tmB, kb * 64, n0, zB, fb);
            }
        }
        return;
    }

    float acc[4][4][4];
#pragma unroll
    for (int mi = 0; mi < 4; mi++)
#pragma unroll
        for (int ni = 0; ni < 4; ni++)
#pragma unroll
            for (int q = 0; q < 4; q++) acc[mi][ni][q] = 0.f;

    const int aR = lane & 15;
    const int aC = (lane >> 4) << 4;
    const int bR = ((lane >> 4) << 3) + (lane & 7);
    const int bC = ((lane >> 3) & 1) << 4;

    for (int kb = 0; kb < KB; kb++) {
        const int s = kb % ST1;
        mbar_wait(full0 + s * 8, (uint32_t)((kb / ST1) & 1));

        const uint32_t A0 = tiles + s * STG1_BYTES;
        const uint32_t B0 = A0 + OP_BYTES;

#pragma unroll
        for (int ki = 0; ki < 4; ki++) {
            const int kc = ki * 32;
            uint32_t af[4][4], bhi[4][2];
#pragma unroll
            for (int mi = 0; mi < 4; mi++) {
                int r = warp_row * 64 + mi * 16 + aR;
                ldsm4(af[mi], swz(A0, r, kc + aC));
            }
#pragma unroll
            for (int g = 0; g < 2; g++) {
                int r = warp_col * 32 + g * 16 + bR;
                uint32_t t[4];
                ldsm4(t, swz(B0, r, kc + bC));
                bhi[2 * g][0] = t[0]; bhi[2 * g][1] = t[1];
                bhi[2 * g + 1][0] = t[2]; bhi[2 * g + 1][1] = t[3];
            }
            if (ki == 3) mbar_arrive(empty0 + s * 8);
#pragma unroll
            for (int mi = 0; mi < 4; mi++)
#pragma unroll
                for (int ni = 0; ni < 4; ni++)
                    mma_f16(acc[mi][ni], af[mi], bhi[ni]);
        }
    }

    const float* biasp = bias2 + zB * 1024;
    const float* gpp   = gposv + zB * 1024;

#pragma unroll
    for (int mi = 0; mi < 4; mi++) {
        int r = m0 + warp_row * 64 + mi * 16 + (lane >> 2);
        float pv = posv[r];
        float pv2 = posv[r + 8];
#pragma unroll
        for (int ni = 0; ni < 4; ni++) {
            int cc = n0 + warp_col * 32 + ni * 8 + (lane & 3) * 2;
            float b0v = biasp[cc], b1v = biasp[cc + 1];
            float g0 = gpp[cc], g1 = gpp[cc + 1];
            float2 v0 = { acc[mi][ni][0] + b0v + pv * g0,
                          acc[mi][ni][1] + b1v + pv * g1 };
            float2 v1 = { acc[mi][ni][2] + b0v + pv2 * g0,
                          acc[mi][ni][3] + b1v + pv2 * g1 };
            *(float2*)(C + (size_t)r * 1024 + cc) = v0;
            *(float2*)(C + (size_t)(r + 8) * 1024 + cc) = v1;
        }
    }
}

// ============================ 3-pass GEMM (A hi/lo, B hi/lo) ===============
// Writes fp16 output directly (Wcomb).
static constexpr int ST3 = 3;
static constexpr uint32_t STG3_BYTES = 4 * OP_BYTES;
static constexpr uint32_t SMEM3_DYN = CTRL_BYTES + ST3 * STG3_BYTES;

__global__ __launch_bounds__(256, 1) void gemm_mma3(
    const __grid_constant__ CUtensorMap tmAhi,
    const __grid_constant__ CUtensorMap tmAlo,
    const __grid_constant__ CUtensorMap tmBhi,
    const __grid_constant__ CUtensorMap tmBlo,
    __half* __restrict__ Cout, int KB)
{
    extern __shared__ __align__(1024) char smem[];
    const uint32_t sb = smem_u32(smem);
    const int tid = threadIdx.x;
    const int wid = tid >> 5, lane = tid & 31;
    const int warp_row = wid >> 2;
    const int warp_col = wid & 3;

    const uint32_t full0  = sb;
    const uint32_t empty0 = sb + 128;
    const uint32_t tiles  = sb + CTRL_BYTES;

    const int n0 = blockIdx.x * 128;
    const int aY = blockIdx.y * 128;
    const int aZ = blockIdx.z;
    const int m0 = blockIdx.z * 1024 + aY;

    if (tid == 0) {
        for (int s = 0; s < ST3; s++) {
            mbar_init(full0 + s * 8, 1);
            mbar_init(empty0 + s * 8, 256);
        }
        fence_async_shared();
    }
    __syncthreads();

    if (tid == 0) {
        for (int s = 0; s < ST3; s++) {
            uint32_t fb = full0 + s * 8;
            mbar_expect_tx(fb, STG3_BYTES);
            uint32_t a0 = tiles + s * STG3_BYTES;
            tma_load_3d(a0,                &tmAhi, s * 64, aY, aZ, fb);
            tma_load_3d(a0 + OP_BYTES,     &tmAlo, s * 64, aY, aZ, fb);
            tma_load_3d(a0 + 2 * OP_BYTES, &tmBhi, s * 64, n0, 0,  fb);
            tma_load_3d(a0 + 3 * OP_BYTES, &tmBlo, s * 64, n0, 0,  fb);
        }
    }

    float acc[4][4][4];
#pragma unroll
    for (int mi = 0; mi < 4; mi++)
#pragma unroll
        for (int ni = 0; ni < 4; ni++)
#pragma unroll
            for (int q = 0; q < 4; q++) acc[mi][ni][q] = 0.f;

    const int aR = lane & 15;
    const int aC = (lane >> 4) << 4;
    const int bR = ((lane >> 4) << 3) + (lane & 7);
    const int bC = ((lane >> 3) & 1) << 4;

    for (int kb = 0; kb < KB; kb++) {
        const int s = kb % ST3;
        const uint32_t ph = (uint32_t)((kb / ST3) & 1);
        mbar_wait(full0 + s * 8, ph);

        const uint32_t A0 = tiles + s * STG3_BYTES;
        const uint32_t B0 = A0 + 2 * OP_BYTES;

#pragma unroll
        for (int ki = 0; ki < 4; ki++) {
            const int kc = ki * 32;
            uint32_t ahi[4][4], alo[4][4], bhi[4][2], blo[4][2];
#pragma unroll
            for (int mi = 0; mi < 4; mi++) {
                int r = warp_row * 64 + mi * 16 + aR;
                uint32_t ad = swz(A0, r, kc + aC);
                ldsm4(ahi[mi], ad);
                ldsm4(alo[mi], ad + OP_BYTES);
            }
#pragma unroll
            for (int g = 0; g < 2; g++) {
                int r = warp_col * 32 + g * 16 + bR;
                uint32_t bd = swz(B0, r, kc + bC);
                uint32_t t[4];
                ldsm4(t, bd);
                bhi[2 * g][0] = t[0]; bhi[2 * g][1] = t[1];
                bhi[2 * g + 1][0] = t[2]; bhi[2 * g + 1][1] = t[3];
                ldsm4(t, bd + OP_BYTES);
                blo[2 * g][0] = t[0]; blo[2 * g][1] = t[1];
                blo[2 * g + 1][0] = t[2]; blo[2 * g + 1][1] = t[3];
            }
#pragma unroll
            for (int mi = 0; mi < 4; mi++)
#pragma unroll
                for (int ni = 0; ni < 4; ni++) {
                    mma_f16(acc[mi][ni], ahi[mi], bhi[ni]);
                    mma_f16(acc[mi][ni], ahi[mi], blo[ni]);
                    mma_f16(acc[mi][ni], alo[mi], bhi[ni]);
                }
        }

        mbar_arrive(empty0 + s * 8);

        if (tid == 0 && kb + ST3 < KB) {
            mbar_wait(empty0 + s * 8, ph);
            uint32_t fb = full0 + s * 8;
            mbar_expect_tx(fb, STG3_BYTES);
            uint32_t a0 = tiles + s * STG3_BYTES;
            int kx = (kb + ST3) * 64;
            tma_load_3d(a0,                &tmAhi, kx, aY, aZ, fb);
            tma_load_3d(a0 + OP_BYTES,     &tmAlo, kx, aY, aZ, fb);
            tma_load_3d(a0 + 2 * OP_BYTES, &tmBhi, kx, n0, 0,  fb);
            tma_load_3d(a0 + 3 * OP_BYTES, &tmBlo, kx, n0, 0,  fb);
        }
    }

#pragma unroll
    for (int mi = 0; mi < 4; mi++) {
        int r = m0 + warp_row * 64 + mi * 16 + (lane >> 2);
#pragma unroll
        for (int ni = 0; ni < 4; ni++) {
            int cc = n0 + warp_col * 32 + ni * 8 + (lane & 3) * 2;
            *(__half2*)(Cout + (size_t)r * 1024 + cc) =
                __half2(__float2half_rn(acc[mi][ni][0]),
                        __float2half_rn(acc[mi][ni][1]));
            *(__half2*)(Cout + (size_t)(r + 8) * 1024 + cc) =
                __half2(__float2half_rn(acc[mi][ni][2]),
                        __float2half_rn(acc[mi][ni][3]));
        }
    }
}

// ---------------------------------------------------------------------------
__global__ __launch_bounds__(256) void cvt16_kernel(
    const float* __restrict__ src, __half* __restrict__ dst, int n)
{
    int i = (blockIdx.x * 256 + threadIdx.x) * 8;
    if (i >= n) return;
    float4 v0 = *(const float4*)(src + i);
    float4 v1 = *(const float4*)(src + i + 4);
    __half2 h[4];
    h[0] = __floats2half2_rn(v0.x, v0.y);
    h[1] = __floats2half2_rn(v0.z, v0.w);
    h[2] = __floats2half2_rn(v1.x, v1.y);
    h[3] = __floats2half2_rn(v1.z, v1.w);
    *(uint4*)(dst + i) = *(uint4*)h;
}

__global__ __launch_bounds__(256) void tsplit16_kernel(
    const float* __restrict__ W, __half* __restrict__ hi, __half* __restrict__ lo)
{
    __shared__ float t[32][33];
    const int o0 = blockIdx.y * 32, i0 = blockIdx.x * 32;
    const int c = threadIdx.x & 31;
    const int r0 = threadIdx.x >> 5;
#pragma unroll
    for (int it = 0; it < 4; it++) {
        int r = r0 + it * 8;
        t[r][c] = W[(size_t)(o0 + r) * 1024 + i0 + c];
    }
    __syncthreads();
#pragma unroll
    for (int it = 0; it < 4; it++) {
        int r = r0 + it * 8;
        float v = t[c][r];
        __half h = __float2half_rn(v);
        size_t idx = (size_t)(i0 + r) * 1024 + o0 + c;
        hi[idx] = h;
        lo[idx] = __float2half_rn(v - __half2float(h));
    }
}

// ---------------------------------------------------------------------------
// p_attn core + edges fused. grid (32 bh, 8 s-split), block 256. Single V.
// ---------------------------------------------------------------------------
__global__ __launch_bounds__(256) void pa_core_mma(
    const __half* __restrict__ k16, const __half* __restrict__ vh16,
    const float* __restrict__ pos, float* __restrict__ pa)
{
    __shared__ __half Ks[32 * 136];
    __shared__ __half Vh[32 * 136];
    __shared__ float ps[32];

    const int bh = blockIdx.x;
    const int b = bh >> 3;
    const int sp = blockIdx.y;
    const int tid = threadIdx.x;
    const int wid = tid >> 5, lane = tid & 31;
    const int warp_row = wid >> 2;
    const int warp_col = wid & 3;

    const uint32_t ksb = smem_u32(Ks);
    const uint32_t vhb = smem_u32(Vh);

    const size_t gbase = ((size_t)bh * NS + sp * 1024) * NDK;
    const float* posb = pos + (size_t)b * NS + sp * 1024;

    float acc[4][4][4];
#pragma unroll
    for (int mi = 0; mi < 4; mi++)
#pragma unroll
        for (int ni = 0; ni < 4; ni++)
#pragma unroll
            for (int q = 0; q < 4; q++) acc[mi][ni][q] = 0.f;

    float eacc = 0.f;
    float p2 = 0.f;

    const int aRow = (lane & 7) | ((lane >> 4) << 3);
    const int aCol = ((lane >> 3) & 1) << 3;
    const int bRow = (lane & 7) | (((lane >> 3) & 1) << 3);
    const int bCol = ((lane >> 4) & 1) << 3;
    const int ecol = tid & 127;

    for (int s0 = 0; s0 < 1024; s0 += 32) {
#pragma unroll
        for (int it = 0; it < 2; it++) {
            int f = tid + it * 256;
            int row = f >> 4;
            int c8 = (f & 15) * 8;
            size_t ga = gbase + (size_t)(s0 + row) * NDK + c8;
            int so = row * 136 + c8;
            *(float4*)(Ks + so) = *(const float4*)(k16 + ga);
            *(float4*)(Vh + so) = *(const float4*)(vh16 + ga);
        }
        if (tid < 32) ps[tid] = posb[s0 + tid];
        __syncthreads();

#pragma unroll
        for (int ki = 0; ki < 2; ki++) {
            const int kio = ki * 16;
            uint32_t af[4][4], bhi[4][2];
#pragma unroll
            for (int mi = 0; mi < 4; mi++) {
                int mcol = warp_row * 64 + mi * 16 + aCol;
                ldsm4t(af[mi], ksb + (kio + aRow) * 272 + mcol * 2);
            }
#pragma unroll
            for (int g = 0; g < 2; g++) {
                int ec = warp_col * 32 + g * 16 + bCol;
                uint32_t t[4];
                ldsm4t(t, vhb + (kio + bRow) * 272 + ec * 2);
                bhi[2 * g][0] = t[0]; bhi[2 * g][1] = t[1];
                bhi[2 * g + 1][0] = t[2]; bhi[2 * g + 1][1] = t[3];
            }
#pragma unroll
            for (int mi = 0; mi < 4; mi++)
#pragma unroll
                for (int ni = 0; ni < 4; ni++)
                    mma_f16(acc[mi][ni], af[mi], bhi[ni]);
        }

        if (tid < 128) {
#pragma unroll 8
            for (int r = 0; r < 32; r++)
                eacc = fmaf(ps[r], __half2float(Vh[r * 136 + ecol]), eacc);
        } else {
#pragma unroll 8
            for (int r = 0; r < 32; r++)
                eacc = fmaf(ps[r], __half2float(Ks[r * 136 + ecol]), eacc);
        }
        if (wid == 0) { float pv = ps[lane]; p2 = fmaf(pv, pv, p2); }
        __syncthreads();
    }

    const float invS = 1.0f / (float)NS;
    float* pab = pa + (size_t)bh * NE * NE;
#pragma unroll
    for (int mi = 0; mi < 4; mi++) {
        int d0 = warp_row * 64 + mi * 16 + (lane >> 2);
#pragma unroll
        for (int ni = 0; ni < 4; ni++) {
            int e0 = warp_col * 32 + ni * 8 + (lane & 3) * 2;
            atomicAdd(&pab[(1 + d0) * NE + 1 + e0],     acc[mi][ni][0] * invS);
            atomicAdd(&pab[(1 + d0) * NE + 2 + e0],     acc[mi][ni][1] * invS);
            atomicAdd(&pab[(1 + d0 + 8) * NE + 1 + e0], acc[mi][ni][2] * invS);
            atomicAdd(&pab[(1 + d0 + 8) * NE + 2 + e0], acc[mi][ni][3] * invS);
        }
    }
    if (tid < 128) atomicAdd(&pab[0 * NE + 1 + ecol], eacc * invS);
    else           atomicAdd(&pab[(1 + ecol) * NE + 0], eacc * invS);
    if (wid == 0) {
#pragma unroll
        for (int o = 16; o > 0; o >>= 1)
            p2 += __shfl_xor_sync(0xffffffffu, p2, o);
        if (lane == 0) atomicAdd(&pab[0], p2 * invS);
    }
}

// ---------------------------------------------------------------------------
// Gd (fp16 hi/lo) = pa @ Wfc_h^T (head cols); d==0 col -> gpos (atomic sum).
// ---------------------------------------------------------------------------
__global__ __launch_bounds__(256) void g_kernel(
    const float* __restrict__ pa, const float* __restrict__ Wfc,
    __half* __restrict__ gdh, __half* __restrict__ gdl, float* __restrict__ gpos)
{
    extern __shared__ float sm[];
    float* pas = sm;
    float* ws  = sm + 129 * 132;

    const int nt = blockIdx.x, h = blockIdx.y, b = blockIdx.z;
    const int tid = threadIdx.x;
    const int n0 = nt * 128;

    const float* pab = pa + ((size_t)(b * NH + h)) * NE * NE;
    for (int i = tid; i < NE * NE; i += 256) {
        int d = i / NE, e = i - d * NE;
        pas[d * 132 + e] = pab[i];
    }
    for (int i = tid; i < 128 * NE; i += 256) {
        int n = i / NE, e = i - n * NE;
        ws[n * 132 + e] = Wfc[(size_t)(n0 + n) * KFC + h * NE + e];
    }
    __syncthreads();

    for (int o = tid; o < 128 * NE; o += 256) {
        int n = o / NE, d = o - n * NE;
        const float* pr = &pas[d * 132];
        const float* wr = &ws[n * 132];
        float acc = 0.f;
#pragma unroll 8
        for (int e4 = 0; e4 < 128; e4 += 4) {
            float4 a = *(const float4*)(pr + e4);
            float4 w = *(const float4*)(wr + e4);
            acc = fmaf(a.x, w.x, acc);
            acc = fmaf(a.y, w.y, acc);
            acc = fmaf(a.z, w.z, acc);
            acc = fmaf(a.w, w.w, acc);
        }
        acc = fmaf(pr[128], wr[128], acc);
        if (d == 0) {
            atomicAdd(&gpos[b * 1024 + n0 + n], acc);
        } else {
            size_t idx = ((size_t)b * 1024 + n0 + n) * 1024 + h * NDK + d - 1;
            __half hh = __float2half_rn(acc);
            gdh[idx] = hh;
            gdl[idx] = __float2half_rn(acc - __half2float(hh));
        }
    }
}

// ---------------------------------------------------------------------------
// bias2[b][n] = bfc[n] + sum_o bq[o] * (gdh+gdl)[b][n][o]
// ---------------------------------------------------------------------------
__global__ __launch_bounds__(256) void bias2_kernel(
    const __half* __restrict__ gdh, const __half* __restrict__ gdl,
    const float* __restrict__ bq, const float* __restrict__ bfc,
    float* __restrict__ bias2)
{
    const int n = blockIdx.x, b = blockIdx.y;
    const int tid = threadIdx.x;
    size_t base = ((size_t)b * 1024 + n) * 1024;
    float acc = 0.f;
    for (int o = tid; o < 1024; o += 256) {
        float v = __half2float(gdh[base + o]) + __half2float(gdl[base + o]);
        acc = fmaf(bq[o], v, acc);
    }
    __shared__ float red[256];
    red[tid] = acc;
    __syncthreads();
    for (int o = 128; o > 0; o >>= 1) {
        if (tid < o) red[tid] += red[tid + o];
        __syncthreads();
    }
    if (tid == 0) bias2[b * 1024 + n] = red[0] + bfc[n];
}

// ============================ host side ====================================
typedef CUresult (*EncodeFn)(CUtensorMap*, CUtensorMapDataType, cuuint32_t, void*,
                             const cuuint64_t*, const cuuint64_t*, const cuuint32_t*,
                             const cuuint32_t*, CUtensorMapInterleave, CUtensorMapSwizzle,
                             CUtensorMapL2promotion, CUtensorMapFloatOOBfill);

static EncodeFn get_encode() {
    static EncodeFn fn = nullptr;
    if (!fn) {
        void* p = nullptr;
        cudaDriverEntryPointQueryResult st;
        cudaGetDriverEntryPoint("cuTensorMapEncodeTiled", &p, cudaEnableDefault, &st);
        fn = (EncodeFn)p;
    }
    return fn;
}

static void encode_f16(CUtensorMap* m, const void* base,
                       uint64_t kdim, uint64_t rows, uint64_t nz) {
    cuuint64_t dims[3]    = { kdim, rows, nz };
    cuuint64_t strides[2] = { kdim * 2, rows * kdim * 2 };
    cuuint32_t box[3]     = { 64, 128, 1 };
    cuuint32_t est[3]     = { 1, 1, 1 };
    get_encode()(m, CU_TENSOR_MAP_DATA_TYPE_FLOAT16, 3, (void*)base,
                 dims, strides, box, est,
                 CU_TENSOR_MAP_INTERLEAVE_NONE, CU_TENSOR_MAP_SWIZZLE_128B,
                 CU_TENSOR_MAP_L2_PROMOTION_L2_128B, CU_TENSOR_MAP_FLOAT_OOB_FILL_NONE);
}

extern "C" void kernel_launch(void* const* d_in, const int* in_sizes, int n_in,
                              void* d_out, int out_size)
{
    (void)in_sizes; (void)n_in; (void)out_size;
    const float* query = (const float*)d_in[0];
    const float* key   = (const float*)d_in[1];
    const float* value = (const float*)d_in[2];
    const float* pos   = (const float*)d_in[3];
    const float* Wq    = (const float*)d_in[4];
    const float* bq    = (const float*)d_in[5];
    const float* Wk    = (const float*)d_in[6];
    const float* bk    = (const float*)d_in[7];
    const float* Wv    = (const float*)d_in[8];
    const float* bv    = (const float*)d_in[9];
    const float* gK    = (const float*)d_in[10];
    const float* betaK = (const float*)d_in[11];
    const float* gV    = (const float*)d_in[12];
    const float* betaV = (const float*)d_in[13];
    const float* Wfc   = (const float*)d_in[14];
    const float* bfc   = (const float*)d_in[15];
    float* out = (float*)d_out;

    float *pa, *gpos, *bias2;
    __half *a16, *c16, *bh16, *bl16, *k16, *vh16, *wc16;
    cudaGetSymbolAddress((void**)&pa, g_pa);
    cudaGetSymbolAddress((void**)&gpos, g_gpos);
    cudaGetSymbolAddress((void**)&bias2, g_bias2);
    cudaGetSymbolAddress((void**)&a16, g_a16);
    cudaGetSymbolAddress((void**)&c16, g_c16);
    cudaGetSymbolAddress((void**)&bh16, g_bh16);
    cudaGetSymbolAddress((void**)&bl16, g_bl16);
    cudaGetSymbolAddress((void**)&k16, g_k16);
    cudaGetSymbolAddress((void**)&vh16, g_vh16);
    cudaGetSymbolAddress((void**)&wc16, g_wc16);

    cudaFuncSetAttribute(gemm_kv, cudaFuncAttributeMaxDynamicSharedMemorySize,
                         (int)SMEM1_DYN);
    cudaFuncSetAttribute(gemm_out, cudaFuncAttributeMaxDynamicSharedMemorySize,
                         (int)SMEM1_DYN);
    cudaFuncSetAttribute(gemm_mma3, cudaFuncAttributeMaxDynamicSharedMemorySize,
                         (int)SMEM3_DYN);
    cudaFuncSetAttribute(g_kernel, cudaFuncAttributeMaxDynamicSharedMemorySize,
                         (129 + 128) * 132 * (int)sizeof(float));

    CUtensorMap tAK, tAV, tBkv, tGh, tGl, tWqh, tWql, tAq, tWc;
    encode_f16(&tAK, a16, 1024, 32768, 1);
    encode_f16(&tAV, c16, 1024, 32768, 1);
    encode_f16(&tBkv, bh16, 1024, 1024, 2);          // z: 0=Wk, 1=Wv
    encode_f16(&tGh,  a16,           1024, 1024, 4); // Gd hi (fp16)
    encode_f16(&tGl,  a16 + 4194304, 1024, 1024, 4); // Gd lo
    encode_f16(&tWqh, bh16, 1024, 1024, 1);
    encode_f16(&tWql, bl16, 1024, 1024, 1);
    encode_f16(&tAq,  a16,  1024, 32768, 1);
    encode_f16(&tWc,  wc16, 1024, 1024, 4);          // Wcomb fp16

    const int NA = 33554432, NW = 1048576;

    // Inputs to fp16
    cvt16_kernel<<<NA / 2048, 256>>>(key, a16, NA);
    cvt16_kernel<<<NA / 2048, 256>>>(value, c16, NA);
    cvt16_kernel<<<NW / 2048, 256>>>(Wk, bh16, NW);
    cvt16_kernel<<<NW / 2048, 256>>>(Wv, bh16 + NW, NW);

    // K+V projection with fused per-head LN (both single fp16 out)
    gemm_kv<<<dim3(8, 256, 2), 288, SMEM1_DYN>>>(
        tAK, tAV, tBkv, bk, bv, gK, betaK, gV, betaV, k16, vh16);

    // p_attn = Kc^T Vc / S  (core + edges fused)
    cudaMemsetAsync(pa, 0, (size_t)32 * NE * NE * sizeof(float));
    pa_core_mma<<<dim3(32, 8), 256>>>(k16, vh16, pos, pa);

    // Gd (fp16 hi/lo directly into a16) + gpos
    cudaMemsetAsync(gpos, 0, 4096 * sizeof(float));
    g_kernel<<<dim3(8, NH, NB), 256, (129 + 128) * 132 * sizeof(float)>>>(
        pa, Wfc, a16, a16 + 4194304, gpos);

    // bias2 = bfc + bq @ (Gd hi+lo)^T
    bias2_kernel<<<dim3(1024, 4), 256>>>(a16, a16 + 4194304, bq, bfc, bias2);

    // Wq^T hi/lo
    tsplit16_kernel<<<dim3(32, 32), 256>>>(Wq, bh16, bl16);

    // Wcomb[b] = Gd[b] @ Wq (3-pass) -> fp16 directly into wc16
    gemm_mma3<<<dim3(8, 8, 4), 256, SMEM3_DYN>>>(tGh, tGl, tWqh, tWql, wc16, 16);

    // query -> fp16 (a16 free after gemm_mma3 consumed Gd)
    cvt16_kernel<<<NA / 2048, 256>>>(query, a16, NA);

    // out[b] = query[b] @ Wcomb[b]^T + pos (x) gpos[b] + bias2[b]
    gemm_out<<<dim3(8, 64, 4), 288, SMEM1_DYN>>>(tAq, tWc, bias2, pos, gpos, out);
}

// round 12
// speedup vs baseline: 7.9441x; 1.0373x over previous
#include <cuda_runtime.h>
#include <cuda.h>
#include <cuda_fp16.h>
#include <cstdint>
#include <cstddef>

// Problem constants
#define NB 4
#define NS 8192
#define ND 1024
#define NH 8
#define NDK 128
#define NE 129
#define NM 32768
#define KFC 1032

// ---------------- scratch (static device globals; no allocations) ----------
static __device__ float g_pa[532512];       // (32, 129, 129) p_attn
static __device__ float g_gpos[4096];       // (B, 1024) pos-column of G (sum over h)
static __device__ float g_bias2[4096];      // (B, 1024) folded bias
static __device__ __half g_a16[33554432];   // key fp16 / Gd hi+lo / query fp16
static __device__ __half g_c16[33554432];   // value fp16
static __device__ __half g_bh16[4227072];   // B hi (Wk+Wv / Wq hi)
static __device__ __half g_bl16[4227072];   // B lo (Wq lo for gemm3)
static __device__ __half g_k16[33554432];   // LN'd K, head-major (bh,s,d) fp16
static __device__ __half g_vh16[33554432];  // LN'd V, head-major fp16
static __device__ __half g_wc16[4194304];   // Wcomb fp16 (B,1024,1024)

// ============================ PTX helpers ==================================
__device__ __forceinline__ uint32_t smem_u32(const void* p) {
    uint32_t a;
    asm("{ .reg .u64 t; cvta.to.shared.u64 t, %1; cvt.u32.u64 %0, t; }"
        : "=r"(a) : "l"(p));
    return a;
}
__device__ __forceinline__ void mbar_init(uint32_t mbar, uint32_t cnt) {
    asm volatile("mbarrier.init.shared.b64 [%0], %1;" :: "r"(mbar), "r"(cnt) : "memory");
}
__device__ __forceinline__ void mbar_expect_tx(uint32_t mbar, uint32_t bytes) {
    asm volatile("mbarrier.arrive.expect_tx.shared.b64 _, [%0], %1;"
                 :: "r"(mbar), "r"(bytes) : "memory");
}
__device__ __forceinline__ void mbar_arrive(uint32_t mbar) {
    asm volatile("mbarrier.arrive.shared.b64 _, [%0];" :: "r"(mbar) : "memory");
}
__device__ __forceinline__ void mbar_wait(uint32_t mbar, uint32_t parity) {
    asm volatile(
        "{\n\t.reg .pred P;\n\t"
        "BWL_%=:\n\t"
        "mbarrier.try_wait.parity.acquire.cta.shared::cta.b64 P, [%0], %1, 0x989680;\n\t"
        "@P bra.uni BWD_%=;\n\t"
        "bra.uni BWL_%=;\n\t"
        "BWD_%=:\n\t}"
        :: "r"(mbar), "r"(parity) : "memory");
}
__device__ __forceinline__ void tma_load_3d(uint32_t dst, const CUtensorMap* tm,
                                            int x, int y, int z, uint32_t mbar) {
    asm volatile(
        "cp.async.bulk.tensor.3d.shared::cta.global.tile.mbarrier::complete_tx::bytes "
        "[%0], [%1, {%2, %3, %4}], [%5];"
        :: "r"(dst), "l"(tm), "r"(x), "r"(y), "r"(z), "r"(mbar) : "memory");
}
__device__ __forceinline__ void fence_async_shared() {
    asm volatile("fence.proxy.async.shared::cta;" ::: "memory");
}
__device__ __forceinline__ void ldsm4(uint32_t* r, uint32_t addr) {
    asm volatile("ldmatrix.sync.aligned.m8n8.x4.shared.b16 {%0,%1,%2,%3}, [%4];"
                 : "=r"(r[0]), "=r"(r[1]), "=r"(r[2]), "=r"(r[3]) : "r"(addr));
}
__device__ __forceinline__ void ldsm4t(uint32_t* r, uint32_t addr) {
    asm volatile("ldmatrix.sync.aligned.m8n8.x4.trans.shared.b16 {%0,%1,%2,%3}, [%4];"
                 : "=r"(r[0]), "=r"(r[1]), "=r"(r[2]), "=r"(r[3]) : "r"(addr));
}
__device__ __forceinline__ void mma_f16(float* c, const uint32_t* a, const uint32_t* b) {
    asm volatile(
        "mma.sync.aligned.m16n8k16.row.col.f32.f16.f16.f32 "
        "{%0,%1,%2,%3}, {%4,%5,%6,%7}, {%8,%9}, {%0,%1,%2,%3};"
        : "+f"(c[0]), "+f"(c[1]), "+f"(c[2]), "+f"(c[3])
        : "r"(a[0]), "r"(a[1]), "r"(a[2]), "r"(a[3]), "r"(b[0]), "r"(b[1]));
}
__device__ __forceinline__ uint32_t swz(uint32_t base, int r, int c) {
    return base + r * 128 + (c ^ ((r & 7) << 4));
}

// ============================ GEMM constants ===============================
// Wide tiles: BM=128, BN=256; A tile 16KB, B tile 32KB per stage.
static constexpr uint32_t OPA_BYTES = 128 * 64 * 2;   // 16 KB
static constexpr uint32_t OPB_BYTES = 256 * 64 * 2;   // 32 KB
static constexpr uint32_t STG_BYTES = OPA_BYTES + OPB_BYTES;  // 48 KB
static constexpr uint32_t CTRL_BYTES = 1024;
static constexpr int ST = 4;
static constexpr uint32_t STAGES_END = CTRL_BYTES + ST * STG_BYTES;   // 197632
// gemm_kv adds LN scratch
static constexpr uint32_t SMEM_KV = STAGES_END + 16384 + 2048;        // 216064
static constexpr uint32_t SMEM_OUT = STAGES_END;                      // 197632

// ============================ K/V projection + fused LN ====================
// grid (4 nblk, 256 m-tiles, 2 kv), 288 threads (8 compute + producer warp).
// Each 256-wide N tile covers heads {2*nblk, 2*nblk+1}.
__global__ __launch_bounds__(288, 1) void gemm_kv(
    const __grid_constant__ CUtensorMap tmAK,
    const __grid_constant__ CUtensorMap tmAV,
    const __grid_constant__ CUtensorMap tmB,    // batched (z: 0=Wk, 1=Wv)
    const float* __restrict__ bk, const float* __restrict__ bv,
    const float* __restrict__ gK, const float* __restrict__ betaK,
    const float* __restrict__ gV, const float* __restrict__ betaV,
    __half* __restrict__ k16, __half* __restrict__ vh16)
{
    extern __shared__ __align__(1024) char smem[];
    const uint32_t sb = smem_u32(smem);
    const int tid = threadIdx.x;
    const int wid = tid >> 5, lane = tid & 31;
    const int warp_row = wid >> 2;     // 0..1 (64 rows each)
    const int warp_col = wid & 3;      // 0..3 (64 cols each)
    const bool producer = (wid == 8);

    const uint32_t full0  = sb;
    const uint32_t empty0 = sb + 128;
    const uint32_t tiles  = sb + CTRL_BYTES;

    const int nblk = blockIdx.x;
    const int n0g = nblk * 256;
    const int m0 = blockIdx.y * 128;
    const int zKV = blockIdx.z;
    const CUtensorMap* tmA = zKV ? &tmAV : &tmAK;
    const int KB = 16;

    if (tid == 0) {
        for (int s = 0; s < ST; s++) {
            mbar_init(full0 + s * 8, 1);
            mbar_init(empty0 + s * 8, 256);
        }
        fence_async_shared();
    }
    __syncthreads();

    float acc[4][8][4];
#pragma unroll
    for (int mi = 0; mi < 4; mi++)
#pragma unroll
        for (int ni = 0; ni < 8; ni++)
#pragma unroll
            for (int q = 0; q < 4; q++) acc[mi][ni][q] = 0.f;

    if (producer) {
        if (lane == 0) {
            for (int s = 0; s < ST; s++) {
                uint32_t fb = full0 + s * 8;
                mbar_expect_tx(fb, STG_BYTES);
                uint32_t a0 = tiles + s * STG_BYTES;
                tma_load_3d(a0,             tmA,  s * 64, m0,  0,   fb);
                tma_load_3d(a0 + OPA_BYTES, &tmB, s * 64, n0g, zKV, fb);
            }
            for (int kb = ST; kb < KB; kb++) {
                int s = kb % ST;
                mbar_wait(empty0 + s * 8, (uint32_t)(((kb - ST) / ST) & 1));
                uint32_t fb = full0 + s * 8;
                mbar_expect_tx(fb, STG_BYTES);
                uint32_t a0 = tiles + s * STG_BYTES;
                tma_load_3d(a0,             tmA,  kb * 64, m0,  0,   fb);
                tma_load_3d(a0 + OPA_BYTES, &tmB, kb * 64, n0g, zKV, fb);
            }
        }
    } else {
        const int aR = lane & 15;
        const int aC = (lane >> 4) << 4;
        const int bR = ((lane >> 4) << 3) + (lane & 7);
        const int bC = ((lane >> 3) & 1) << 4;

        for (int kb = 0; kb < KB; kb++) {
            const int s = kb % ST;
            mbar_wait(full0 + s * 8, (uint32_t)((kb / ST) & 1));

            const uint32_t A0 = tiles + s * STG_BYTES;
            const uint32_t B0 = A0 + OPA_BYTES;

#pragma unroll
            for (int ki = 0; ki < 4; ki++) {
                const int kc = ki * 32;
                uint32_t af[4][4], bhi[8][2];
#pragma unroll
                for (int mi = 0; mi < 4; mi++) {
                    int r = warp_row * 64 + mi * 16 + aR;
                    ldsm4(af[mi], swz(A0, r, kc + aC));
                }
#pragma unroll
                for (int g = 0; g < 4; g++) {
                    int r = warp_col * 64 + g * 16 + bR;
                    uint32_t tr[4];
                    ldsm4(tr, swz(B0, r, kc + bC));
                    bhi[2 * g][0] = tr[0]; bhi[2 * g][1] = tr[1];
                    bhi[2 * g + 1][0] = tr[2]; bhi[2 * g + 1][1] = tr[3];
                }
                if (ki == 3) mbar_arrive(empty0 + s * 8);
#pragma unroll
                for (int mi = 0; mi < 4; mi++)
#pragma unroll
                    for (int ni = 0; ni < 8; ni++)
                        mma_f16(acc[mi][ni], af[mi], bhi[ni]);
            }
        }
    }

    // ---- fused LN epilogue (all 288 threads in __syncthreads) ----
    __syncthreads();

    float2* part  = (float2*)(smem + STAGES_END);           // [128][16]
    float2* stats = (float2*)(smem + STAGES_END + 16384);   // [128][2]

    const float* biasp = zKV ? bv : bk;
    const float* gsel  = zKV ? gV : gK;
    const float* besel = zKV ? betaV : betaK;
    __half* outp = zKV ? vh16 : k16;
    const int hh = warp_col >> 1;            // warp-uniform head within pair

    if (!producer) {
        const int slot = warp_col * 4 + (lane & 3);   // head = slot>>3
#pragma unroll
        for (int mi = 0; mi < 4; mi++) {
#pragma unroll
            for (int ni = 0; ni < 8; ni++) {
                int col = warp_col * 64 + ni * 8 + (lane & 3) * 2;
                float b0v = biasp[n0g + col], b1v = biasp[n0g + col + 1];
                acc[mi][ni][0] += b0v; acc[mi][ni][1] += b1v;
                acc[mi][ni][2] += b0v; acc[mi][ni][3] += b1v;
            }
#pragma unroll
            for (int half = 0; half < 2; half++) {
                float s = 0.f, sq = 0.f;
#pragma unroll
                for (int ni = 0; ni < 8; ni++) {
                    float v0 = acc[mi][ni][half * 2 + 0];
                    float v1 = acc[mi][ni][half * 2 + 1];
                    s += v0 + v1;
                    sq += v0 * v0 + v1 * v1;
                }
                int r = warp_row * 64 + mi * 16 + (lane >> 2) + half * 8;
                part[r * 16 + slot] = make_float2(s, sq);
            }
        }
    }
    __syncthreads();
    if (tid < 256) {
        int r = tid >> 1, hsel = tid & 1;   // 128 rows x 2 heads
        float s = 0.f, sq = 0.f;
#pragma unroll
        for (int i = 0; i < 8; i++) {
            float2 p = part[r * 16 + hsel * 8 + i];
            s += p.x; sq += p.y;
        }
        float mean = s * (1.f / 128.f);
        float var  = sq * (1.f / 128.f) - mean * mean;
        stats[r * 2 + hsel] = make_float2(mean, rsqrtf(var + 1e-5f));
    }
    __syncthreads();

    if (!producer) {
#pragma unroll
        for (int mi = 0; mi < 4; mi++) {
#pragma unroll
            for (int half = 0; half < 2; half++) {
                int r = warp_row * 64 + mi * 16 + (lane >> 2) + half * 8;
                float2 st = stats[r * 2 + hh];
                int m = m0 + r;
                int b = m >> 13, sIdx = m & 8191;
                size_t base = (((size_t)(b * NH + nblk * 2 + hh)) * NS + sIdx) * NDK;
#pragma unroll
                for (int ni = 0; ni < 8; ni++) {
                    int col = warp_col * 64 + ni * 8 + (lane & 3) * 2;
                    int c128 = col & 127;
                    float gg0 = gsel[n0g + col],  gg1 = gsel[n0g + col + 1];
                    float be0 = besel[n0g + col], be1 = besel[n0g + col + 1];
                    float y0 = (acc[mi][ni][half * 2 + 0] - st.x) * st.y * gg0 + be0;
                    float y1 = (acc[mi][ni][half * 2 + 1] - st.x) * st.y * gg1 + be1;
                    *(__half2*)(outp + base + c128) =
                        __half2(__float2half_rn(y0), __float2half_rn(y1));
                }
            }
        }
    }
}

// ============================ final GEMM (BN=256) ==========================
// out[b] = query[b] @ Wcomb[b]^T + pos (x) gpos[b] + bias2[b]
// grid (4 nblk, 64 mblk, 4 b), 288 threads.
__global__ __launch_bounds__(288, 1) void gemm_out(
    const __grid_constant__ CUtensorMap tmA,
    const __grid_constant__ CUtensorMap tmB,
    const float* __restrict__ bias2,
    const float* __restrict__ posv,
    const float* __restrict__ gposv,
    float* __restrict__ C)
{
    extern __shared__ __align__(1024) char smem[];
    const uint32_t sb = smem_u32(smem);
    const int tid = threadIdx.x;
    const int wid = tid >> 5, lane = tid & 31;
    const int warp_row = wid >> 2;
    const int warp_col = wid & 3;
    const bool producer = (wid == 8);

    const uint32_t full0  = sb;
    const uint32_t empty0 = sb + 128;
    const uint32_t tiles  = sb + CTRL_BYTES;

    const int n0 = blockIdx.x * 256;
    const int zB = blockIdx.z;
    const int m0 = zB * 8192 + blockIdx.y * 128;
    const int KB = 16;

    if (tid == 0) {
        for (int s = 0; s < ST; s++) {
            mbar_init(full0 + s * 8, 1);
            mbar_init(empty0 + s * 8, 256);
        }
        fence_async_shared();
    }
    __syncthreads();

    if (producer) {
        if (lane == 0) {
            for (int s = 0; s < ST; s++) {
                uint32_t fb = full0 + s * 8;
                mbar_expect_tx(fb, STG_BYTES);
                uint32_t a0 = tiles + s * STG_BYTES;
                tma_load_3d(a0,             &tmA, s * 64, m0, 0,  fb);
                tma_load_3d(a0 + OPA_BYTES, &tmB, s * 64, n0, zB, fb);
            }
            for (int kb = ST; kb < KB; kb++) {
                int s = kb % ST;
                mbar_wait(empty0 + s * 8, (uint32_t)(((kb - ST) / ST) & 1));
                uint32_t fb = full0 + s * 8;
                mbar_expect_tx(fb, STG_BYTES);
                uint32_t a0 = tiles + s * STG_BYTES;
                tma_load_3d(a0,             &tmA, kb * 64, m0, 0,  fb);
                tma_load_3d(a0 + OPA_BYTES, &tmB, kb * 64, n0, zB, fb);
            }
        }
        return;
    }

    float acc[4][8][4];
#pragma unroll
    for (int mi = 0; mi < 4; mi++)
#pragma unroll
        for (int ni = 0; ni < 8; ni++)
#pragma unroll
            for (int q = 0; q < 4; q++) acc[mi][ni][q] = 0.f;

    const int aR = lane & 15;
    const int aC = (lane >> 4) << 4;
    const int bR = ((lane >> 4) << 3) + (lane & 7);
    const int bC = ((lane >> 3) & 1) << 4;

    for (int kb = 0; kb < KB; kb++) {
        const int s = kb % ST;
        mbar_wait(full0 + s * 8, (uint32_t)((kb / ST) & 1));

        const uint32_t A0 = tiles + s * STG_BYTES;
        const uint32_t B0 = A0 + OPA_BYTES;

#pragma unroll
        for (int ki = 0; ki < 4; ki++) {
            const int kc = ki * 32;
            uint32_t af[4][4], bhi[8][2];
#pragma unroll
            for (int mi = 0; mi < 4; mi++) {
                int r = warp_row * 64 + mi * 16 + aR;
                ldsm4(af[mi], swz(A0, r, kc + aC));
            }
#pragma unroll
            for (int g = 0; g < 4; g++) {
                int r = warp_col * 64 + g * 16 + bR;
                uint32_t tr[4];
                ldsm4(tr, swz(B0, r, kc + bC));
                bhi[2 * g][0] = tr[0]; bhi[2 * g][1] = tr[1];
                bhi[2 * g + 1][0] = tr[2]; bhi[2 * g + 1][1] = tr[3];
            }
            if (ki == 3) mbar_arrive(empty0 + s * 8);
#pragma unroll
            for (int mi = 0; mi < 4; mi++)
#pragma unroll
                for (int ni = 0; ni < 8; ni++)
                    mma_f16(acc[mi][ni], af[mi], bhi[ni]);
        }
    }

    const float* biasp = bias2 + zB * 1024;
    const float* gpp   = gposv + zB * 1024;

#pragma unroll
    for (int mi = 0; mi < 4; mi++) {
        int r = m0 + warp_row * 64 + mi * 16 + (lane >> 2);
        float pv = posv[r];
        float pv2 = posv[r + 8];
#pragma unroll
        for (int ni = 0; ni < 8; ni++) {
            int cc = n0 + warp_col * 64 + ni * 8 + (lane & 3) * 2;
            float b0v = biasp[cc], b1v = biasp[cc + 1];
            float g0 = gpp[cc], g1 = gpp[cc + 1];
            float2 v0 = { acc[mi][ni][0] + b0v + pv * g0,
                          acc[mi][ni][1] + b1v + pv * g1 };
            float2 v1 = { acc[mi][ni][2] + b0v + pv2 * g0,
                          acc[mi][ni][3] + b1v + pv2 * g1 };
            *(float2*)(C + (size_t)r * 1024 + cc) = v0;
            *(float2*)(C + (size_t)(r + 8) * 1024 + cc) = v1;
        }
    }
}

// ============================ 3-pass GEMM (A hi/lo, B hi/lo) ===============
static constexpr int ST3 = 3;
static constexpr uint32_t OP_BYTES = 128 * 64 * 2;
static constexpr uint32_t STG3_BYTES = 4 * OP_BYTES;
static constexpr uint32_t SMEM3_DYN = CTRL_BYTES + ST3 * STG3_BYTES;

__global__ __launch_bounds__(256, 1) void gemm_mma3(
    const __grid_constant__ CUtensorMap tmAhi,
    const __grid_constant__ CUtensorMap tmAlo,
    const __grid_constant__ CUtensorMap tmBhi,
    const __grid_constant__ CUtensorMap tmBlo,
    __half* __restrict__ Cout, int KB)
{
    extern __shared__ __align__(1024) char smem[];
    const uint32_t sb = smem_u32(smem);
    const int tid = threadIdx.x;
    const int wid = tid >> 5, lane = tid & 31;
    const int warp_row = wid >> 2;
    const int warp_col = wid & 3;

    const uint32_t full0  = sb;
    const uint32_t empty0 = sb + 128;
    const uint32_t tiles  = sb + CTRL_BYTES;

    const int n0 = blockIdx.x * 128;
    const int aY = blockIdx.y * 128;
    const int aZ = blockIdx.z;
    const int m0 = blockIdx.z * 1024 + aY;

    if (tid == 0) {
        for (int s = 0; s < ST3; s++) {
            mbar_init(full0 + s * 8, 1);
            mbar_init(empty0 + s * 8, 256);
        }
        fence_async_shared();
    }
    __syncthreads();

    if (tid == 0) {
        for (int s = 0; s < ST3; s++) {
            uint32_t fb = full0 + s * 8;
            mbar_expect_tx(fb, STG3_BYTES);
            uint32_t a0 = tiles + s * STG3_BYTES;
            tma_load_3d(a0,                &tmAhi, s * 64, aY, aZ, fb);
            tma_load_3d(a0 + OP_BYTES,     &tmAlo, s * 64, aY, aZ, fb);
            tma_load_3d(a0 + 2 * OP_BYTES, &tmBhi, s * 64, n0, 0,  fb);
            tma_load_3d(a0 + 3 * OP_BYTES, &tmBlo, s * 64, n0, 0,  fb);
        }
    }

    float acc[4][4][4];
#pragma unroll
    for (int mi = 0; mi < 4; mi++)
#pragma unroll
        for (int ni = 0; ni < 4; ni++)
#pragma unroll
            for (int q = 0; q < 4; q++) acc[mi][ni][q] = 0.f;

    const int aR = lane & 15;
    const int aC = (lane >> 4) << 4;
    const int bR = ((lane >> 4) << 3) + (lane & 7);
    const int bC = ((lane >> 3) & 1) << 4;

    for (int kb = 0; kb < KB; kb++) {
        const int s = kb % ST3;
        const uint32_t ph = (uint32_t)((kb / ST3) & 1);
        mbar_wait(full0 + s * 8, ph);

        const uint32_t A0 = tiles + s * STG3_BYTES;
        const uint32_t B0 = A0 + 2 * OP_BYTES;

#pragma unroll
        for (int ki = 0; ki < 4; ki++) {
            const int kc = ki * 32;
            uint32_t ahi[4][4], alo[4][4], bhi[4][2], blo[4][2];
#pragma unroll
            for (int mi = 0; mi < 4; mi++) {
                int r = warp_row * 64 + mi * 16 + aR;
                uint32_t ad = swz(A0, r, kc + aC);
                ldsm4(ahi[mi], ad);
                ldsm4(alo[mi], ad + OP_BYTES);
            }
#pragma unroll
            for (int g = 0; g < 2; g++) {
                int r = warp_col * 32 + g * 16 + bR;
                uint32_t bd = swz(B0, r, kc + bC);
                uint32_t tr[4];
                ldsm4(tr, bd);
                bhi[2 * g][0] = tr[0]; bhi[2 * g][1] = tr[1];
                bhi[2 * g + 1][0] = tr[2]; bhi[2 * g + 1][1] = tr[3];
                ldsm4(tr, bd + OP_BYTES);
                blo[2 * g][0] = tr[0]; blo[2 * g][1] = tr[1];
                blo[2 * g + 1][0] = tr[2]; blo[2 * g + 1][1] = tr[3];
            }
#pragma unroll
            for (int mi = 0; mi < 4; mi++)
#pragma unroll
                for (int ni = 0; ni < 4; ni++) {
                    mma_f16(acc[mi][ni], ahi[mi], bhi[ni]);
                    mma_f16(acc[mi][ni], ahi[mi], blo[ni]);
                    mma_f16(acc[mi][ni], alo[mi], bhi[ni]);
                }
        }

        mbar_arrive(empty0 + s * 8);

        if (tid == 0 && kb + ST3 < KB) {
            mbar_wait(empty0 + s * 8, ph);
            uint32_t fb = full0 + s * 8;
            mbar_expect_tx(fb, STG3_BYTES);
            uint32_t a0 = tiles + s * STG3_BYTES;
            int kx = (kb + ST3) * 64;
            tma_load_3d(a0,                &tmAhi, kx, aY, aZ, fb);
            tma_load_3d(a0 + OP_BYTES,     &tmAlo, kx, aY, aZ, fb);
            tma_load_3d(a0 + 2 * OP_BYTES, &tmBhi, kx, n0, 0,  fb);
            tma_load_3d(a0 + 3 * OP_BYTES, &tmBlo, kx, n0, 0,  fb);
        }
    }

#pragma unroll
    for (int mi = 0; mi < 4; mi++) {
        int r = m0 + warp_row * 64 + mi * 16 + (lane >> 2);
#pragma unroll
        for (int ni = 0; ni < 4; ni++) {
            int cc = n0 + warp_col * 32 + ni * 8 + (lane & 3) * 2;
            *(__half2*)(Cout + (size_t)r * 1024 + cc) =
                __half2(__float2half_rn(acc[mi][ni][0]),
                        __float2half_rn(acc[mi][ni][1]));
            *(__half2*)(Cout + (size_t)(r + 8) * 1024 + cc) =
                __half2(__float2half_rn(acc[mi][ni][2]),
                        __float2half_rn(acc[mi][ni][3]));
        }
    }
}

// ---------------------------------------------------------------------------
// Batched fp32->fp16 convert for (key, value, Wk, Wv) in one launch.
// ---------------------------------------------------------------------------
__global__ __launch_bounds__(256) void cvt_all_kernel(
    const float* __restrict__ key, __half* __restrict__ dk,
    const float* __restrict__ value, __half* __restrict__ dv,
    const float* __restrict__ Wk, __half* __restrict__ dwk,
    const float* __restrict__ Wv, __half* __restrict__ dwv)
{
    int b = blockIdx.x;
    const float* s; __half* d; int i;
    if (b < 16384)      { s = key;   d = dk;  i = b; }
    else if (b < 32768) { s = value; d = dv;  i = b - 16384; }
    else if (b < 33280) { s = Wk;    d = dwk; i = b - 32768; }
    else                { s = Wv;    d = dwv; i = b - 33280; }
    int idx = (i * 256 + threadIdx.x) * 8;
    float4 v0 = *(const float4*)(s + idx);
    float4 v1 = *(const float4*)(s + idx + 4);
    __half2 h[4];
    h[0] = __floats2half2_rn(v0.x, v0.y);
    h[1] = __floats2half2_rn(v0.z, v0.w);
    h[2] = __floats2half2_rn(v1.x, v1.y);
    h[3] = __floats2half2_rn(v1.z, v1.w);
    *(uint4*)(d + idx) = *(uint4*)h;
}

__global__ __launch_bounds__(256) void cvt16_kernel(
    const float* __restrict__ src, __half* __restrict__ dst, int n)
{
    int i = (blockIdx.x * 256 + threadIdx.x) * 8;
    if (i >= n) return;
    float4 v0 = *(const float4*)(src + i);
    float4 v1 = *(const float4*)(src + i + 4);
    __half2 h[4];
    h[0] = __floats2half2_rn(v0.x, v0.y);
    h[1] = __floats2half2_rn(v0.z, v0.w);
    h[2] = __floats2half2_rn(v1.x, v1.y);
    h[3] = __floats2half2_rn(v1.z, v1.w);
    *(uint4*)(dst + i) = *(uint4*)h;
}

__global__ __launch_bounds__(256) void tsplit16_kernel(
    const float* __restrict__ W, __half* __restrict__ hi, __half* __restrict__ lo)
{
    __shared__ float t[32][33];
    const int o0 = blockIdx.y * 32, i0 = blockIdx.x * 32;
    const int c = threadIdx.x & 31;
    const int r0 = threadIdx.x >> 5;
#pragma unroll
    for (int it = 0; it < 4; it++) {
        int r = r0 + it * 8;
        t[r][c] = W[(size_t)(o0 + r) * 1024 + i0 + c];
    }
    __syncthreads();
#pragma unroll
    for (int it = 0; it < 4; it++) {
        int r = r0 + it * 8;
        float v = t[c][r];
        __half h = __float2half_rn(v);
        size_t idx = (size_t)(i0 + r) * 1024 + o0 + c;
        hi[idx] = h;
        lo[idx] = __float2half_rn(v - __half2float(h));
    }
}

// ---------------------------------------------------------------------------
// p_attn core + edges fused. grid (32 bh, 16 s-split), block 256.
// ---------------------------------------------------------------------------
__global__ __launch_bounds__(256) void pa_core_mma(
    const __half* __restrict__ k16, const __half* __restrict__ vh16,
    const float* __restrict__ pos, float* __restrict__ pa)
{
    __shared__ __half Ks[32 * 136];
    __shared__ __half Vh[32 * 136];
    __shared__ float ps[32];

    const int bh = blockIdx.x;
    const int b = bh >> 3;
    const int sp = blockIdx.y;
    const int tid = threadIdx.x;
    const int wid = tid >> 5, lane = tid & 31;
    const int warp_row = wid >> 2;
    const int warp_col = wid & 3;

    const uint32_t ksb = smem_u32(Ks);
    const uint32_t vhb = smem_u32(Vh);

    const size_t gbase = ((size_t)bh * NS + sp * 512) * NDK;
    const float* posb = pos + (size_t)b * NS + sp * 512;

    float acc[4][4][4];
#pragma unroll
    for (int mi = 0; mi < 4; mi++)
#pragma unroll
        for (int ni = 0; ni < 4; ni++)
#pragma unroll
            for (int q = 0; q < 4; q++) acc[mi][ni][q] = 0.f;

    float eacc = 0.f;
    float p2 = 0.f;

    const int aRow = (lane & 7) | ((lane >> 4) << 3);
    const int aCol = ((lane >> 3) & 1) << 3;
    const int bRow = (lane & 7) | (((lane >> 3) & 1) << 3);
    const int bCol = ((lane >> 4) & 1) << 3;
    const int ecol = tid & 127;

    for (int s0 = 0; s0 < 512; s0 += 32) {
#pragma unroll
        for (int it = 0; it < 2; it++) {
            int f = tid + it * 256;
            int row = f >> 4;
            int c8 = (f & 15) * 8;
            size_t ga = gbase + (size_t)(s0 + row) * NDK + c8;
            int so = row * 136 + c8;
            *(float4*)(Ks + so) = *(const float4*)(k16 + ga);
            *(float4*)(Vh + so) = *(const float4*)(vh16 + ga);
        }
        if (tid < 32) ps[tid] = posb[s0 + tid];
        __syncthreads();

#pragma unroll
        for (int ki = 0; ki < 2; ki++) {
            const int kio = ki * 16;
            uint32_t af[4][4], bhi[4][2];
#pragma unroll
            for (int mi = 0; mi < 4; mi++) {
                int mcol = warp_row * 64 + mi * 16 + aCol;
                ldsm4t(af[mi], ksb + (kio + aRow) * 272 + mcol * 2);
            }
#pragma unroll
            for (int g = 0; g < 2; g++) {
                int ec = warp_col * 32 + g * 16 + bCol;
                uint32_t tr[4];
                ldsm4t(tr, vhb + (kio + bRow) * 272 + ec * 2);
                bhi[2 * g][0] = tr[0]; bhi[2 * g][1] = tr[1];
                bhi[2 * g + 1][0] = tr[2]; bhi[2 * g + 1][1] = tr[3];
            }
#pragma unroll
            for (int mi = 0; mi < 4; mi++)
#pragma unroll
                for (int ni = 0; ni < 4; ni++)
                    mma_f16(acc[mi][ni], af[mi], bhi[ni]);
        }

        if (tid < 128) {
#pragma unroll 8
            for (int r = 0; r < 32; r++)
                eacc = fmaf(ps[r], __half2float(Vh[r * 136 + ecol]), eacc);
        } else {
#pragma unroll 8
            for (int r = 0; r < 32; r++)
                eacc = fmaf(ps[r], __half2float(Ks[r * 136 + ecol]), eacc);
        }
        if (wid == 0) { float pv = ps[lane]; p2 = fmaf(pv, pv, p2); }
        __syncthreads();
    }

    const float invS = 1.0f / (float)NS;
    float* pab = pa + (size_t)bh * NE * NE;
#pragma unroll
    for (int mi = 0; mi < 4; mi++) {
        int d0 = warp_row * 64 + mi * 16 + (lane >> 2);
#pragma unroll
        for (int ni = 0; ni < 4; ni++) {
            int e0 = warp_col * 32 + ni * 8 + (lane & 3) * 2;
            atomicAdd(&pab[(1 + d0) * NE + 1 + e0],     acc[mi][ni][0] * invS);
            atomicAdd(&pab[(1 + d0) * NE + 2 + e0],     acc[mi][ni][1] * invS);
            atomicAdd(&pab[(1 + d0 + 8) * NE + 1 + e0], acc[mi][ni][2] * invS);
            atomicAdd(&pab[(1 + d0 + 8) * NE + 2 + e0], acc[mi][ni][3] * invS);
        }
    }
    if (tid < 128) atomicAdd(&pab[0 * NE + 1 + ecol], eacc * invS);
    else           atomicAdd(&pab[(1 + ecol) * NE + 0], eacc * invS);
    if (wid == 0) {
#pragma unroll
        for (int o = 16; o > 0; o >>= 1)
            p2 += __shfl_xor_sync(0xffffffffu, p2, o);
        if (lane == 0) atomicAdd(&pab[0], p2 * invS);
    }
}

// ---------------------------------------------------------------------------
// Gd (fp16 hi/lo) = pa @ Wfc_h^T (head cols); d==0 col -> gpos (atomic sum).
// ---------------------------------------------------------------------------
__global__ __launch_bounds__(256) void g_kernel(
    const float* __restrict__ pa, const float* __restrict__ Wfc,
    __half* __restrict__ gdh, __half* __restrict__ gdl, float* __restrict__ gpos)
{
    extern __shared__ float sm[];
    float* pas = sm;
    float* ws  = sm + 129 * 132;

    const int nt = blockIdx.x, h = blockIdx.y, b = blockIdx.z;
    const int tid = threadIdx.x;
    const int n0 = nt * 128;

    const float* pab = pa + ((size_t)(b * NH + h)) * NE * NE;
    for (int i = tid; i < NE * NE; i += 256) {
        int d = i / NE, e = i - d * NE;
        pas[d * 132 + e] = pab[i];
    }
    for (int i = tid; i < 128 * NE; i += 256) {
        int n = i / NE, e = i - n * NE;
        ws[n * 132 + e] = Wfc[(size_t)(n0 + n) * KFC + h * NE + e];
    }
    __syncthreads();

    for (int o = tid; o < 128 * NE; o += 256) {
        int n = o / NE, d = o - n * NE;
        const float* pr = &pas[d * 132];
        const float* wr = &ws[n * 132];
        float acc = 0.f;
#pragma unroll 8
        for (int e4 = 0; e4 < 128; e4 += 4) {
            float4 a = *(const float4*)(pr + e4);
            float4 w = *(const float4*)(wr + e4);
            acc = fmaf(a.x, w.x, acc);
            acc = fmaf(a.y, w.y, acc);
            acc = fmaf(a.z, w.z, acc);
            acc = fmaf(a.w, w.w, acc);
        }
        acc = fmaf(pr[128], wr[128], acc);
        if (d == 0) {
            atomicAdd(&gpos[b * 1024 + n0 + n], acc);
        } else {
            size_t idx = ((size_t)b * 1024 + n0 + n) * 1024 + h * NDK + d - 1;
            __half hh = __float2half_rn(acc);
            gdh[idx] = hh;
            gdl[idx] = __float2half_rn(acc - __half2float(hh));
        }
    }
}

// ---------------------------------------------------------------------------
__global__ __launch_bounds__(256) void bias2_kernel(
    const __half* __restrict__ gdh, const __half* __restrict__ gdl,
    const float* __restrict__ bq, const float* __restrict__ bfc,
    float* __restrict__ bias2)
{
    const int n = blockIdx.x, b = blockIdx.y;
    const int tid = threadIdx.x;
    size_t base = ((size_t)b * 1024 + n) * 1024;
    float acc = 0.f;
    for (int o = tid; o < 1024; o += 256) {
        float v = __half2float(gdh[base + o]) + __half2float(gdl[base + o]);
        acc = fmaf(bq[o], v, acc);
    }
    __shared__ float red[256];
    red[tid] = acc;
    __syncthreads();
    for (int o = 128; o > 0; o >>= 1) {
        if (tid < o) red[tid] += red[tid + o];
        __syncthreads();
    }
    if (tid == 0) bias2[b * 1024 + n] = red[0] + bfc[n];
}

// ============================ host side ====================================
typedef CUresult (*EncodeFn)(CUtensorMap*, CUtensorMapDataType, cuuint32_t, void*,
                             const cuuint64_t*, const cuuint64_t*, const cuuint32_t*,
                             const cuuint32_t*, CUtensorMapInterleave, CUtensorMapSwizzle,
                             CUtensorMapL2promotion, CUtensorMapFloatOOBfill);

static EncodeFn get_encode() {
    static EncodeFn fn = nullptr;
    if (!fn) {
        void* p = nullptr;
        cudaDriverEntryPointQueryResult st;
        cudaGetDriverEntryPoint("cuTensorMapEncodeTiled", &p, cudaEnableDefault, &st);
        fn = (EncodeFn)p;
    }
    return fn;
}

static void encode_f16(CUtensorMap* m, const void* base,
                       uint64_t kdim, uint64_t rows, uint64_t nz, uint32_t boxRows) {
    cuuint64_t dims[3]    = { kdim, rows, nz };
    cuuint64_t strides[2] = { kdim * 2, rows * kdim * 2 };
    cuuint32_t box[3]     = { 64, boxRows, 1 };
    cuuint32_t est[3]     = { 1, 1, 1 };
    get_encode()(m, CU_TENSOR_MAP_DATA_TYPE_FLOAT16, 3, (void*)base,
                 dims, strides, box, est,
                 CU_TENSOR_MAP_INTERLEAVE_NONE, CU_TENSOR_MAP_SWIZZLE_128B,
                 CU_TENSOR_MAP_L2_PROMOTION_L2_128B, CU_TENSOR_MAP_FLOAT_OOB_FILL_NONE);
}

extern "C" void kernel_launch(void* const* d_in, const int* in_sizes, int n_in,
                              void* d_out, int out_size)
{
    (void)in_sizes; (void)n_in; (void)out_size;
    const float* query = (const float*)d_in[0];
    const float* key   = (const float*)d_in[1];
    const float* value = (const float*)d_in[2];
    const float* pos   = (const float*)d_in[3];
    const float* Wq    = (const float*)d_in[4];
    const float* bq    = (const float*)d_in[5];
    const float* Wk    = (const float*)d_in[6];
    const float* bk    = (const float*)d_in[7];
    const float* Wv    = (const float*)d_in[8];
    const float* bv    = (const float*)d_in[9];
    const float* gK    = (const float*)d_in[10];
    const float* betaK = (const float*)d_in[11];
    const float* gV    = (const float*)d_in[12];
    const float* betaV = (const float*)d_in[13];
    const float* Wfc   = (const float*)d_in[14];
    const float* bfc   = (const float*)d_in[15];
    float* out = (float*)d_out;

    float *pa, *gpos, *bias2;
    __half *a16, *c16, *bh16, *bl16, *k16, *vh16, *wc16;
    cudaGetSymbolAddress((void**)&pa, g_pa);
    cudaGetSymbolAddress((void**)&gpos, g_gpos);
    cudaGetSymbolAddress((void**)&bias2, g_bias2);
    cudaGetSymbolAddress((void**)&a16, g_a16);
    cudaGetSymbolAddress((void**)&c16, g_c16);
    cudaGetSymbolAddress((void**)&bh16, g_bh16);
    cudaGetSymbolAddress((void**)&bl16, g_bl16);
    cudaGetSymbolAddress((void**)&k16, g_k16);
    cudaGetSymbolAddress((void**)&vh16, g_vh16);
    cudaGetSymbolAddress((void**)&wc16, g_wc16);

    cudaFuncSetAttribute(gemm_kv, cudaFuncAttributeMaxDynamicSharedMemorySize,
                         (int)SMEM_KV);
    cudaFuncSetAttribute(gemm_out, cudaFuncAttributeMaxDynamicSharedMemorySize,
                         (int)SMEM_OUT);
    cudaFuncSetAttribute(gemm_mma3, cudaFuncAttributeMaxDynamicSharedMemorySize,
                         (int)SMEM3_DYN);
    cudaFuncSetAttribute(g_kernel, cudaFuncAttributeMaxDynamicSharedMemorySize,
                         (129 + 128) * 132 * (int)sizeof(float));

    CUtensorMap tAK, tAV, tBkv, tGh, tGl, tWqh, tWql, tAq, tWc;
    encode_f16(&tAK, a16, 1024, 32768, 1, 128);
    encode_f16(&tAV, c16, 1024, 32768, 1, 128);
    encode_f16(&tBkv, bh16, 1024, 1024, 2, 256);          // z: 0=Wk, 1=Wv
    encode_f16(&tGh,  a16,           1024, 1024, 4, 128); // Gd hi
    encode_f16(&tGl,  a16 + 4194304, 1024, 1024, 4, 128); // Gd lo
    encode_f16(&tWqh, bh16, 1024, 1024, 1, 128);
    encode_f16(&tWql, bl16, 1024, 1024, 1, 128);
    encode_f16(&tAq,  a16,  1024, 32768, 1, 128);
    encode_f16(&tWc,  wc16, 1024, 1024, 4, 256);          // Wcomb fp16

    const int NA = 33554432, NW = 1048576;

    // Inputs to fp16 (key, value, Wk, Wv in one launch)
    cvt_all_kernel<<<33792, 256>>>(key, a16, value, c16,
                                   Wk, bh16, Wv, bh16 + NW);

    // K+V projection with fused per-head LN (BN=256: 2 heads per tile)
    gemm_kv<<<dim3(4, 256, 2), 288, SMEM_KV>>>(
        tAK, tAV, tBkv, bk, bv, gK, betaK, gV, betaV, k16, vh16);

    // p_attn = Kc^T Vc / S  (core + edges fused)
    cudaMemsetAsync(pa, 0, (size_t)32 * NE * NE * sizeof(float));
    pa_core_mma<<<dim3(32, 16), 256>>>(k16, vh16, pos, pa);

    // Gd (fp16 hi/lo directly into a16) + gpos
    cudaMemsetAsync(gpos, 0, 4096 * sizeof(float));
    g_kernel<<<dim3(8, NH, NB), 256, (129 + 128) * 132 * sizeof(float)>>>(
        pa, Wfc, a16, a16 + 4194304, gpos);

    // bias2 = bfc + bq @ (Gd hi+lo)^T
    bias2_kernel<<<dim3(1024, 4), 256>>>(a16, a16 + 4194304, bq, bfc, bias2);

    // Wq^T hi/lo
    tsplit16_kernel<<<dim3(32, 32), 256>>>(Wq, bh16, bl16);

    // Wcomb[b] = Gd[b] @ Wq (3-pass) -> fp16 directly into wc16
    gemm_mma3<<<dim3(8, 8, 4), 256, SMEM3_DYN>>>(tGh, tGl, tWqh, tWql, wc16, 16);

    // query -> fp16 (a16 free after gemm_mma3 consumed Gd)
    cvt16_kernel<<<NA / 2048, 256>>>(query, a16, NA);

    // out[b] = query[b] @ Wcomb[b]^T + pos (x) gpos[b] + bias2[b]  (BN=256)
    gemm_out<<<dim3(4, 64, 4), 288, SMEM_OUT>>>(tAq, tWc, bias2, pos, gpos, out);
}

// round 13
// speedup vs baseline: 8.6165x; 1.0846x over previous
#include <cuda_runtime.h>
#include <cuda.h>
#include <cuda_fp16.h>
#include <cstdint>
#include <cstddef>

// Problem constants
#define NB 4
#define NS 8192
#define ND 1024
#define NH 8
#define NDK 128
#define NE 129
#define NM 32768
#define KFC 1032

// ---------------- scratch (static device globals; no allocations) ----------
static __device__ float g_pa[532512];       // (32, 129, 129) p_attn
static __device__ float g_gpos[4096];       // (B, 1024) pos-column of G (sum over h)
static __device__ float g_bias2[4096];      // (B, 1024) folded bias
static __device__ __half g_a16[33554432];   // key fp16 / Gd hi+lo / query fp16
static __device__ __half g_c16[33554432];   // value fp16
static __device__ __half g_bh16[4227072];   // B hi (Wk+Wv / Wq hi)
static __device__ __half g_bl16[4227072];   // B lo (Wq lo for gemm3)
static __device__ __half g_k16[33554432];   // LN'd K, head-major (bh,s,d) fp16
static __device__ __half g_vh16[33554432];  // LN'd V, head-major fp16
static __device__ __half g_wc16[4194304];   // Wcomb fp16 (B,1024,1024)

// ============================ PTX helpers ==================================
__device__ __forceinline__ uint32_t smem_u32(const void* p) {
    uint32_t a;
    asm("{ .reg .u64 t; cvta.to.shared.u64 t, %1; cvt.u32.u64 %0, t; }"
        : "=r"(a) : "l"(p));
    return a;
}
__device__ __forceinline__ void mbar_init(uint32_t mbar, uint32_t cnt) {
    asm volatile("mbarrier.init.shared.b64 [%0], %1;" :: "r"(mbar), "r"(cnt) : "memory");
}
__device__ __forceinline__ void mbar_expect_tx(uint32_t mbar, uint32_t bytes) {
    asm volatile("mbarrier.arrive.expect_tx.shared.b64 _, [%0], %1;"
                 :: "r"(mbar), "r"(bytes) : "memory");
}
__device__ __forceinline__ void mbar_arrive(uint32_t mbar) {
    asm volatile("mbarrier.arrive.shared.b64 _, [%0];" :: "r"(mbar) : "memory");
}
__device__ __forceinline__ void mbar_wait(uint32_t mbar, uint32_t parity) {
    asm volatile(
        "{\n\t.reg .pred P;\n\t"
        "BWL_%=:\n\t"
        "mbarrier.try_wait.parity.acquire.cta.shared::cta.b64 P, [%0], %1, 0x989680;\n\t"
        "@P bra.uni BWD_%=;\n\t"
        "bra.uni BWL_%=;\n\t"
        "BWD_%=:\n\t}"
        :: "r"(mbar), "r"(parity) : "memory");
}
__device__ __forceinline__ void tma_load_3d(uint32_t dst, const CUtensorMap* tm,
                                            int x, int y, int z, uint32_t mbar) {
    asm volatile(
        "cp.async.bulk.tensor.3d.shared::cta.global.tile.mbarrier::complete_tx::bytes "
        "[%0], [%1, {%2, %3, %4}], [%5];"
        :: "r"(dst), "l"(tm), "r"(x), "r"(y), "r"(z), "r"(mbar) : "memory");
}
__device__ __forceinline__ void fence_async_shared() {
    asm volatile("fence.proxy.async.shared::cta;" ::: "memory");
}
__device__ __forceinline__ void ldsm4(uint32_t* r, uint32_t addr) {
    asm volatile("ldmatrix.sync.aligned.m8n8.x4.shared.b16 {%0,%1,%2,%3}, [%4];"
                 : "=r"(r[0]), "=r"(r[1]), "=r"(r[2]), "=r"(r[3]) : "r"(addr));
}
__device__ __forceinline__ void ldsm4t(uint32_t* r, uint32_t addr) {
    asm volatile("ldmatrix.sync.aligned.m8n8.x4.trans.shared.b16 {%0,%1,%2,%3}, [%4];"
                 : "=r"(r[0]), "=r"(r[1]), "=r"(r[2]), "=r"(r[3]) : "r"(addr));
}
__device__ __forceinline__ void mma_f16(float* c, const uint32_t* a, const uint32_t* b) {
    asm volatile(
        "mma.sync.aligned.m16n8k16.row.col.f32.f16.f16.f32 "
        "{%0,%1,%2,%3}, {%4,%5,%6,%7}, {%8,%9}, {%0,%1,%2,%3};"
        : "+f"(c[0]), "+f"(c[1]), "+f"(c[2]), "+f"(c[3])
        : "r"(a[0]), "r"(a[1]), "r"(a[2]), "r"(a[3]), "r"(b[0]), "r"(b[1]));
}
__device__ __forceinline__ uint32_t swz(uint32_t base, int r, int c) {
    return base + r * 128 + (c ^ ((r & 7) << 4));
}

// ============================ GEMM constants ===============================
static constexpr uint32_t OPA_BYTES = 128 * 64 * 2;   // 16 KB
static constexpr uint32_t OPB_BYTES = 256 * 64 * 2;   // 32 KB
static constexpr uint32_t STG_BYTES = OPA_BYTES + OPB_BYTES;  // 48 KB
static constexpr uint32_t CTRL_BYTES = 1024;
static constexpr int ST = 4;
static constexpr uint32_t STAGES_END = CTRL_BYTES + ST * STG_BYTES;   // 197632
static constexpr uint32_t SMEM_KV = STAGES_END + 16384 + 2048;        // 216064
static constexpr uint32_t SMEM_OUT = STAGES_END;                      // 197632

// ============================ K/V projection + fused LN ====================
// grid (4 nblk, 256 m-tiles, 2 kv), 288 threads (8 compute + producer warp).
__global__ __launch_bounds__(288, 1) void gemm_kv(
    const __grid_constant__ CUtensorMap tmAK,
    const __grid_constant__ CUtensorMap tmAV,
    const __grid_constant__ CUtensorMap tmB,    // batched (z: 0=Wk, 1=Wv)
    const float* __restrict__ bk, const float* __restrict__ bv,
    const float* __restrict__ gK, const float* __restrict__ betaK,
    const float* __restrict__ gV, const float* __restrict__ betaV,
    __half* __restrict__ k16, __half* __restrict__ vh16)
{
    extern __shared__ __align__(1024) char smem[];
    const uint32_t sb = smem_u32(smem);
    const int tid = threadIdx.x;
    const int wid = tid >> 5, lane = tid & 31;
    const int warp_row = wid >> 2;
    const int warp_col = wid & 3;
    const bool producer = (wid == 8);

    const uint32_t full0  = sb;
    const uint32_t empty0 = sb + 128;
    const uint32_t tiles  = sb + CTRL_BYTES;

    const int nblk = blockIdx.x;
    const int n0g = nblk * 256;
    const int m0 = blockIdx.y * 128;
    const int zKV = blockIdx.z;
    const CUtensorMap* tmA = zKV ? &tmAV : &tmAK;
    const int KB = 16;

    if (tid == 0) {
        for (int s = 0; s < ST; s++) {
            mbar_init(full0 + s * 8, 1);
            mbar_init(empty0 + s * 8, 256);
        }
        fence_async_shared();
    }
    __syncthreads();

    float acc[4][8][4];
#pragma unroll
    for (int mi = 0; mi < 4; mi++)
#pragma unroll
        for (int ni = 0; ni < 8; ni++)
#pragma unroll
            for (int q = 0; q < 4; q++) acc[mi][ni][q] = 0.f;

    if (producer) {
        if (lane == 0) {
            for (int s = 0; s < ST; s++) {
                uint32_t fb = full0 + s * 8;
                mbar_expect_tx(fb, STG_BYTES);
                uint32_t a0 = tiles + s * STG_BYTES;
                tma_load_3d(a0,             tmA,  s * 64, m0,  0,   fb);
                tma_load_3d(a0 + OPA_BYTES, &tmB, s * 64, n0g, zKV, fb);
            }
            for (int kb = ST; kb < KB; kb++) {
                int s = kb % ST;
                mbar_wait(empty0 + s * 8, (uint32_t)(((kb - ST) / ST) & 1));
                uint32_t fb = full0 + s * 8;
                mbar_expect_tx(fb, STG_BYTES);
                uint32_t a0 = tiles + s * STG_BYTES;
                tma_load_3d(a0,             tmA,  kb * 64, m0,  0,   fb);
                tma_load_3d(a0 + OPA_BYTES, &tmB, kb * 64, n0g, zKV, fb);
            }
        }
    } else {
        const int aR = lane & 15;
        const int aC = (lane >> 4) << 4;
        const int bR = ((lane >> 4) << 3) + (lane & 7);
        const int bC = ((lane >> 3) & 1) << 4;

        for (int kb = 0; kb < KB; kb++) {
            const int s = kb % ST;
            mbar_wait(full0 + s * 8, (uint32_t)((kb / ST) & 1));

            const uint32_t A0 = tiles + s * STG_BYTES;
            const uint32_t B0 = A0 + OPA_BYTES;

#pragma unroll
            for (int ki = 0; ki < 4; ki++) {
                const int kc = ki * 32;
                uint32_t af[4][4], bhi[8][2];
#pragma unroll
                for (int mi = 0; mi < 4; mi++) {
                    int r = warp_row * 64 + mi * 16 + aR;
                    ldsm4(af[mi], swz(A0, r, kc + aC));
                }
#pragma unroll
                for (int g = 0; g < 4; g++) {
                    int r = warp_col * 64 + g * 16 + bR;
                    uint32_t tr[4];
                    ldsm4(tr, swz(B0, r, kc + bC));
                    bhi[2 * g][0] = tr[0]; bhi[2 * g][1] = tr[1];
                    bhi[2 * g + 1][0] = tr[2]; bhi[2 * g + 1][1] = tr[3];
                }
                if (ki == 3) mbar_arrive(empty0 + s * 8);
#pragma unroll
                for (int mi = 0; mi < 4; mi++)
#pragma unroll
                    for (int ni = 0; ni < 8; ni++)
                        mma_f16(acc[mi][ni], af[mi], bhi[ni]);
            }
        }
    }

    // ---- fused LN epilogue ----
    __syncthreads();

    float2* part  = (float2*)(smem + STAGES_END);           // [128][16]
    float2* stats = (float2*)(smem + STAGES_END + 16384);   // [128][2]

    const float* biasp = zKV ? bv : bk;
    const float* gsel  = zKV ? gV : gK;
    const float* besel = zKV ? betaV : betaK;
    __half* outp = zKV ? vh16 : k16;
    const int hh = warp_col >> 1;

    if (!producer) {
        const int slot = warp_col * 4 + (lane & 3);
#pragma unroll
        for (int mi = 0; mi < 4; mi++) {
#pragma unroll
            for (int ni = 0; ni < 8; ni++) {
                int col = warp_col * 64 + ni * 8 + (lane & 3) * 2;
                float b0v = biasp[n0g + col], b1v = biasp[n0g + col + 1];
                acc[mi][ni][0] += b0v; acc[mi][ni][1] += b1v;
                acc[mi][ni][2] += b0v; acc[mi][ni][3] += b1v;
            }
#pragma unroll
            for (int half = 0; half < 2; half++) {
                float s = 0.f, sq = 0.f;
#pragma unroll
                for (int ni = 0; ni < 8; ni++) {
                    float v0 = acc[mi][ni][half * 2 + 0];
                    float v1 = acc[mi][ni][half * 2 + 1];
                    s += v0 + v1;
                    sq += v0 * v0 + v1 * v1;
                }
                int r = warp_row * 64 + mi * 16 + (lane >> 2) + half * 8;
                part[r * 16 + slot] = make_float2(s, sq);
            }
        }
    }
    __syncthreads();
    if (tid < 256) {
        int r = tid >> 1, hsel = tid & 1;
        float s = 0.f, sq = 0.f;
#pragma unroll
        for (int i = 0; i < 8; i++) {
            float2 p = part[r * 16 + hsel * 8 + i];
            s += p.x; sq += p.y;
        }
        float mean = s * (1.f / 128.f);
        float var  = sq * (1.f / 128.f) - mean * mean;
        stats[r * 2 + hsel] = make_float2(mean, rsqrtf(var + 1e-5f));
    }
    __syncthreads();

    if (!producer) {
#pragma unroll
        for (int mi = 0; mi < 4; mi++) {
#pragma unroll
            for (int half = 0; half < 2; half++) {
                int r = warp_row * 64 + mi * 16 + (lane >> 2) + half * 8;
                float2 st = stats[r * 2 + hh];
                int m = m0 + r;
                int b = m >> 13, sIdx = m & 8191;
                size_t base = (((size_t)(b * NH + nblk * 2 + hh)) * NS + sIdx) * NDK;
#pragma unroll
                for (int ni = 0; ni < 8; ni++) {
                    int col = warp_col * 64 + ni * 8 + (lane & 3) * 2;
                    int c128 = col & 127;
                    float gg0 = gsel[n0g + col],  gg1 = gsel[n0g + col + 1];
                    float be0 = besel[n0g + col], be1 = besel[n0g + col + 1];
                    float y0 = (acc[mi][ni][half * 2 + 0] - st.x) * st.y * gg0 + be0;
                    float y1 = (acc[mi][ni][half * 2 + 1] - st.x) * st.y * gg1 + be1;
                    *(__half2*)(outp + base + c128) =
                        __half2(__float2half_rn(y0), __float2half_rn(y1));
                }
            }
        }
    }
}

// ============================ final GEMM (BN=256) ==========================
__global__ __launch_bounds__(288, 1) void gemm_out(
    const __grid_constant__ CUtensorMap tmA,
    const __grid_constant__ CUtensorMap tmB,
    const float* __restrict__ bias2,
    const float* __restrict__ posv,
    const float* __restrict__ gposv,
    float* __restrict__ C)
{
    extern __shared__ __align__(1024) char smem[];
    const uint32_t sb = smem_u32(smem);
    const int tid = threadIdx.x;
    const int wid = tid >> 5, lane = tid & 31;
    const int warp_row = wid >> 2;
    const int warp_col = wid & 3;
    const bool producer = (wid == 8);

    const uint32_t full0  = sb;
    const uint32_t empty0 = sb + 128;
    const uint32_t tiles  = sb + CTRL_BYTES;

    const int n0 = blockIdx.x * 256;
    const int zB = blockIdx.z;
    const int m0 = zB * 8192 + blockIdx.y * 128;
    const int KB = 16;

    if (tid == 0) {
        for (int s = 0; s < ST; s++) {
            mbar_init(full0 + s * 8, 1);
            mbar_init(empty0 + s * 8, 256);
        }
        fence_async_shared();
    }
    __syncthreads();

    if (producer) {
        if (lane == 0) {
            for (int s = 0; s < ST; s++) {
                uint32_t fb = full0 + s * 8;
                mbar_expect_tx(fb, STG_BYTES);
                uint32_t a0 = tiles + s * STG_BYTES;
                tma_load_3d(a0,             &tmA, s * 64, m0, 0,  fb);
                tma_load_3d(a0 + OPA_BYTES, &tmB, s * 64, n0, zB, fb);
            }
            for (int kb = ST; kb < KB; kb++) {
                int s = kb % ST;
                mbar_wait(empty0 + s * 8, (uint32_t)(((kb - ST) / ST) & 1));
                uint32_t fb = full0 + s * 8;
                mbar_expect_tx(fb, STG_BYTES);
                uint32_t a0 = tiles + s * STG_BYTES;
                tma_load_3d(a0,             &tmA, kb * 64, m0, 0,  fb);
                tma_load_3d(a0 + OPA_BYTES, &tmB, kb * 64, n0, zB, fb);
            }
        }
        return;
    }

    float acc[4][8][4];
#pragma unroll
    for (int mi = 0; mi < 4; mi++)
#pragma unroll
        for (int ni = 0; ni < 8; ni++)
#pragma unroll
            for (int q = 0; q < 4; q++) acc[mi][ni][q] = 0.f;

    const int aR = lane & 15;
    const int aC = (lane >> 4) << 4;
    const int bR = ((lane >> 4) << 3) + (lane & 7);
    const int bC = ((lane >> 3) & 1) << 4;

    for (int kb = 0; kb < KB; kb++) {
        const int s = kb % ST;
        mbar_wait(full0 + s * 8, (uint32_t)((kb / ST) & 1));

        const uint32_t A0 = tiles + s * STG_BYTES;
        const uint32_t B0 = A0 + OPA_BYTES;

#pragma unroll
        for (int ki = 0; ki < 4; ki++) {
            const int kc = ki * 32;
            uint32_t af[4][4], bhi[8][2];
#pragma unroll
            for (int mi = 0; mi < 4; mi++) {
                int r = warp_row * 64 + mi * 16 + aR;
                ldsm4(af[mi], swz(A0, r, kc + aC));
            }
#pragma unroll
            for (int g = 0; g < 4; g++) {
                int r = warp_col * 64 + g * 16 + bR;
                uint32_t tr[4];
                ldsm4(tr, swz(B0, r, kc + bC));
                bhi[2 * g][0] = tr[0]; bhi[2 * g][1] = tr[1];
                bhi[2 * g + 1][0] = tr[2]; bhi[2 * g + 1][1] = tr[3];
            }
            if (ki == 3) mbar_arrive(empty0 + s * 8);
#pragma unroll
            for (int mi = 0; mi < 4; mi++)
#pragma unroll
                for (int ni = 0; ni < 8; ni++)
                    mma_f16(acc[mi][ni], af[mi], bhi[ni]);
        }
    }

    const float* biasp = bias2 + zB * 1024;
    const float* gpp   = gposv + zB * 1024;

#pragma unroll
    for (int mi = 0; mi < 4; mi++) {
        int r = m0 + warp_row * 64 + mi * 16 + (lane >> 2);
        float pv = posv[r];
        float pv2 = posv[r + 8];
#pragma unroll
        for (int ni = 0; ni < 8; ni++) {
            int cc = n0 + warp_col * 64 + ni * 8 + (lane & 3) * 2;
            float b0v = biasp[cc], b1v = biasp[cc + 1];
            float g0 = gpp[cc], g1 = gpp[cc + 1];
            float2 v0 = { acc[mi][ni][0] + b0v + pv * g0,
                          acc[mi][ni][1] + b1v + pv * g1 };
            float2 v1 = { acc[mi][ni][2] + b0v + pv2 * g0,
                          acc[mi][ni][3] + b1v + pv2 * g1 };
            *(float2*)(C + (size_t)r * 1024 + cc) = v0;
            *(float2*)(C + (size_t)(r + 8) * 1024 + cc) = v1;
        }
    }
}

// ============================ 3-pass GEMM (A hi/lo, B hi/lo) ===============
static constexpr int ST3 = 3;
static constexpr uint32_t OP_BYTES = 128 * 64 * 2;
static constexpr uint32_t STG3_BYTES = 4 * OP_BYTES;
static constexpr uint32_t SMEM3_DYN = CTRL_BYTES + ST3 * STG3_BYTES;

__global__ __launch_bounds__(256, 1) void gemm_mma3(
    const __grid_constant__ CUtensorMap tmAhi,
    const __grid_constant__ CUtensorMap tmAlo,
    const __grid_constant__ CUtensorMap tmBhi,
    const __grid_constant__ CUtensorMap tmBlo,
    __half* __restrict__ Cout, int KB)
{
    extern __shared__ __align__(1024) char smem[];
    const uint32_t sb = smem_u32(smem);
    const int tid = threadIdx.x;
    const int wid = tid >> 5, lane = tid & 31;
    const int warp_row = wid >> 2;
    const int warp_col = wid & 3;

    const uint32_t full0  = sb;
    const uint32_t empty0 = sb + 128;
    const uint32_t tiles  = sb + CTRL_BYTES;

    const int n0 = blockIdx.x * 128;
    const int aY = blockIdx.y * 128;
    const int aZ = blockIdx.z;
    const int m0 = blockIdx.z * 1024 + aY;

    if (tid == 0) {
        for (int s = 0; s < ST3; s++) {
            mbar_init(full0 + s * 8, 1);
            mbar_init(empty0 + s * 8, 256);
        }
        fence_async_shared();
    }
    __syncthreads();

    if (tid == 0) {
        for (int s = 0; s < ST3; s++) {
            uint32_t fb = full0 + s * 8;
            mbar_expect_tx(fb, STG3_BYTES);
            uint32_t a0 = tiles + s * STG3_BYTES;
            tma_load_3d(a0,                &tmAhi, s * 64, aY, aZ, fb);
            tma_load_3d(a0 + OP_BYTES,     &tmAlo, s * 64, aY, aZ, fb);
            tma_load_3d(a0 + 2 * OP_BYTES, &tmBhi, s * 64, n0, 0,  fb);
            tma_load_3d(a0 + 3 * OP_BYTES, &tmBlo, s * 64, n0, 0,  fb);
        }
    }

    float acc[4][4][4];
#pragma unroll
    for (int mi = 0; mi < 4; mi++)
#pragma unroll
        for (int ni = 0; ni < 4; ni++)
#pragma unroll
            for (int q = 0; q < 4; q++) acc[mi][ni][q] = 0.f;

    const int aR = lane & 15;
    const int aC = (lane >> 4) << 4;
    const int bR = ((lane >> 4) << 3) + (lane & 7);
    const int bC = ((lane >> 3) & 1) << 4;

    for (int kb = 0; kb < KB; kb++) {
        const int s = kb % ST3;
        const uint32_t ph = (uint32_t)((kb / ST3) & 1);
        mbar_wait(full0 + s * 8, ph);

        const uint32_t A0 = tiles + s * STG3_BYTES;
        const uint32_t B0 = A0 + 2 * OP_BYTES;

#pragma unroll
        for (int ki = 0; ki < 4; ki++) {
            const int kc = ki * 32;
            uint32_t ahi[4][4], alo[4][4], bhi[4][2], blo[4][2];
#pragma unroll
            for (int mi = 0; mi < 4; mi++) {
                int r = warp_row * 64 + mi * 16 + aR;
                uint32_t ad = swz(A0, r, kc + aC);
                ldsm4(ahi[mi], ad);
                ldsm4(alo[mi], ad + OP_BYTES);
            }
#pragma unroll
            for (int g = 0; g < 2; g++) {
                int r = warp_col * 32 + g * 16 + bR;
                uint32_t bd = swz(B0, r, kc + bC);
                uint32_t tr[4];
                ldsm4(tr, bd);
                bhi[2 * g][0] = tr[0]; bhi[2 * g][1] = tr[1];
                bhi[2 * g + 1][0] = tr[2]; bhi[2 * g + 1][1] = tr[3];
                ldsm4(tr, bd + OP_BYTES);
                blo[2 * g][0] = tr[0]; blo[2 * g][1] = tr[1];
                blo[2 * g + 1][0] = tr[2]; blo[2 * g + 1][1] = tr[3];
            }
#pragma unroll
            for (int mi = 0; mi < 4; mi++)
#pragma unroll
                for (int ni = 0; ni < 4; ni++) {
                    mma_f16(acc[mi][ni], ahi[mi], bhi[ni]);
                    mma_f16(acc[mi][ni], ahi[mi], blo[ni]);
                    mma_f16(acc[mi][ni], alo[mi], bhi[ni]);
                }
        }

        mbar_arrive(empty0 + s * 8);

        if (tid == 0 && kb + ST3 < KB) {
            mbar_wait(empty0 + s * 8, ph);
            uint32_t fb = full0 + s * 8;
            mbar_expect_tx(fb, STG3_BYTES);
            uint32_t a0 = tiles + s * STG3_BYTES;
            int kx = (kb + ST3) * 64;
            tma_load_3d(a0,                &tmAhi, kx, aY, aZ, fb);
            tma_load_3d(a0 + OP_BYTES,     &tmAlo, kx, aY, aZ, fb);
            tma_load_3d(a0 + 2 * OP_BYTES, &tmBhi, kx, n0, 0,  fb);
            tma_load_3d(a0 + 3 * OP_BYTES, &tmBlo, kx, n0, 0,  fb);
        }
    }

#pragma unroll
    for (int mi = 0; mi < 4; mi++) {
        int r = m0 + warp_row * 64 + mi * 16 + (lane >> 2);
#pragma unroll
        for (int ni = 0; ni < 4; ni++) {
            int cc = n0 + warp_col * 32 + ni * 8 + (lane & 3) * 2;
            *(__half2*)(Cout + (size_t)r * 1024 + cc) =
                __half2(__float2half_rn(acc[mi][ni][0]),
                        __float2half_rn(acc[mi][ni][1]));
            *(__half2*)(Cout + (size_t)(r + 8) * 1024 + cc) =
                __half2(__float2half_rn(acc[mi][ni][2]),
                        __float2half_rn(acc[mi][ni][3]));
        }
    }
}

// ---------------------------------------------------------------------------
__global__ __launch_bounds__(256) void cvt_all_kernel(
    const float* __restrict__ key, __half* __restrict__ dk,
    const float* __restrict__ value, __half* __restrict__ dv,
    const float* __restrict__ Wk, __half* __restrict__ dwk,
    const float* __restrict__ Wv, __half* __restrict__ dwv)
{
    int b = blockIdx.x;
    const float* s; __half* d; int i;
    if (b < 16384)      { s = key;   d = dk;  i = b; }
    else if (b < 32768) { s = value; d = dv;  i = b - 16384; }
    else if (b < 33280) { s = Wk;    d = dwk; i = b - 32768; }
    else                { s = Wv;    d = dwv; i = b - 33280; }
    int idx = (i * 256 + threadIdx.x) * 8;
    float4 v0 = *(const float4*)(s + idx);
    float4 v1 = *(const float4*)(s + idx + 4);
    __half2 h[4];
    h[0] = __floats2half2_rn(v0.x, v0.y);
    h[1] = __floats2half2_rn(v0.z, v0.w);
    h[2] = __floats2half2_rn(v1.x, v1.y);
    h[3] = __floats2half2_rn(v1.z, v1.w);
    *(uint4*)(d + idx) = *(uint4*)h;
}

__global__ __launch_bounds__(256) void cvt16_kernel(
    const float* __restrict__ src, __half* __restrict__ dst, int n)
{
    int i = (blockIdx.x * 256 + threadIdx.x) * 8;
    if (i >= n) return;
    float4 v0 = *(const float4*)(src + i);
    float4 v1 = *(const float4*)(src + i + 4);
    __half2 h[4];
    h[0] = __floats2half2_rn(v0.x, v0.y);
    h[1] = __floats2half2_rn(v0.z, v0.w);
    h[2] = __floats2half2_rn(v1.x, v1.y);
    h[3] = __floats2half2_rn(v1.z, v1.w);
    *(uint4*)(dst + i) = *(uint4*)h;
}

__global__ __launch_bounds__(256) void tsplit16_kernel(
    const float* __restrict__ W, __half* __restrict__ hi, __half* __restrict__ lo)
{
    __shared__ float t[32][33];
    const int o0 = blockIdx.y * 32, i0 = blockIdx.x * 32;
    const int c = threadIdx.x & 31;
    const int r0 = threadIdx.x >> 5;
#pragma unroll
    for (int it = 0; it < 4; it++) {
        int r = r0 + it * 8;
        t[r][c] = W[(size_t)(o0 + r) * 1024 + i0 + c];
    }
    __syncthreads();
#pragma unroll
    for (int it = 0; it < 4; it++) {
        int r = r0 + it * 8;
        float v = t[c][r];
        __half h = __float2half_rn(v);
        size_t idx = (size_t)(i0 + r) * 1024 + o0 + c;
        hi[idx] = h;
        lo[idx] = __float2half_rn(v - __half2float(h));
    }
}

// ---------------------------------------------------------------------------
// p_attn core + edges fused. grid (32 bh, 16 s-split), block 256.
// ---------------------------------------------------------------------------
__global__ __launch_bounds__(256) void pa_core_mma(
    const __half* __restrict__ k16, const __half* __restrict__ vh16,
    const float* __restrict__ pos, float* __restrict__ pa)
{
    __shared__ __half Ks[32 * 136];
    __shared__ __half Vh[32 * 136];
    __shared__ float ps[32];

    const int bh = blockIdx.x;
    const int b = bh >> 3;
    const int sp = blockIdx.y;
    const int tid = threadIdx.x;
    const int wid = tid >> 5, lane = tid & 31;
    const int warp_row = wid >> 2;
    const int warp_col = wid & 3;

    const uint32_t ksb = smem_u32(Ks);
    const uint32_t vhb = smem_u32(Vh);

    const size_t gbase = ((size_t)bh * NS + sp * 512) * NDK;
    const float* posb = pos + (size_t)b * NS + sp * 512;

    float acc[4][4][4];
#pragma unroll
    for (int mi = 0; mi < 4; mi++)
#pragma unroll
        for (int ni = 0; ni < 4; ni++)
#pragma unroll
            for (int q = 0; q < 4; q++) acc[mi][ni][q] = 0.f;

    float eacc = 0.f;
    float p2 = 0.f;

    const int aRow = (lane & 7) | ((lane >> 4) << 3);
    const int aCol = ((lane >> 3) & 1) << 3;
    const int bRow = (lane & 7) | (((lane >> 3) & 1) << 3);
    const int bCol = ((lane >> 4) & 1) << 3;
    const int ecol = tid & 127;

    for (int s0 = 0; s0 < 512; s0 += 32) {
#pragma unroll
        for (int it = 0; it < 2; it++) {
            int f = tid + it * 256;
            int row = f >> 4;
            int c8 = (f & 15) * 8;
            size_t ga = gbase + (size_t)(s0 + row) * NDK + c8;
            int so = row * 136 + c8;
            *(float4*)(Ks + so) = *(const float4*)(k16 + ga);
            *(float4*)(Vh + so) = *(const float4*)(vh16 + ga);
        }
        if (tid < 32) ps[tid] = posb[s0 + tid];
        __syncthreads();

#pragma unroll
        for (int ki = 0; ki < 2; ki++) {
            const int kio = ki * 16;
            uint32_t af[4][4], bhi[4][2];
#pragma unroll
            for (int mi = 0; mi < 4; mi++) {
                int mcol = warp_row * 64 + mi * 16 + aCol;
                ldsm4t(af[mi], ksb + (kio + aRow) * 272 + mcol * 2);
            }
#pragma unroll
            for (int g = 0; g < 2; g++) {
                int ec = warp_col * 32 + g * 16 + bCol;
                uint32_t tr[4];
                ldsm4t(tr, vhb + (kio + bRow) * 272 + ec * 2);
                bhi[2 * g][0] = tr[0]; bhi[2 * g][1] = tr[1];
                bhi[2 * g + 1][0] = tr[2]; bhi[2 * g + 1][1] = tr[3];
            }
#pragma unroll
            for (int mi = 0; mi < 4; mi++)
#pragma unroll
                for (int ni = 0; ni < 4; ni++)
                    mma_f16(acc[mi][ni], af[mi], bhi[ni]);
        }

        if (tid < 128) {
#pragma unroll 8
            for (int r = 0; r < 32; r++)
                eacc = fmaf(ps[r], __half2float(Vh[r * 136 + ecol]), eacc);
        } else {
#pragma unroll 8
            for (int r = 0; r < 32; r++)
                eacc = fmaf(ps[r], __half2float(Ks[r * 136 + ecol]), eacc);
        }
        if (wid == 0) { float pv = ps[lane]; p2 = fmaf(pv, pv, p2); }
        __syncthreads();
    }

    const float invS = 1.0f / (float)NS;
    float* pab = pa + (size_t)bh * NE * NE;
#pragma unroll
    for (int mi = 0; mi < 4; mi++) {
        int d0 = warp_row * 64 + mi * 16 + (lane >> 2);
#pragma unroll
        for (int ni = 0; ni < 4; ni++) {
            int e0 = warp_col * 32 + ni * 8 + (lane & 3) * 2;
            atomicAdd(&pab[(1 + d0) * NE + 1 + e0],     acc[mi][ni][0] * invS);
            atomicAdd(&pab[(1 + d0) * NE + 2 + e0],     acc[mi][ni][1] * invS);
            atomicAdd(&pab[(1 + d0 + 8) * NE + 1 + e0], acc[mi][ni][2] * invS);
            atomicAdd(&pab[(1 + d0 + 8) * NE + 2 + e0], acc[mi][ni][3] * invS);
        }
    }
    if (tid < 128) atomicAdd(&pab[0 * NE + 1 + ecol], eacc * invS);
    else           atomicAdd(&pab[(1 + ecol) * NE + 0], eacc * invS);
    if (wid == 0) {
#pragma unroll
        for (int o = 16; o > 0; o >>= 1)
            p2 += __shfl_xor_sync(0xffffffffu, p2, o);
        if (lane == 0) atomicAdd(&pab[0], p2 * invS);
    }
}

// ---------------------------------------------------------------------------
// Gd (fp16 hi/lo) = pa @ Wfc_h^T; outer-product register tiling (e-major smem).
// grid (8 ntile, 8 h, 4 b), 256 threads as 16x16; 4 (pass_n x pass_d) passes.
// ---------------------------------------------------------------------------
__global__ __launch_bounds__(256) void g_kernel(
    const float* __restrict__ pa, const float* __restrict__ Wfc,
    __half* __restrict__ gdh, __half* __restrict__ gdl, float* __restrict__ gpos)
{
    extern __shared__ float sm[];
    float* pat = sm;                  // [129 e][132 d-stride]  pa transposed
    float* wt  = sm + 129 * 132;      // [129 e][132 n-stride]  Wfc transposed

    const int nt = blockIdx.x, h = blockIdx.y, b = blockIdx.z;
    const int tid = threadIdx.x;
    const int n0 = nt * 128;
    const int ty = tid >> 4, tx = tid & 15;

    const float* pab = pa + ((size_t)(b * NH + h)) * NE * NE;
    for (int i = tid; i < NE * NE; i += 256) {
        int d = i / NE, e = i - d * NE;
        pat[e * 132 + d] = pab[i];
    }
    for (int i = tid; i < 128 * NE; i += 256) {
        int n = i / NE, e = i - n * NE;
        wt[e * 132 + n] = Wfc[(size_t)(n0 + n) * KFC + h * NE + e];
    }
    __syncthreads();

#pragma unroll
    for (int pn = 0; pn < 2; pn++) {
#pragma unroll
        for (int pd = 0; pd < 2; pd++) {
            const int nn = pn * 64 + ty * 4;
            const int dd = pd * 64 + tx * 4;
            float acc[4][4];
#pragma unroll
            for (int i = 0; i < 4; i++)
#pragma unroll
                for (int j = 0; j < 4; j++) acc[i][j] = 0.f;

            for (int e = 0; e < NE; e++) {
                float4 a = *(const float4*)(wt + e * 132 + nn);
                float4 p = *(const float4*)(pat + e * 132 + dd);
                float ar[4] = {a.x, a.y, a.z, a.w};
                float pr[4] = {p.x, p.y, p.z, p.w};
#pragma unroll
                for (int i = 0; i < 4; i++)
#pragma unroll
                    for (int j = 0; j < 4; j++)
                        acc[i][j] = fmaf(ar[i], pr[j], acc[i][j]);
            }

#pragma unroll
            for (int i = 0; i < 4; i++) {
                int n = nn + i;
#pragma unroll
                for (int j = 0; j < 4; j++) {
                    int d = dd + j;
                    float v = acc[i][j];
                    if (d == 0) {
                        atomicAdd(&gpos[b * 1024 + n0 + n], v);
                    } else {
                        size_t idx = ((size_t)b * 1024 + n0 + n) * 1024
                                     + h * NDK + d - 1;
                        __half hh = __float2half_rn(v);
                        gdh[idx] = hh;
                        gdl[idx] = __float2half_rn(v - __half2float(hh));
                    }
                }
            }
        }
    }

    // d = 128 column (last of 129)
    if (tid < 128) {
        int n = tid;
        float accv = 0.f;
        for (int e = 0; e < NE; e++)
            accv = fmaf(wt[e * 132 + n], pat[e * 132 + 128], accv);
        size_t idx = ((size_t)b * 1024 + n0 + n) * 1024 + h * NDK + 127;
        __half hh = __float2half_rn(accv);
        gdh[idx] = hh;
        gdl[idx] = __float2half_rn(accv - __half2float(hh));
    }
}

// ---------------------------------------------------------------------------
__global__ __launch_bounds__(256) void bias2_kernel(
    const __half* __restrict__ gdh, const __half* __restrict__ gdl,
    const float* __restrict__ bq, const float* __restrict__ bfc,
    float* __restrict__ bias2)
{
    const int n = blockIdx.x, b = blockIdx.y;
    const int tid = threadIdx.x;
    size_t base = ((size_t)b * 1024 + n) * 1024;
    float acc = 0.f;
    for (int o = tid; o < 1024; o += 256) {
        float v = __half2float(gdh[base + o]) + __half2float(gdl[base + o]);
        acc = fmaf(bq[o], v, acc);
    }
    __shared__ float red[256];
    red[tid] = acc;
    __syncthreads();
    for (int o = 128; o > 0; o >>= 1) {
        if (tid < o) red[tid] += red[tid + o];
        __syncthreads();
    }
    if (tid == 0) bias2[b * 1024 + n] = red[0] + bfc[n];
}

// ============================ host side ====================================
typedef CUresult (*EncodeFn)(CUtensorMap*, CUtensorMapDataType, cuuint32_t, void*,
                             const cuuint64_t*, const cuuint64_t*, const cuuint32_t*,
                             const cuuint32_t*, CUtensorMapInterleave, CUtensorMapSwizzle,
                             CUtensorMapL2promotion, CUtensorMapFloatOOBfill);

static EncodeFn get_encode() {
    static EncodeFn fn = nullptr;
    if (!fn) {
        void* p = nullptr;
        cudaDriverEntryPointQueryResult st;
        cudaGetDriverEntryPoint("cuTensorMapEncodeTiled", &p, cudaEnableDefault, &st);
        fn = (EncodeFn)p;
    }
    return fn;
}

static void encode_f16(CUtensorMap* m, const void* base,
                       uint64_t kdim, uint64_t rows, uint64_t nz, uint32_t boxRows) {
    cuuint64_t dims[3]    = { kdim, rows, nz };
    cuuint64_t strides[2] = { kdim * 2, rows * kdim * 2 };
    cuuint32_t box[3]     = { 64, boxRows, 1 };
    cuuint32_t est[3]     = { 1, 1, 1 };
    get_encode()(m, CU_TENSOR_MAP_DATA_TYPE_FLOAT16, 3, (void*)base,
                 dims, strides, box, est,
                 CU_TENSOR_MAP_INTERLEAVE_NONE, CU_TENSOR_MAP_SWIZZLE_128B,
                 CU_TENSOR_MAP_L2_PROMOTION_L2_128B, CU_TENSOR_MAP_FLOAT_OOB_FILL_NONE);
}

extern "C" void kernel_launch(void* const* d_in, const int* in_sizes, int n_in,
                              void* d_out, int out_size)
{
    (void)in_sizes; (void)n_in; (void)out_size;
    const float* query = (const float*)d_in[0];
    const float* key   = (const float*)d_in[1];
    const float* value = (const float*)d_in[2];
    const float* pos   = (const float*)d_in[3];
    const float* Wq    = (const float*)d_in[4];
    const float* bq    = (const float*)d_in[5];
    const float* Wk    = (const float*)d_in[6];
    const float* bk    = (const float*)d_in[7];
    const float* Wv    = (const float*)d_in[8];
    const float* bv    = (const float*)d_in[9];
    const float* gK    = (const float*)d_in[10];
    const float* betaK = (const float*)d_in[11];
    const float* gV    = (const float*)d_in[12];
    const float* betaV = (const float*)d_in[13];
    const float* Wfc   = (const float*)d_in[14];
    const float* bfc   = (const float*)d_in[15];
    float* out = (float*)d_out;

    float *pa, *gpos, *bias2;
    __half *a16, *c16, *bh16, *bl16, *k16, *vh16, *wc16;
    cudaGetSymbolAddress((void**)&pa, g_pa);
    cudaGetSymbolAddress((void**)&gpos, g_gpos);
    cudaGetSymbolAddress((void**)&bias2, g_bias2);
    cudaGetSymbolAddress((void**)&a16, g_a16);
    cudaGetSymbolAddress((void**)&c16, g_c16);
    cudaGetSymbolAddress((void**)&bh16, g_bh16);
    cudaGetSymbolAddress((void**)&bl16, g_bl16);
    cudaGetSymbolAddress((void**)&k16, g_k16);
    cudaGetSymbolAddress((void**)&vh16, g_vh16);
    cudaGetSymbolAddress((void**)&wc16, g_wc16);

    cudaFuncSetAttribute(gemm_kv, cudaFuncAttributeMaxDynamicSharedMemorySize,
                         (int)SMEM_KV);
    cudaFuncSetAttribute(gemm_out, cudaFuncAttributeMaxDynamicSharedMemorySize,
                         (int)SMEM_OUT);
    cudaFuncSetAttribute(gemm_mma3, cudaFuncAttributeMaxDynamicSharedMemorySize,
                         (int)SMEM3_DYN);
    cudaFuncSetAttribute(g_kernel, cudaFuncAttributeMaxDynamicSharedMemorySize,
                         (129 + 129) * 132 * (int)sizeof(float));

    CUtensorMap tAK, tAV, tBkv, tGh, tGl, tWqh, tWql, tAq, tWc;
    encode_f16(&tAK, a16, 1024, 32768, 1, 128);
    encode_f16(&tAV, c16, 1024, 32768, 1, 128);
    encode_f16(&tBkv, bh16, 1024, 1024, 2, 256);
    encode_f16(&tGh,  a16,           1024, 1024, 4, 128);
    encode_f16(&tGl,  a16 + 4194304, 1024, 1024, 4, 128);
    encode_f16(&tWqh, bh16, 1024, 1024, 1, 128);
    encode_f16(&tWql, bl16, 1024, 1024, 1, 128);
    encode_f16(&tAq,  a16,  1024, 32768, 1, 128);
    encode_f16(&tWc,  wc16, 1024, 1024, 4, 256);

    const int NA = 33554432, NW = 1048576;

    // Inputs to fp16 (key, value, Wk, Wv in one launch)
    cvt_all_kernel<<<33792, 256>>>(key, a16, value, c16,
                                   Wk, bh16, Wv, bh16 + NW);

    // K+V projection with fused per-head LN (BN=256: 2 heads per tile)
    gemm_kv<<<dim3(4, 256, 2), 288, SMEM_KV>>>(
        tAK, tAV, tBkv, bk, bv, gK, betaK, gV, betaV, k16, vh16);

    // p_attn = Kc^T Vc / S  (core + edges fused)
    cudaMemsetAsync(pa, 0, (size_t)32 * NE * NE * sizeof(float));
    pa_core_mma<<<dim3(32, 16), 256>>>(k16, vh16, pos, pa);

    // Gd (fp16 hi/lo directly into a16) + gpos
    cudaMemsetAsync(gpos, 0, 4096 * sizeof(float));
    g_kernel<<<dim3(8, NH, NB), 256, (129 + 129) * 132 * sizeof(float)>>>(
        pa, Wfc, a16, a16 + 4194304, gpos);

    // bias2 = bfc + bq @ (Gd hi+lo)^T
    bias2_kernel<<<dim3(1024, 4), 256>>>(a16, a16 + 4194304, bq, bfc, bias2);

    // Wq^T hi/lo
    tsplit16_kernel<<<dim3(32, 32), 256>>>(Wq, bh16, bl16);

    // Wcomb[b] = Gd[b] @ Wq (3-pass) -> fp16 directly into wc16
    gemm_mma3<<<dim3(8, 8, 4), 256, SMEM3_DYN>>>(tGh, tGl, tWqh, tWql, wc16, 16);

    // query -> fp16 (a16 free after gemm_mma3 consumed Gd)
    cvt16_kernel<<<NA / 2048, 256>>>(query, a16, NA);

    // out[b] = query[b] @ Wcomb[b]^T + pos (x) gpos[b] + bias2[b]  (BN=256)
    gemm_out<<<dim3(4, 64, 4), 288, SMEM_OUT>>>(tAq, tWc, bias2, pos, gpos, out);
}